// round 1
// baseline (speedup 1.0000x reference)
#include <cuda_runtime.h>

// Problem constants
#define BB 4
#define SS 2048
#define DD 768
#define HH 8
#define DHH 96
#define MM (BB * SS)   // 8192

// Scratch (device globals — allocation-free)
__device__ float g_Q[(size_t)BB * HH * SS * DHH];
__device__ float g_K[(size_t)BB * HH * SS * DHH];
__device__ float g_V[(size_t)BB * HH * SS * DHH];
__device__ float g_cat[(size_t)MM * DD];

// ---------------------------------------------------------------------------
// QKV projection: out[b,h,s,k] = sum_d X[b,s,d] * W[h,d,k] + bias[h,k]
// Tiles: 64 (rows) x 96 (one full head) x BK=32.  256 threads, 4x6 microtile.
// grid = (MM/64, HH, 3)
// ---------------------------------------------------------------------------
__global__ __launch_bounds__(256) void qkv_kernel(
    const float* __restrict__ Xq, const float* __restrict__ Xk, const float* __restrict__ Xv,
    const float* __restrict__ Wq, const float* __restrict__ Wk, const float* __restrict__ Wv,
    const float* __restrict__ bq, const float* __restrict__ bk, const float* __restrict__ bv)
{
    __shared__ float As[32][68];   // A tile, transposed [k][m], padded
    __shared__ float Bs[32][96];   // W tile [k][n]

    const float* X; const float* W; const float* bias; float* out;
    if (blockIdx.z == 0)      { X = Xq; W = Wq; bias = bq; out = g_Q; }
    else if (blockIdx.z == 1) { X = Xk; W = Wk; bias = bk; out = g_K; }
    else                      { X = Xv; W = Wv; bias = bv; out = g_V; }

    const int h  = blockIdx.y;
    const int m0 = blockIdx.x * 64;
    const int tid = threadIdx.x;
    const int ty = tid >> 4;        // 0..15 -> rows ty*4..+3
    const int tx = tid & 15;        // 0..15 -> cols tx*6..+5
    const float* Wh = W + (size_t)h * DD * DHH;

    float acc[4][6] = {};

    const int a_m  = tid >> 2;          // 0..63
    const int a_k0 = (tid & 3) * 8;     // 0,8,16,24
    const int b_k  = tid >> 3;          // 0..31
    const int b_c0 = (tid & 7) * 12;    // 0..84

    for (int kt = 0; kt < DD; kt += 32) {
        const float* asrc = X + (size_t)(m0 + a_m) * DD + kt + a_k0;
        float4 av0 = *(const float4*)(asrc);
        float4 av1 = *(const float4*)(asrc + 4);
        As[a_k0 + 0][a_m] = av0.x; As[a_k0 + 1][a_m] = av0.y;
        As[a_k0 + 2][a_m] = av0.z; As[a_k0 + 3][a_m] = av0.w;
        As[a_k0 + 4][a_m] = av1.x; As[a_k0 + 5][a_m] = av1.y;
        As[a_k0 + 6][a_m] = av1.z; As[a_k0 + 7][a_m] = av1.w;

        const float* bsrc = Wh + (size_t)(kt + b_k) * DHH + b_c0;
        *(float4*)&Bs[b_k][b_c0]     = *(const float4*)(bsrc);
        *(float4*)&Bs[b_k][b_c0 + 4] = *(const float4*)(bsrc + 4);
        *(float4*)&Bs[b_k][b_c0 + 8] = *(const float4*)(bsrc + 8);
        __syncthreads();

        #pragma unroll
        for (int kk = 0; kk < 32; kk++) {
            float4 a4 = *(const float4*)&As[kk][ty * 4];
            float2 b0 = *(const float2*)&Bs[kk][tx * 6];
            float2 b1 = *(const float2*)&Bs[kk][tx * 6 + 2];
            float2 b2 = *(const float2*)&Bs[kk][tx * 6 + 4];
            float a[4]  = {a4.x, a4.y, a4.z, a4.w};
            float bb[6] = {b0.x, b0.y, b1.x, b1.y, b2.x, b2.y};
            #pragma unroll
            for (int i = 0; i < 4; i++)
                #pragma unroll
                for (int j = 0; j < 6; j++)
                    acc[i][j] += a[i] * bb[j];
        }
        __syncthreads();
    }

    #pragma unroll
    for (int i = 0; i < 4; i++) {
        int m = m0 + ty * 4 + i;
        int b = m / SS, s = m % SS;
        float* dst = out + (((size_t)(b * HH + h)) * SS + s) * DHH + tx * 6;
        #pragma unroll
        for (int j = 0; j < 6; j++)
            dst[j] = acc[i][j] + bias[h * DHH + tx * 6 + j];
    }
}

// ---------------------------------------------------------------------------
// Flash attention: one block per (b, h, 64-row query tile). Online softmax.
// 256 threads. smem: Qt[96][64], Kt[96][64], Vs[64][96], P[64][68], row stats.
// ---------------------------------------------------------------------------
__global__ __launch_bounds__(256) void attn_kernel()
{
    extern __shared__ float sm[];
    float* Qt   = sm;                  // [96][64]  (transposed, pre-scaled)
    float* Kt   = Qt + 96 * 64;        // [96][64]  (transposed)
    float* Vs   = Kt + 96 * 64;        // [64][96]
    float* P    = Vs + 64 * 96;        // [64][68]
    float* rowm = P + 64 * 68;         // [64]
    float* rowl = rowm + 64;           // [64]
    float* rowc = rowl + 64;           // [64]

    const int b  = blockIdx.z;
    const int h  = blockIdx.y;
    const int s0 = blockIdx.x * 64;
    const int tid = threadIdx.x;
    const int ty = tid >> 4;   // rows ty*4..+3
    const int tx = tid & 15;
    const float scale = rsqrtf((float)DHH);

    const size_t headBase = ((size_t)(b * HH + h)) * SS;

    // Load Q tile transposed (scaled by 1/sqrt(DH))
    {
        int r  = tid >> 2;               // 0..63
        int d0 = (tid & 3) * 24;         // 0,24,48,72
        const float* src = g_Q + (headBase + s0 + r) * DHH + d0;
        #pragma unroll
        for (int i = 0; i < 6; i++) {
            float4 v = *(const float4*)(src + i * 4);
            Qt[(d0 + i * 4 + 0) * 64 + r] = v.x * scale;
            Qt[(d0 + i * 4 + 1) * 64 + r] = v.y * scale;
            Qt[(d0 + i * 4 + 2) * 64 + r] = v.z * scale;
            Qt[(d0 + i * 4 + 3) * 64 + r] = v.w * scale;
        }
    }
    if (tid < 64) { rowm[tid] = -1e30f; rowl[tid] = 0.0f; }

    float acc[4][6] = {};
    __syncthreads();

    for (int kt = 0; kt < SS; kt += 64) {
        // Load K tile (transposed) and V tile (row-major)
        {
            int r  = tid >> 2;
            int d0 = (tid & 3) * 24;
            const float* ksrc = g_K + (headBase + kt + r) * DHH + d0;
            #pragma unroll
            for (int i = 0; i < 6; i++) {
                float4 v = *(const float4*)(ksrc + i * 4);
                Kt[(d0 + i * 4 + 0) * 64 + r] = v.x;
                Kt[(d0 + i * 4 + 1) * 64 + r] = v.y;
                Kt[(d0 + i * 4 + 2) * 64 + r] = v.z;
                Kt[(d0 + i * 4 + 3) * 64 + r] = v.w;
            }
            const float* vsrc = g_V + (headBase + kt + r) * DHH + d0;
            float* vdst = Vs + r * 96 + d0;
            #pragma unroll
            for (int i = 0; i < 6; i++)
                *(float4*)(vdst + i * 4) = *(const float4*)(vsrc + i * 4);
        }
        __syncthreads();

        // Scores: S[row][col] for rows ty*4..+3, cols tx*4..+3
        float sreg[4][4] = {};
        #pragma unroll 4
        for (int d = 0; d < 96; d++) {
            float4 a4 = *(const float4*)(Qt + d * 64 + ty * 4);
            float4 k4 = *(const float4*)(Kt + d * 64 + tx * 4);
            float a[4] = {a4.x, a4.y, a4.z, a4.w};
            float k[4] = {k4.x, k4.y, k4.z, k4.w};
            #pragma unroll
            for (int i = 0; i < 4; i++)
                #pragma unroll
                for (int j = 0; j < 4; j++)
                    sreg[i][j] += a[i] * k[j];
        }
        #pragma unroll
        for (int i = 0; i < 4; i++)
            *(float4*)(P + (ty * 4 + i) * 68 + tx * 4) =
                make_float4(sreg[i][0], sreg[i][1], sreg[i][2], sreg[i][3]);
        __syncthreads();

        // Online softmax for this tile (one thread per row)
        if (tid < 64) {
            float* pr = P + tid * 68;
            float mprev = rowm[tid];
            float mx = mprev;
            #pragma unroll 8
            for (int j = 0; j < 64; j++) mx = fmaxf(mx, pr[j]);
            float corr = __expf(mprev - mx);
            float sum = 0.0f;
            #pragma unroll 8
            for (int j = 0; j < 64; j++) {
                float p = __expf(pr[j] - mx);
                pr[j] = p;
                sum += p;
            }
            rowl[tid] = rowl[tid] * corr + sum;
            rowm[tid] = mx;
            rowc[tid] = corr;
        }
        __syncthreads();

        // Rescale accumulators, then O += P @ V
        float cr[4];
        #pragma unroll
        for (int i = 0; i < 4; i++) cr[i] = rowc[ty * 4 + i];
        #pragma unroll
        for (int i = 0; i < 4; i++)
            #pragma unroll
            for (int j = 0; j < 6; j++)
                acc[i][j] *= cr[i];

        #pragma unroll 2
        for (int j = 0; j < 64; j++) {
            float a[4];
            #pragma unroll
            for (int i = 0; i < 4; i++)
                a[i] = P[(ty * 4 + i) * 68 + j];
            const float* vr = Vs + j * 96 + tx * 6;
            float2 v0 = *(const float2*)(vr);
            float2 v1 = *(const float2*)(vr + 2);
            float2 v2 = *(const float2*)(vr + 4);
            float vb[6] = {v0.x, v0.y, v1.x, v1.y, v2.x, v2.y};
            #pragma unroll
            for (int i = 0; i < 4; i++)
                #pragma unroll
                for (int c = 0; c < 6; c++)
                    acc[i][c] += a[i] * vb[c];
        }
        __syncthreads();
    }

    // Epilogue: divide by l and write to concatenated layout [B,S,H*DH]
    #pragma unroll
    for (int i = 0; i < 4; i++) {
        int r = ty * 4 + i;
        float inv = 1.0f / rowl[r];
        float* dst = g_cat + ((size_t)b * SS + (s0 + r)) * DD + h * DHH + tx * 6;
        #pragma unroll
        for (int j = 0; j < 6; j++)
            dst[j] = acc[i][j] * inv;
    }
}

// ---------------------------------------------------------------------------
// Output projection: out[m, n] = sum_k g_cat[m, k] * Wo[k, n] + bo[n]
// grid = (MM/64, DD/96)
// ---------------------------------------------------------------------------
__global__ __launch_bounds__(256) void oproj_kernel(
    const float* __restrict__ Wo, const float* __restrict__ bo,
    float* __restrict__ out)
{
    __shared__ float As[32][68];
    __shared__ float Bs[32][96];

    const int n0 = blockIdx.y * 96;
    const int m0 = blockIdx.x * 64;
    const int tid = threadIdx.x;
    const int ty = tid >> 4, tx = tid & 15;

    float acc[4][6] = {};

    const int a_m  = tid >> 2;
    const int a_k0 = (tid & 3) * 8;
    const int b_k  = tid >> 3;
    const int b_c0 = (tid & 7) * 12;

    for (int kt = 0; kt < DD; kt += 32) {
        const float* asrc = g_cat + (size_t)(m0 + a_m) * DD + kt + a_k0;
        float4 av0 = *(const float4*)(asrc);
        float4 av1 = *(const float4*)(asrc + 4);
        As[a_k0 + 0][a_m] = av0.x; As[a_k0 + 1][a_m] = av0.y;
        As[a_k0 + 2][a_m] = av0.z; As[a_k0 + 3][a_m] = av0.w;
        As[a_k0 + 4][a_m] = av1.x; As[a_k0 + 5][a_m] = av1.y;
        As[a_k0 + 6][a_m] = av1.z; As[a_k0 + 7][a_m] = av1.w;

        const float* bsrc = Wo + (size_t)(kt + b_k) * DD + n0 + b_c0;
        *(float4*)&Bs[b_k][b_c0]     = *(const float4*)(bsrc);
        *(float4*)&Bs[b_k][b_c0 + 4] = *(const float4*)(bsrc + 4);
        *(float4*)&Bs[b_k][b_c0 + 8] = *(const float4*)(bsrc + 8);
        __syncthreads();

        #pragma unroll
        for (int kk = 0; kk < 32; kk++) {
            float4 a4 = *(const float4*)&As[kk][ty * 4];
            float2 b0 = *(const float2*)&Bs[kk][tx * 6];
            float2 b1 = *(const float2*)&Bs[kk][tx * 6 + 2];
            float2 b2 = *(const float2*)&Bs[kk][tx * 6 + 4];
            float a[4]  = {a4.x, a4.y, a4.z, a4.w};
            float bb[6] = {b0.x, b0.y, b1.x, b1.y, b2.x, b2.y};
            #pragma unroll
            for (int i = 0; i < 4; i++)
                #pragma unroll
                for (int j = 0; j < 6; j++)
                    acc[i][j] += a[i] * bb[j];
        }
        __syncthreads();
    }

    #pragma unroll
    for (int i = 0; i < 4; i++) {
        int m = m0 + ty * 4 + i;
        float* dst = out + (size_t)m * DD + n0 + tx * 6;
        #pragma unroll
        for (int j = 0; j < 6; j++)
            dst[j] = acc[i][j] + bo[n0 + tx * 6 + j];
    }
}

// ---------------------------------------------------------------------------
extern "C" void kernel_launch(void* const* d_in, const int* in_sizes, int n_in,
                              void* d_out, int out_size)
{
    (void)in_sizes; (void)n_in; (void)out_size;
    const float* Xq = (const float*)d_in[0];
    const float* Xk = (const float*)d_in[1];
    const float* Xv = (const float*)d_in[2];
    const float* Wq = (const float*)d_in[3];
    const float* bq = (const float*)d_in[4];
    const float* Wk = (const float*)d_in[5];
    const float* bk = (const float*)d_in[6];
    const float* Wv = (const float*)d_in[7];
    const float* bv = (const float*)d_in[8];
    const float* Wo = (const float*)d_in[9];
    const float* bo = (const float*)d_in[10];
    float* out = (float*)d_out;

    dim3 gq(MM / 64, HH, 3);
    qkv_kernel<<<gq, 256>>>(Xq, Xk, Xv, Wq, Wk, Wv, bq, bk, bv);

    const int smem = (96 * 64 * 2 + 64 * 96 + 64 * 68 + 3 * 64) * (int)sizeof(float);
    cudaFuncSetAttribute(attn_kernel, cudaFuncAttributeMaxDynamicSharedMemorySize, smem);
    dim3 ga(SS / 64, HH, BB);
    attn_kernel<<<ga, 256, smem>>>();

    dim3 go(MM / 64, DD / 96);
    oproj_kernel<<<go, 256>>>(Wo, bo, out);
}

// round 2
// speedup vs baseline: 1.0367x; 1.0367x over previous
#include <cuda_runtime.h>

// Problem constants
#define BB 4
#define SS 2048
#define DD 768
#define HH 8
#define DHH 96
#define MM (BB * SS)   // 8192

// Scratch (device globals — allocation-free)
__device__ float g_Q[(size_t)BB * HH * SS * DHH];
__device__ float g_K[(size_t)BB * HH * SS * DHH];
__device__ float g_V[(size_t)BB * HH * SS * DHH];
__device__ float g_cat[(size_t)MM * DD];

// ---------------------------------------------------------------------------
// QKV projection: out[b,h,s,k] = sum_d X[b,s,d] * W[h,d,k] + bias[h,k]
// Tiles: BM=128 x BN=96 (one head) x BK=32. 256 threads, 8x6 microtile.
// grid = (MM/128, HH, 3)
// ---------------------------------------------------------------------------
__global__ __launch_bounds__(256) void qkv_kernel(
    const float* __restrict__ Xq, const float* __restrict__ Xk, const float* __restrict__ Xv,
    const float* __restrict__ Wq, const float* __restrict__ Wk, const float* __restrict__ Wv,
    const float* __restrict__ bq, const float* __restrict__ bk, const float* __restrict__ bv)
{
    __shared__ float As[32][132];   // A tile, transposed [k][m], padded
    __shared__ float Bs[32][96];    // W tile [k][n]

    const float* X; const float* W; const float* bias; float* out;
    if (blockIdx.z == 0)      { X = Xq; W = Wq; bias = bq; out = g_Q; }
    else if (blockIdx.z == 1) { X = Xk; W = Wk; bias = bk; out = g_K; }
    else                      { X = Xv; W = Wv; bias = bv; out = g_V; }

    const int h  = blockIdx.y;
    const int m0 = blockIdx.x * 128;
    const int tid = threadIdx.x;
    const int ty = tid >> 4;        // 0..15 -> rows ty*8..+7
    const int tx = tid & 15;        // 0..15 -> cols tx*6..+5
    const float* Wh = W + (size_t)h * DD * DHH;

    float acc[8][6] = {};

    const int a_m  = tid >> 1;          // 0..127
    const int a_k0 = (tid & 1) * 16;    // 0,16
    const int b_k  = tid >> 3;          // 0..31
    const int b_c0 = (tid & 7) * 12;    // 0..84

    for (int kt = 0; kt < DD; kt += 32) {
        const float* asrc = X + (size_t)(m0 + a_m) * DD + kt + a_k0;
        #pragma unroll
        for (int i = 0; i < 4; i++) {
            float4 v = *(const float4*)(asrc + i * 4);
            As[a_k0 + i * 4 + 0][a_m] = v.x;
            As[a_k0 + i * 4 + 1][a_m] = v.y;
            As[a_k0 + i * 4 + 2][a_m] = v.z;
            As[a_k0 + i * 4 + 3][a_m] = v.w;
        }

        const float* bsrc = Wh + (size_t)(kt + b_k) * DHH + b_c0;
        *(float4*)&Bs[b_k][b_c0]     = *(const float4*)(bsrc);
        *(float4*)&Bs[b_k][b_c0 + 4] = *(const float4*)(bsrc + 4);
        *(float4*)&Bs[b_k][b_c0 + 8] = *(const float4*)(bsrc + 8);
        __syncthreads();

        #pragma unroll
        for (int kk = 0; kk < 32; kk++) {
            float4 a0 = *(const float4*)&As[kk][ty * 8];
            float4 a1 = *(const float4*)&As[kk][ty * 8 + 4];
            float2 b0 = *(const float2*)&Bs[kk][tx * 6];
            float2 b1 = *(const float2*)&Bs[kk][tx * 6 + 2];
            float2 b2 = *(const float2*)&Bs[kk][tx * 6 + 4];
            float a[8]  = {a0.x, a0.y, a0.z, a0.w, a1.x, a1.y, a1.z, a1.w};
            float bb[6] = {b0.x, b0.y, b1.x, b1.y, b2.x, b2.y};
            #pragma unroll
            for (int i = 0; i < 8; i++)
                #pragma unroll
                for (int j = 0; j < 6; j++)
                    acc[i][j] += a[i] * bb[j];
        }
        __syncthreads();
    }

    float bv6[6];
    #pragma unroll
    for (int j = 0; j < 6; j++) bv6[j] = bias[h * DHH + tx * 6 + j];

    #pragma unroll
    for (int i = 0; i < 8; i++) {
        int m = m0 + ty * 8 + i;
        int b = m / SS, s = m % SS;
        float* dst = out + (((size_t)(b * HH + h)) * SS + s) * DHH + tx * 6;
        #pragma unroll
        for (int j = 0; j < 6; j++)
            dst[j] = acc[i][j] + bv6[j];
    }
}

// ---------------------------------------------------------------------------
// Flash attention: one block per (b, h, 128-row query tile). Online softmax.
// 256 threads. 8x4 score microtile, 8x6 PV microtile. Parallel softmax.
// ---------------------------------------------------------------------------
__global__ __launch_bounds__(256) void attn_kernel()
{
    extern __shared__ float sm[];
    float* Qt   = sm;                    // [96][132]  (transposed, pre-scaled)
    float* Kt   = Qt + 96 * 132;         // [96][68]   (transposed)
    float* Vs   = Kt + 96 * 68;          // [64][96]
    float* P    = Vs + 64 * 96;          // [128][68]
    float* rowm = P + 128 * 68;          // [128]
    float* rowl = rowm + 128;            // [128]
    float* rowc = rowl + 128;            // [128]

    const int b  = blockIdx.z;
    const int h  = blockIdx.y;
    const int s0 = blockIdx.x * 128;
    const int tid = threadIdx.x;
    const int ty = tid >> 4;   // rows ty*8..+7
    const int tx = tid & 15;
    const float scale = rsqrtf((float)DHH);

    const size_t headBase = ((size_t)(b * HH + h)) * SS;

    // Load Q tile transposed (scaled by 1/sqrt(DH)): 128 rows x 96 d
    {
        int r  = tid & 127;              // 0..127
        int d0 = (tid >> 7) * 48;        // 0 or 48
        const float* src = g_Q + (headBase + s0 + r) * DHH + d0;
        #pragma unroll
        for (int i = 0; i < 12; i++) {
            float4 v = *(const float4*)(src + i * 4);
            Qt[(d0 + i * 4 + 0) * 132 + r] = v.x * scale;
            Qt[(d0 + i * 4 + 1) * 132 + r] = v.y * scale;
            Qt[(d0 + i * 4 + 2) * 132 + r] = v.z * scale;
            Qt[(d0 + i * 4 + 3) * 132 + r] = v.w * scale;
        }
    }
    if (tid < 128) { rowm[tid] = -1e30f; rowl[tid] = 0.0f; }

    float acc[8][6] = {};
    __syncthreads();

    for (int kt = 0; kt < SS; kt += 64) {
        // Load K tile (transposed) and V tile (row-major)
        {
            int r  = tid & 63;           // 0..63
            int d0 = (tid >> 6) * 24;    // 0,24,48,72
            const float* ksrc = g_K + (headBase + kt + r) * DHH + d0;
            #pragma unroll
            for (int i = 0; i < 6; i++) {
                float4 v = *(const float4*)(ksrc + i * 4);
                Kt[(d0 + i * 4 + 0) * 68 + r] = v.x;
                Kt[(d0 + i * 4 + 1) * 68 + r] = v.y;
                Kt[(d0 + i * 4 + 2) * 68 + r] = v.z;
                Kt[(d0 + i * 4 + 3) * 68 + r] = v.w;
            }
            int vr  = tid >> 2;          // 0..63
            int vd0 = (tid & 3) * 24;
            const float* vsrc = g_V + (headBase + kt + vr) * DHH + vd0;
            float* vdst = Vs + vr * 96 + vd0;
            #pragma unroll
            for (int i = 0; i < 6; i++)
                *(float4*)(vdst + i * 4) = *(const float4*)(vsrc + i * 4);
        }
        __syncthreads();

        // Scores: rows ty*8..+7, cols tx*4..+3
        float sreg[8][4] = {};
        #pragma unroll 2
        for (int d = 0; d < 96; d++) {
            float4 a0 = *(const float4*)(Qt + d * 132 + ty * 8);
            float4 a1 = *(const float4*)(Qt + d * 132 + ty * 8 + 4);
            float4 k4 = *(const float4*)(Kt + d * 68 + tx * 4);
            float a[8] = {a0.x, a0.y, a0.z, a0.w, a1.x, a1.y, a1.z, a1.w};
            float k[4] = {k4.x, k4.y, k4.z, k4.w};
            #pragma unroll
            for (int i = 0; i < 8; i++)
                #pragma unroll
                for (int j = 0; j < 4; j++)
                    sreg[i][j] += a[i] * k[j];
        }
        #pragma unroll
        for (int i = 0; i < 8; i++)
            *(float4*)(P + (ty * 8 + i) * 68 + tx * 4) =
                make_float4(sreg[i][0], sreg[i][1], sreg[i][2], sreg[i][3]);
        __syncthreads();

        // Parallel online softmax: 2 threads per row, 32 cols each
        {
            int row  = tid >> 1;
            int c0   = (tid & 1) * 32;
            float* pr = P + row * 68 + c0;
            float mloc = -1e30f;
            #pragma unroll 8
            for (int j = 0; j < 32; j++) mloc = fmaxf(mloc, pr[j]);
            mloc = fmaxf(mloc, __shfl_xor_sync(0xffffffffu, mloc, 1));
            float mprev = rowm[row];
            float mnew  = fmaxf(mprev, mloc);
            float sum = 0.0f;
            #pragma unroll 8
            for (int j = 0; j < 32; j++) {
                float p = __expf(pr[j] - mnew);
                pr[j] = p;
                sum += p;
            }
            sum += __shfl_xor_sync(0xffffffffu, sum, 1);
            float corr = __expf(mprev - mnew);
            if ((tid & 1) == 0) {
                rowl[row] = rowl[row] * corr + sum;
                rowm[row] = mnew;
                rowc[row] = corr;
            }
        }
        __syncthreads();

        // Rescale accumulators, then O += P @ V
        float cr[8];
        #pragma unroll
        for (int i = 0; i < 8; i++) cr[i] = rowc[ty * 8 + i];
        #pragma unroll
        for (int i = 0; i < 8; i++)
            #pragma unroll
            for (int j = 0; j < 6; j++)
                acc[i][j] *= cr[i];

        for (int j0 = 0; j0 < 64; j0 += 4) {
            float4 p4[8];
            #pragma unroll
            for (int i = 0; i < 8; i++)
                p4[i] = *(const float4*)(P + (ty * 8 + i) * 68 + j0);
            #pragma unroll
            for (int jj = 0; jj < 4; jj++) {
                const float* vr = Vs + (j0 + jj) * 96 + tx * 6;
                float2 v0 = *(const float2*)(vr);
                float2 v1 = *(const float2*)(vr + 2);
                float2 v2 = *(const float2*)(vr + 4);
                float vb[6] = {v0.x, v0.y, v1.x, v1.y, v2.x, v2.y};
                #pragma unroll
                for (int i = 0; i < 8; i++) {
                    float a = (jj == 0) ? p4[i].x : (jj == 1) ? p4[i].y
                            : (jj == 2) ? p4[i].z : p4[i].w;
                    #pragma unroll
                    for (int c = 0; c < 6; c++)
                        acc[i][c] += a * vb[c];
                }
            }
        }
        __syncthreads();
    }

    // Epilogue: divide by l and write to concatenated layout [B,S,H*DH]
    #pragma unroll
    for (int i = 0; i < 8; i++) {
        int r = ty * 8 + i;
        float inv = 1.0f / rowl[r];
        float* dst = g_cat + ((size_t)b * SS + (s0 + r)) * DD + h * DHH + tx * 6;
        #pragma unroll
        for (int j = 0; j < 6; j++)
            dst[j] = acc[i][j] * inv;
    }
}

// ---------------------------------------------------------------------------
// Output projection: out[m, n] = sum_k g_cat[m, k] * Wo[k, n] + bo[n]
// BM=128 x BN=96 x BK=32, 8x6 microtile. grid = (MM/128, DD/96)
// ---------------------------------------------------------------------------
__global__ __launch_bounds__(256) void oproj_kernel(
    const float* __restrict__ Wo, const float* __restrict__ bo,
    float* __restrict__ out)
{
    __shared__ float As[32][132];
    __shared__ float Bs[32][96];

    const int n0 = blockIdx.y * 96;
    const int m0 = blockIdx.x * 128;
    const int tid = threadIdx.x;
    const int ty = tid >> 4, tx = tid & 15;

    float acc[8][6] = {};

    const int a_m  = tid >> 1;
    const int a_k0 = (tid & 1) * 16;
    const int b_k  = tid >> 3;
    const int b_c0 = (tid & 7) * 12;

    for (int kt = 0; kt < DD; kt += 32) {
        const float* asrc = g_cat + (size_t)(m0 + a_m) * DD + kt + a_k0;
        #pragma unroll
        for (int i = 0; i < 4; i++) {
            float4 v = *(const float4*)(asrc + i * 4);
            As[a_k0 + i * 4 + 0][a_m] = v.x;
            As[a_k0 + i * 4 + 1][a_m] = v.y;
            As[a_k0 + i * 4 + 2][a_m] = v.z;
            As[a_k0 + i * 4 + 3][a_m] = v.w;
        }

        const float* bsrc = Wo + (size_t)(kt + b_k) * DD + n0 + b_c0;
        *(float4*)&Bs[b_k][b_c0]     = *(const float4*)(bsrc);
        *(float4*)&Bs[b_k][b_c0 + 4] = *(const float4*)(bsrc + 4);
        *(float4*)&Bs[b_k][b_c0 + 8] = *(const float4*)(bsrc + 8);
        __syncthreads();

        #pragma unroll
        for (int kk = 0; kk < 32; kk++) {
            float4 a0 = *(const float4*)&As[kk][ty * 8];
            float4 a1 = *(const float4*)&As[kk][ty * 8 + 4];
            float2 b0 = *(const float2*)&Bs[kk][tx * 6];
            float2 b1 = *(const float2*)&Bs[kk][tx * 6 + 2];
            float2 b2 = *(const float2*)&Bs[kk][tx * 6 + 4];
            float a[8]  = {a0.x, a0.y, a0.z, a0.w, a1.x, a1.y, a1.z, a1.w};
            float bb[6] = {b0.x, b0.y, b1.x, b1.y, b2.x, b2.y};
            #pragma unroll
            for (int i = 0; i < 8; i++)
                #pragma unroll
                for (int j = 0; j < 6; j++)
                    acc[i][j] += a[i] * bb[j];
        }
        __syncthreads();
    }

    #pragma unroll
    for (int i = 0; i < 8; i++) {
        int m = m0 + ty * 8 + i;
        float* dst = out + (size_t)m * DD + n0 + tx * 6;
        #pragma unroll
        for (int j = 0; j < 6; j++)
            dst[j] = acc[i][j] + bo[n0 + tx * 6 + j];
    }
}

// ---------------------------------------------------------------------------
extern "C" void kernel_launch(void* const* d_in, const int* in_sizes, int n_in,
                              void* d_out, int out_size)
{
    (void)in_sizes; (void)n_in; (void)out_size;
    const float* Xq = (const float*)d_in[0];
    const float* Xk = (const float*)d_in[1];
    const float* Xv = (const float*)d_in[2];
    const float* Wq = (const float*)d_in[3];
    const float* bq = (const float*)d_in[4];
    const float* Wk = (const float*)d_in[5];
    const float* bk = (const float*)d_in[6];
    const float* Wv = (const float*)d_in[7];
    const float* bv = (const float*)d_in[8];
    const float* Wo = (const float*)d_in[9];
    const float* bo = (const float*)d_in[10];
    float* out = (float*)d_out;

    dim3 gq(MM / 128, HH, 3);
    qkv_kernel<<<gq, 256>>>(Xq, Xk, Xv, Wq, Wk, Wv, bq, bk, bv);

    const int smem = (96 * 132 + 96 * 68 + 64 * 96 + 128 * 68 + 3 * 128) * (int)sizeof(float);
    cudaFuncSetAttribute(attn_kernel, cudaFuncAttributeMaxDynamicSharedMemorySize, smem);
    dim3 ga(SS / 128, HH, BB);
    attn_kernel<<<ga, 256, smem>>>();

    dim3 go(MM / 128, DD / 96);
    oproj_kernel<<<go, 256>>>(Wo, bo, out);
}

// round 3
// speedup vs baseline: 2.7052x; 2.6095x over previous
#include <cuda_runtime.h>
#include <cuda_fp16.h>

#define BB 4
#define SS 2048
#define DD 768
#define HH 8
#define DHH 96
#define MM (BB*SS)   // 8192

// Scratch: split hi/lo fp16 representations (hi+lo ~= fp32)
__device__ __half g_Qh[(size_t)BB*HH*SS*DHH];
__device__ __half g_Ql[(size_t)BB*HH*SS*DHH];
__device__ __half g_Kh[(size_t)BB*HH*SS*DHH];
__device__ __half g_Kl[(size_t)BB*HH*SS*DHH];
__device__ __half g_Vh[(size_t)BB*HH*SS*DHH];
__device__ __half g_Vl[(size_t)BB*HH*SS*DHH];
__device__ __half g_cath[(size_t)MM*DD];
__device__ __half g_catl[(size_t)MM*DD];

__device__ __forceinline__ unsigned su32(const void* p) {
    return (unsigned)__cvta_generic_to_shared(p);
}
__device__ __forceinline__ unsigned h2u(half2 v) {
    union { half2 h; unsigned u; } x; x.h = v; return x.u;
}
__device__ __forceinline__ void ldsm4(unsigned r[4], unsigned addr) {
    asm volatile("ldmatrix.sync.aligned.m8n8.x4.shared.b16 {%0,%1,%2,%3},[%4];\n"
        : "=r"(r[0]), "=r"(r[1]), "=r"(r[2]), "=r"(r[3]) : "r"(addr));
}
__device__ __forceinline__ void ldsm4t(unsigned r[4], unsigned addr) {
    asm volatile("ldmatrix.sync.aligned.m8n8.x4.trans.shared.b16 {%0,%1,%2,%3},[%4];\n"
        : "=r"(r[0]), "=r"(r[1]), "=r"(r[2]), "=r"(r[3]) : "r"(addr));
}
__device__ __forceinline__ void mma16816(float* c, const unsigned* a, const unsigned* b) {
    asm volatile("mma.sync.aligned.m16n8k16.row.col.f32.f16.f16.f32 "
        "{%0,%1,%2,%3},{%4,%5,%6,%7},{%8,%9},{%0,%1,%2,%3};\n"
        : "+f"(c[0]), "+f"(c[1]), "+f"(c[2]), "+f"(c[3])
        : "r"(a[0]), "r"(a[1]), "r"(a[2]), "r"(a[3]), "r"(b[0]), "r"(b[1]));
}
// split fp32 -> (hi, lo) fp16 pair
__device__ __forceinline__ void splitf(float x, __half& h, __half& l) {
    h = __float2half_rn(x);
    l = __float2half_rn(x - __half2float(h));
}

// ---------------------------------------------------------------------------
// QKV projection: C[128x96] = X[128x768] @ W[768x96] + bias, split-fp16 HMMA.
// 8 warps (4m x 2n), warp tile 32x48. BK=32. grid=(64, 8, 3).
// ---------------------------------------------------------------------------
#define QK_LDA 40
#define QK_LDB 104

__global__ __launch_bounds__(256) void qkv_kernel(
    const float* __restrict__ Xq, const float* __restrict__ Xk, const float* __restrict__ Xv,
    const float* __restrict__ Wq, const float* __restrict__ Wk, const float* __restrict__ Wv,
    const float* __restrict__ bq, const float* __restrict__ bk, const float* __restrict__ bv)
{
    __shared__ __half Ah[128*QK_LDA], Al[128*QK_LDA];
    __shared__ __half Bh[32*QK_LDB],  Bl[32*QK_LDB];

    const float* X; const float* W; const float* bias;
    __half *oh, *ol;
    if (blockIdx.z == 0)      { X = Xq; W = Wq; bias = bq; oh = g_Qh; ol = g_Ql; }
    else if (blockIdx.z == 1) { X = Xk; W = Wk; bias = bk; oh = g_Kh; ol = g_Kl; }
    else                      { X = Xv; W = Wv; bias = bv; oh = g_Vh; ol = g_Vl; }

    const int h   = blockIdx.y;
    const int m0  = blockIdx.x * 128;
    const int tid = threadIdx.x;
    const int wid = tid >> 5, lane = tid & 31;
    const int wm  = wid >> 1, wn = wid & 1;
    const float* Wh = W + (size_t)h * DD * DHH;

    float acc[2][6][4];
    #pragma unroll
    for (int i = 0; i < 2; i++)
        #pragma unroll
        for (int j = 0; j < 6; j++)
            #pragma unroll
            for (int k = 0; k < 4; k++) acc[i][j][k] = 0.f;

    const int lrow = lane & 15, lcol8 = (lane >> 4) << 3;

    for (int kt = 0; kt < DD; kt += 32) {
        {   // X tile 128x32 fp32 -> split
            int r = tid >> 1, c0 = (tid & 1) * 16;
            const float* src = X + (size_t)(m0 + r) * DD + kt + c0;
            __half* dh = Ah + r * QK_LDA + c0;
            __half* dl = Al + r * QK_LDA + c0;
            #pragma unroll
            for (int i = 0; i < 4; i++) {
                float4 v = *(const float4*)(src + i * 4);
                __half h0,l0,h1,l1,h2,l2,h3,l3;
                splitf(v.x,h0,l0); splitf(v.y,h1,l1); splitf(v.z,h2,l2); splitf(v.w,h3,l3);
                *(half2*)(dh + i*4)     = __halves2half2(h0,h1);
                *(half2*)(dh + i*4 + 2) = __halves2half2(h2,h3);
                *(half2*)(dl + i*4)     = __halves2half2(l0,l1);
                *(half2*)(dl + i*4 + 2) = __halves2half2(l2,l3);
            }
        }
        {   // W tile 32x96 fp32 -> split
            int r = tid >> 3, c0 = (tid & 7) * 12;
            const float* src = Wh + (size_t)(kt + r) * DHH + c0;
            __half* dh = Bh + r * QK_LDB + c0;
            __half* dl = Bl + r * QK_LDB + c0;
            #pragma unroll
            for (int i = 0; i < 3; i++) {
                float4 v = *(const float4*)(src + i * 4);
                __half h0,l0,h1,l1,h2,l2,h3,l3;
                splitf(v.x,h0,l0); splitf(v.y,h1,l1); splitf(v.z,h2,l2); splitf(v.w,h3,l3);
                *(half2*)(dh + i*4)     = __halves2half2(h0,h1);
                *(half2*)(dh + i*4 + 2) = __halves2half2(h2,h3);
                *(half2*)(dl + i*4)     = __halves2half2(l0,l1);
                *(half2*)(dl + i*4 + 2) = __halves2half2(l2,l3);
            }
        }
        __syncthreads();

        #pragma unroll
        for (int ks = 0; ks < 2; ks++) {
            int k0 = ks * 16;
            unsigned ah[2][4], al[2][4];
            #pragma unroll
            for (int mf = 0; mf < 2; mf++) {
                int row = wm * 32 + mf * 16 + lrow;
                ldsm4(ah[mf], su32(Ah + row * QK_LDA + k0 + lcol8));
                ldsm4(al[mf], su32(Al + row * QK_LDA + k0 + lcol8));
            }
            #pragma unroll
            for (int nf2 = 0; nf2 < 3; nf2++) {
                unsigned bh[4], bl[4];
                int n0 = wn * 48 + nf2 * 16;
                int brow = k0 + lrow;
                ldsm4t(bh, su32(Bh + brow * QK_LDB + n0 + lcol8));
                ldsm4t(bl, su32(Bl + brow * QK_LDB + n0 + lcol8));
                #pragma unroll
                for (int hn = 0; hn < 2; hn++) {
                    #pragma unroll
                    for (int mf = 0; mf < 2; mf++) {
                        float* c = acc[mf][nf2*2 + hn];
                        mma16816(c, ah[mf], bh + hn*2);
                        mma16816(c, ah[mf], bl + hn*2);
                        mma16816(c, al[mf], bh + hn*2);
                    }
                }
            }
        }
        __syncthreads();
    }

    // Epilogue: add bias, split-store to [B,H,S,DH] hi/lo
    #pragma unroll
    for (int mf = 0; mf < 2; mf++) {
        #pragma unroll
        for (int nf = 0; nf < 6; nf++) {
            int col = wn * 48 + nf * 8 + (lane & 3) * 2;
            float b0 = bias[h*DHH + col], b1 = bias[h*DHH + col + 1];
            #pragma unroll
            for (int hr = 0; hr < 2; hr++) {
                int m = m0 + wm * 32 + mf * 16 + (lane >> 2) + hr * 8;
                int bb = m >> 11, s = m & 2047;
                size_t off = (((size_t)(bb * HH + h)) * SS + s) * DHH + col;
                float v0 = acc[mf][nf][hr*2 + 0] + b0;
                float v1 = acc[mf][nf][hr*2 + 1] + b1;
                __half h0,l0,h1,l1; splitf(v0,h0,l0); splitf(v1,h1,l1);
                *(half2*)(oh + off) = __halves2half2(h0,h1);
                *(half2*)(ol + off) = __halves2half2(l0,l1);
            }
        }
    }
}

// ---------------------------------------------------------------------------
// Flash attention, split-fp16 HMMA. Block = (b,h,128 q rows), 8 warps x 16 rows.
// Key tile 64. S frags -> softmax in regs -> P frags (register pass) -> PV.
// ---------------------------------------------------------------------------
#define AT_LD 104

__global__ __launch_bounds__(256) void attn_kernel()
{
    extern __shared__ __half smh[];
    __half* Qh = smh;                    // [128][104]
    __half* Ql = Qh + 128 * AT_LD;
    __half* Kh = Ql + 128 * AT_LD;       // [64][104]
    __half* Kl = Kh + 64 * AT_LD;
    __half* Vh = Kl + 64 * AT_LD;        // [64][104]
    __half* Vl = Vh + 64 * AT_LD;

    const int b  = blockIdx.z, h = blockIdx.y;
    const int s0 = blockIdx.x * 128;
    const int tid = threadIdx.x, wid = tid >> 5, lane = tid & 31;
    const size_t base = ((size_t)(b * HH + h)) * SS;
    const float scale = rsqrtf(96.0f);

    {   // load Q tile (hi/lo)
        int r = tid >> 1, c0 = (tid & 1) * 48;
        size_t go = (base + s0 + r) * DHH + c0;
        __half* dh = Qh + r * AT_LD + c0;
        __half* dl = Ql + r * AT_LD + c0;
        #pragma unroll
        for (int i = 0; i < 6; i++) {
            *(uint4*)(dh + i*8) = *(const uint4*)(g_Qh + go + i*8);
            *(uint4*)(dl + i*8) = *(const uint4*)(g_Ql + go + i*8);
        }
    }

    float oacc[12][4];
    #pragma unroll
    for (int j = 0; j < 12; j++)
        #pragma unroll
        for (int t = 0; t < 4; t++) oacc[j][t] = 0.f;
    float m0r = -1e30f, m1r = -1e30f, l0r = 0.f, l1r = 0.f;

    const int lrow = lane & 15, lcol8 = (lane >> 4) << 3;
    // K-as-B (non-trans) addressing: row=key, col=d
    const int krow_off = (lane & 7) + ((lane & 16) >> 1);
    const int kcol_off = (lane & 8);

    for (int kt = 0; kt < SS; kt += 64) {
        {   // load K,V tiles (hi/lo)
            int r = tid >> 2, c0 = (tid & 3) * 24;
            size_t go = (base + kt + r) * DHH + c0;
            __half* dKh = Kh + r * AT_LD + c0;
            __half* dKl = Kl + r * AT_LD + c0;
            __half* dVh = Vh + r * AT_LD + c0;
            __half* dVl = Vl + r * AT_LD + c0;
            #pragma unroll
            for (int i = 0; i < 3; i++) {
                *(uint4*)(dKh + i*8) = *(const uint4*)(g_Kh + go + i*8);
                *(uint4*)(dKl + i*8) = *(const uint4*)(g_Kl + go + i*8);
                *(uint4*)(dVh + i*8) = *(const uint4*)(g_Vh + go + i*8);
                *(uint4*)(dVl + i*8) = *(const uint4*)(g_Vl + go + i*8);
            }
        }
        __syncthreads();

        // S = Q @ K^T  (16 q-rows per warp x 64 keys)
        float sacc[8][4];
        #pragma unroll
        for (int j = 0; j < 8; j++)
            #pragma unroll
            for (int t = 0; t < 4; t++) sacc[j][t] = 0.f;

        #pragma unroll
        for (int dk = 0; dk < 6; dk++) {
            int d0 = dk * 16;
            unsigned ah[4], al[4];
            int qrow = wid * 16 + lrow;
            ldsm4(ah, su32(Qh + qrow * AT_LD + d0 + lcol8));
            ldsm4(al, su32(Ql + qrow * AT_LD + d0 + lcol8));
            #pragma unroll
            for (int nf2 = 0; nf2 < 4; nf2++) {
                unsigned bh[4], bl[4];
                int n0 = nf2 * 16;
                ldsm4(bh, su32(Kh + (n0 + krow_off) * AT_LD + d0 + kcol_off));
                ldsm4(bl, su32(Kl + (n0 + krow_off) * AT_LD + d0 + kcol_off));
                #pragma unroll
                for (int hn = 0; hn < 2; hn++) {
                    float* c = sacc[nf2*2 + hn];
                    mma16816(c, ah, bh + hn*2);
                    mma16816(c, ah, bl + hn*2);
                    mma16816(c, al, bh + hn*2);
                }
            }
        }

        // online softmax (rows lane/4 and lane/4+8)
        float mx0 = -1e30f, mx1 = -1e30f;
        #pragma unroll
        for (int j = 0; j < 8; j++) {
            #pragma unroll
            for (int t = 0; t < 4; t++) sacc[j][t] *= scale;
            mx0 = fmaxf(mx0, fmaxf(sacc[j][0], sacc[j][1]));
            mx1 = fmaxf(mx1, fmaxf(sacc[j][2], sacc[j][3]));
        }
        mx0 = fmaxf(mx0, __shfl_xor_sync(0xffffffffu, mx0, 1));
        mx0 = fmaxf(mx0, __shfl_xor_sync(0xffffffffu, mx0, 2));
        mx1 = fmaxf(mx1, __shfl_xor_sync(0xffffffffu, mx1, 1));
        mx1 = fmaxf(mx1, __shfl_xor_sync(0xffffffffu, mx1, 2));
        float mn0 = fmaxf(m0r, mx0), mn1 = fmaxf(m1r, mx1);
        float corr0 = __expf(m0r - mn0), corr1 = __expf(m1r - mn1);
        m0r = mn0; m1r = mn1;
        float sum0 = 0.f, sum1 = 0.f;
        #pragma unroll
        for (int j = 0; j < 8; j++) {
            sacc[j][0] = __expf(sacc[j][0] - mn0);
            sacc[j][1] = __expf(sacc[j][1] - mn0);
            sacc[j][2] = __expf(sacc[j][2] - mn1);
            sacc[j][3] = __expf(sacc[j][3] - mn1);
            sum0 += sacc[j][0] + sacc[j][1];
            sum1 += sacc[j][2] + sacc[j][3];
        }
        sum0 += __shfl_xor_sync(0xffffffffu, sum0, 1);
        sum0 += __shfl_xor_sync(0xffffffffu, sum0, 2);
        sum1 += __shfl_xor_sync(0xffffffffu, sum1, 1);
        sum1 += __shfl_xor_sync(0xffffffffu, sum1, 2);
        l0r = l0r * corr0 + sum0;
        l1r = l1r * corr1 + sum1;

        // rescale output accumulators
        #pragma unroll
        for (int j = 0; j < 12; j++) {
            oacc[j][0] *= corr0; oacc[j][1] *= corr0;
            oacc[j][2] *= corr1; oacc[j][3] *= corr1;
        }

        // P fragments from S accumulators (register pass, split hi/lo)
        unsigned ph[4][4], pl[4][4];
        #pragma unroll
        for (int kf = 0; kf < 4; kf++) {
            #pragma unroll
            for (int q = 0; q < 4; q++) {
                int fj = kf*2 + (q >> 1);
                int t0 = (q & 1) * 2;
                float v0 = sacc[fj][t0], v1 = sacc[fj][t0 + 1];
                __half h0,l0,h1,l1; splitf(v0,h0,l0); splitf(v1,h1,l1);
                ph[kf][q] = h2u(__halves2half2(h0,h1));
                pl[kf][q] = h2u(__halves2half2(l0,l1));
            }
        }

        // O += P @ V
        #pragma unroll
        for (int kf = 0; kf < 4; kf++) {
            int k0 = kf * 16;
            #pragma unroll
            for (int nf2 = 0; nf2 < 6; nf2++) {
                unsigned bh[4], bl[4];
                int n0 = nf2 * 16;
                int vrow = k0 + lrow;
                ldsm4t(bh, su32(Vh + vrow * AT_LD + n0 + lcol8));
                ldsm4t(bl, su32(Vl + vrow * AT_LD + n0 + lcol8));
                #pragma unroll
                for (int hn = 0; hn < 2; hn++) {
                    float* c = oacc[nf2*2 + hn];
                    mma16816(c, ph[kf], bh + hn*2);
                    mma16816(c, ph[kf], bl + hn*2);
                    mma16816(c, pl[kf], bh + hn*2);
                }
            }
        }
        __syncthreads();
    }

    // Epilogue: normalize, split-store to cat [M][768] hi/lo
    float inv0 = 1.0f / l0r, inv1 = 1.0f / l1r;
    #pragma unroll
    for (int nf = 0; nf < 12; nf++) {
        int col = h * DHH + nf * 8 + (lane & 3) * 2;
        #pragma unroll
        for (int hr = 0; hr < 2; hr++) {
            int s = s0 + wid * 16 + (lane >> 2) + hr * 8;
            size_t off = ((size_t)b * SS + s) * DD + col;
            float inv = hr ? inv1 : inv0;
            float v0 = oacc[nf][hr*2 + 0] * inv;
            float v1 = oacc[nf][hr*2 + 1] * inv;
            __half h0,l0,h1,l1; splitf(v0,h0,l0); splitf(v1,h1,l1);
            *(half2*)(g_cath + off) = __halves2half2(h0,h1);
            *(half2*)(g_catl + off) = __halves2half2(l0,l1);
        }
    }
}

// ---------------------------------------------------------------------------
// Output projection: out[128x128] = cat[128x768] @ Wo[768x128] + bo.
// 8 warps (4m x 2n), warp tile 32x64. grid=(64, 6).
// ---------------------------------------------------------------------------
#define OP_LDA 40
#define OP_LDB 136

__global__ __launch_bounds__(256) void oproj_kernel(
    const float* __restrict__ Wo, const float* __restrict__ bo,
    float* __restrict__ out)
{
    __shared__ __half Ah[128*OP_LDA], Al[128*OP_LDA];
    __shared__ __half Bh[32*OP_LDB],  Bl[32*OP_LDB];

    const int m0  = blockIdx.x * 128;
    const int n0b = blockIdx.y * 128;
    const int tid = threadIdx.x, wid = tid >> 5, lane = tid & 31;
    const int wm = wid >> 1, wn = wid & 1;

    float acc[2][8][4];
    #pragma unroll
    for (int i = 0; i < 2; i++)
        #pragma unroll
        for (int j = 0; j < 8; j++)
            #pragma unroll
            for (int k = 0; k < 4; k++) acc[i][j][k] = 0.f;

    const int lrow = lane & 15, lcol8 = (lane >> 4) << 3;

    for (int kt = 0; kt < DD; kt += 32) {
        {   // A from split cat (already fp16 hi/lo)
            int r = tid >> 1, c0 = (tid & 1) * 16;
            size_t go = (size_t)(m0 + r) * DD + kt + c0;
            *(uint4*)(Ah + r*OP_LDA + c0)     = *(const uint4*)(g_cath + go);
            *(uint4*)(Ah + r*OP_LDA + c0 + 8) = *(const uint4*)(g_cath + go + 8);
            *(uint4*)(Al + r*OP_LDA + c0)     = *(const uint4*)(g_catl + go);
            *(uint4*)(Al + r*OP_LDA + c0 + 8) = *(const uint4*)(g_catl + go + 8);
        }
        {   // B from Wo fp32 -> split
            int r = tid >> 3, c0 = (tid & 7) * 16;
            const float* src = Wo + (size_t)(kt + r) * DD + n0b + c0;
            __half* dh = Bh + r * OP_LDB + c0;
            __half* dl = Bl + r * OP_LDB + c0;
            #pragma unroll
            for (int i = 0; i < 4; i++) {
                float4 v = *(const float4*)(src + i * 4);
                __half h0,l0,h1,l1,h2,l2,h3,l3;
                splitf(v.x,h0,l0); splitf(v.y,h1,l1); splitf(v.z,h2,l2); splitf(v.w,h3,l3);
                *(half2*)(dh + i*4)     = __halves2half2(h0,h1);
                *(half2*)(dh + i*4 + 2) = __halves2half2(h2,h3);
                *(half2*)(dl + i*4)     = __halves2half2(l0,l1);
                *(half2*)(dl + i*4 + 2) = __halves2half2(l2,l3);
            }
        }
        __syncthreads();

        #pragma unroll
        for (int ks = 0; ks < 2; ks++) {
            int k0 = ks * 16;
            unsigned ah[2][4], al[2][4];
            #pragma unroll
            for (int mf = 0; mf < 2; mf++) {
                int row = wm * 32 + mf * 16 + lrow;
                ldsm4(ah[mf], su32(Ah + row * OP_LDA + k0 + lcol8));
                ldsm4(al[mf], su32(Al + row * OP_LDA + k0 + lcol8));
            }
            #pragma unroll
            for (int nf2 = 0; nf2 < 4; nf2++) {
                unsigned bh[4], bl[4];
                int n0 = wn * 64 + nf2 * 16;
                int brow = k0 + lrow;
                ldsm4t(bh, su32(Bh + brow * OP_LDB + n0 + lcol8));
                ldsm4t(bl, su32(Bl + brow * OP_LDB + n0 + lcol8));
                #pragma unroll
                for (int hn = 0; hn < 2; hn++) {
                    #pragma unroll
                    for (int mf = 0; mf < 2; mf++) {
                        float* c = acc[mf][nf2*2 + hn];
                        mma16816(c, ah[mf], bh + hn*2);
                        mma16816(c, ah[mf], bl + hn*2);
                        mma16816(c, al[mf], bh + hn*2);
                    }
                }
            }
        }
        __syncthreads();
    }

    #pragma unroll
    for (int mf = 0; mf < 2; mf++) {
        #pragma unroll
        for (int nf = 0; nf < 8; nf++) {
            int col = n0b + wn * 64 + nf * 8 + (lane & 3) * 2;
            float b0 = bo[col], b1 = bo[col + 1];
            #pragma unroll
            for (int hr = 0; hr < 2; hr++) {
                int m = m0 + wm * 32 + mf * 16 + (lane >> 2) + hr * 8;
                float2 v = make_float2(acc[mf][nf][hr*2+0] + b0,
                                       acc[mf][nf][hr*2+1] + b1);
                *(float2*)(out + (size_t)m * DD + col) = v;
            }
        }
    }
}

// ---------------------------------------------------------------------------
extern "C" void kernel_launch(void* const* d_in, const int* in_sizes, int n_in,
                              void* d_out, int out_size)
{
    (void)in_sizes; (void)n_in; (void)out_size;
    const float* Xq = (const float*)d_in[0];
    const float* Xk = (const float*)d_in[1];
    const float* Xv = (const float*)d_in[2];
    const float* Wq = (const float*)d_in[3];
    const float* bq = (const float*)d_in[4];
    const float* Wk = (const float*)d_in[5];
    const float* bk = (const float*)d_in[6];
    const float* Wv = (const float*)d_in[7];
    const float* bv = (const float*)d_in[8];
    const float* Wo = (const float*)d_in[9];
    const float* bo = (const float*)d_in[10];
    float* out = (float*)d_out;

    dim3 gq(MM / 128, HH, 3);
    qkv_kernel<<<gq, 256>>>(Xq, Xk, Xv, Wq, Wk, Wv, bq, bk, bv);

    const int smem = (2 * 128 + 4 * 64) * AT_LD * (int)sizeof(__half); // 106496
    cudaFuncSetAttribute(attn_kernel, cudaFuncAttributeMaxDynamicSharedMemorySize, smem);
    dim3 ga(SS / 128, HH, BB);
    attn_kernel<<<ga, 256, smem>>>();

    dim3 go(MM / 128, DD / 128);
    oproj_kernel<<<go, 256>>>(Wo, bo, out);
}

// round 4
// speedup vs baseline: 2.9247x; 1.0811x over previous
#include <cuda_runtime.h>
#include <cuda_fp16.h>

#define BB 4
#define SS 2048
#define DD 768
#define HH 8
#define DHH 96
#define MM (BB*SS)   // 8192

// Split hi/lo fp16 scratch
__device__ __half g_Xqh[(size_t)MM*DD], g_Xql[(size_t)MM*DD];
__device__ __half g_Xkh[(size_t)MM*DD], g_Xkl[(size_t)MM*DD];
__device__ __half g_Xvh[(size_t)MM*DD], g_Xvl[(size_t)MM*DD];
__device__ __half g_Wqh[(size_t)HH*DD*DHH], g_Wql[(size_t)HH*DD*DHH];
__device__ __half g_Wkh[(size_t)HH*DD*DHH], g_Wkl[(size_t)HH*DD*DHH];
__device__ __half g_Wvh[(size_t)HH*DD*DHH], g_Wvl[(size_t)HH*DD*DHH];
__device__ __half g_Woh[(size_t)DD*DD],     g_Wol[(size_t)DD*DD];
__device__ __half g_Qh[(size_t)BB*HH*SS*DHH], g_Ql[(size_t)BB*HH*SS*DHH];
__device__ __half g_Kh[(size_t)BB*HH*SS*DHH], g_Kl[(size_t)BB*HH*SS*DHH];
__device__ __half g_Vh[(size_t)BB*HH*SS*DHH], g_Vl[(size_t)BB*HH*SS*DHH];
__device__ __half g_cath[(size_t)MM*DD],      g_catl[(size_t)MM*DD];

__device__ __forceinline__ unsigned su32(const void* p) {
    return (unsigned)__cvta_generic_to_shared(p);
}
__device__ __forceinline__ unsigned h2u(half2 v) {
    union { half2 h; unsigned u; } x; x.h = v; return x.u;
}
__device__ __forceinline__ void ldsm4(unsigned r[4], unsigned addr) {
    asm volatile("ldmatrix.sync.aligned.m8n8.x4.shared.b16 {%0,%1,%2,%3},[%4];\n"
        : "=r"(r[0]), "=r"(r[1]), "=r"(r[2]), "=r"(r[3]) : "r"(addr));
}
__device__ __forceinline__ void ldsm4t(unsigned r[4], unsigned addr) {
    asm volatile("ldmatrix.sync.aligned.m8n8.x4.trans.shared.b16 {%0,%1,%2,%3},[%4];\n"
        : "=r"(r[0]), "=r"(r[1]), "=r"(r[2]), "=r"(r[3]) : "r"(addr));
}
__device__ __forceinline__ void mma16816(float* c, const unsigned* a, const unsigned* b) {
    asm volatile("mma.sync.aligned.m16n8k16.row.col.f32.f16.f16.f32 "
        "{%0,%1,%2,%3},{%4,%5,%6,%7},{%8,%9},{%0,%1,%2,%3};\n"
        : "+f"(c[0]), "+f"(c[1]), "+f"(c[2]), "+f"(c[3])
        : "r"(a[0]), "r"(a[1]), "r"(a[2]), "r"(a[3]), "r"(b[0]), "r"(b[1]));
}
__device__ __forceinline__ void splitf(float x, __half& h, __half& l) {
    h = __float2half_rn(x);
    l = __float2half_rn(x - __half2float(h));
}
#define CPA(dst, src) asm volatile("cp.async.cg.shared.global [%0], [%1], 16;\n" :: "r"(dst), "l"(src))
#define CP_COMMIT asm volatile("cp.async.commit_group;\n")
#define CP_WAIT1  asm volatile("cp.async.wait_group 1;\n")
#define CP_WAIT0  asm volatile("cp.async.wait_group 0;\n")

// ---------------------------------------------------------------------------
// Preconvert fp32 -> split hi/lo fp16 (elementwise, 4 floats/thread)
// ---------------------------------------------------------------------------
__global__ __launch_bounds__(256) void split_kernel(const float* __restrict__ src, int sel, int n4)
{
    int i = blockIdx.x * blockDim.x + threadIdx.x;
    if (i >= n4) return;
    __half *dh, *dl;
    if (sel == 0)      { dh = g_Xqh; dl = g_Xql; }
    else if (sel == 1) { dh = g_Xkh; dl = g_Xkl; }
    else if (sel == 2) { dh = g_Xvh; dl = g_Xvl; }
    else if (sel == 3) { dh = g_Wqh; dl = g_Wql; }
    else if (sel == 4) { dh = g_Wkh; dl = g_Wkl; }
    else if (sel == 5) { dh = g_Wvh; dl = g_Wvl; }
    else               { dh = g_Woh; dl = g_Wol; }
    float4 v = ((const float4*)src)[i];
    union { __half h[4]; uint2 u; } ph, pl;
    splitf(v.x, ph.h[0], pl.h[0]);
    splitf(v.y, ph.h[1], pl.h[1]);
    splitf(v.z, ph.h[2], pl.h[2]);
    splitf(v.w, ph.h[3], pl.h[3]);
    ((uint2*)dh)[i] = ph.u;
    ((uint2*)dl)[i] = pl.u;
}

// ---------------------------------------------------------------------------
// QKV GEMM: C[128x96] = X[128x768] @ W[768x96] + bias. Split-fp16 HMMA.
// cp.async double-buffered BK=32. 8 warps (4m x 2n). grid=(64, 8, 3).
// ---------------------------------------------------------------------------
#define QK_LDA 40
#define QK_LDB 104

__device__ __forceinline__ void qkv_load(
    __half* Ah, __half* Al, __half* Bh, __half* Bl,
    const __half* gXh, const __half* gXl, const __half* gWh, const __half* gWl,
    int p, int m0, int kt, size_t wbase, int tid)
{
    #pragma unroll
    for (int j = 0; j < 7; j++) {
        int c = tid + j * 256;
        if (c < 1024) {
            int arr = c >> 9, rem = c & 511, row = rem >> 2, off = (rem & 3) * 8;
            const __half* sp = (arr ? gXl : gXh) + (size_t)(m0 + row) * DD + kt + off;
            __half* dp = (arr ? Al : Ah) + p * (128*QK_LDA) + row * QK_LDA + off;
            CPA(su32(dp), sp);
        } else {
            int c2 = c - 1024;
            int arr = (c2 >= 384) ? 1 : 0;
            int rem = c2 - arr * 384;
            int row = rem / 12, off = (rem - row * 12) * 8;
            const __half* sp = (arr ? gWl : gWh) + wbase + (size_t)(kt + row) * DHH + off;
            __half* dp = (arr ? Bl : Bh) + p * (32*QK_LDB) + row * QK_LDB + off;
            CPA(su32(dp), sp);
        }
    }
}

__global__ __launch_bounds__(256) void qkv_kernel(
    const float* __restrict__ bq, const float* __restrict__ bk, const float* __restrict__ bv)
{
    extern __shared__ __half smq[];
    __half* Ah = smq;               // 2 stages x 128 x 40
    __half* Al = Ah + 2*128*QK_LDA;
    __half* Bh = Al + 2*128*QK_LDA; // 2 stages x 32 x 104
    __half* Bl = Bh + 2*32*QK_LDB;

    const __half *gXh, *gXl, *gWh, *gWl; const float* bias; __half *oh, *ol;
    if (blockIdx.z == 0)      { gXh=g_Xqh; gXl=g_Xql; gWh=g_Wqh; gWl=g_Wql; bias=bq; oh=g_Qh; ol=g_Ql; }
    else if (blockIdx.z == 1) { gXh=g_Xkh; gXl=g_Xkl; gWh=g_Wkh; gWl=g_Wkl; bias=bk; oh=g_Kh; ol=g_Kl; }
    else                      { gXh=g_Xvh; gXl=g_Xvl; gWh=g_Wvh; gWl=g_Wvl; bias=bv; oh=g_Vh; ol=g_Vl; }

    const int h   = blockIdx.y;
    const int m0  = blockIdx.x * 128;
    const int tid = threadIdx.x;
    const int wid = tid >> 5, lane = tid & 31;
    const int wm  = wid >> 1, wn = wid & 1;
    const size_t wbase = (size_t)h * DD * DHH;

    float acc[2][6][4];
    #pragma unroll
    for (int i = 0; i < 2; i++)
        #pragma unroll
        for (int j = 0; j < 6; j++)
            #pragma unroll
            for (int k = 0; k < 4; k++) acc[i][j][k] = 0.f;

    const int lrow = lane & 15, lcol8 = (lane >> 4) << 3;

    qkv_load(Ah, Al, Bh, Bl, gXh, gXl, gWh, gWl, 0, m0, 0, wbase, tid);
    CP_COMMIT;

    const int NT = DD / 32;  // 24
    for (int it = 0; it < NT; it++) {
        int p = it & 1;
        if (it + 1 < NT) {
            qkv_load(Ah, Al, Bh, Bl, gXh, gXl, gWh, gWl, (it+1)&1, m0, (it+1)*32, wbase, tid);
            CP_COMMIT;
            CP_WAIT1;
        } else {
            CP_WAIT0;
        }
        __syncthreads();

        __half* Ahp = Ah + p * (128*QK_LDA);
        __half* Alp = Al + p * (128*QK_LDA);
        __half* Bhp = Bh + p * (32*QK_LDB);
        __half* Blp = Bl + p * (32*QK_LDB);

        #pragma unroll
        for (int ks = 0; ks < 2; ks++) {
            int k0 = ks * 16;
            unsigned ah[2][4], al[2][4];
            #pragma unroll
            for (int mf = 0; mf < 2; mf++) {
                int row = wm * 32 + mf * 16 + lrow;
                ldsm4(ah[mf], su32(Ahp + row * QK_LDA + k0 + lcol8));
                ldsm4(al[mf], su32(Alp + row * QK_LDA + k0 + lcol8));
            }
            #pragma unroll
            for (int nf2 = 0; nf2 < 3; nf2++) {
                unsigned bh[4], bl[4];
                int n0 = wn * 48 + nf2 * 16;
                int brow = k0 + lrow;
                ldsm4t(bh, su32(Bhp + brow * QK_LDB + n0 + lcol8));
                ldsm4t(bl, su32(Blp + brow * QK_LDB + n0 + lcol8));
                #pragma unroll
                for (int hn = 0; hn < 2; hn++) {
                    #pragma unroll
                    for (int mf = 0; mf < 2; mf++) {
                        float* c = acc[mf][nf2*2 + hn];
                        mma16816(c, ah[mf], bh + hn*2);
                        mma16816(c, ah[mf], bl + hn*2);
                        mma16816(c, al[mf], bh + hn*2);
                    }
                }
            }
        }
        __syncthreads();
    }

    #pragma unroll
    for (int mf = 0; mf < 2; mf++) {
        #pragma unroll
        for (int nf = 0; nf < 6; nf++) {
            int col = wn * 48 + nf * 8 + (lane & 3) * 2;
            float b0 = bias[h*DHH + col], b1 = bias[h*DHH + col + 1];
            #pragma unroll
            for (int hr = 0; hr < 2; hr++) {
                int m = m0 + wm * 32 + mf * 16 + (lane >> 2) + hr * 8;
                int bb = m >> 11, s = m & 2047;
                size_t off = (((size_t)(bb * HH + h)) * SS + s) * DHH + col;
                float v0 = acc[mf][nf][hr*2 + 0] + b0;
                float v1 = acc[mf][nf][hr*2 + 1] + b1;
                __half h0,l0,h1,l1; splitf(v0,h0,l0); splitf(v1,h1,l1);
                *(half2*)(oh + off) = __halves2half2(h0,h1);
                *(half2*)(ol + off) = __halves2half2(l0,l1);
            }
        }
    }
}

// ---------------------------------------------------------------------------
// Flash attention, split-fp16 HMMA, cp.async double-buffered K/V tiles (64).
// Block = (b,h,128 q rows), 8 warps x 16 rows. grid=(16, 8, 4).
// ---------------------------------------------------------------------------
#define AT_LD 104
#define KV_STG (64*AT_LD)

__device__ __forceinline__ void attn_load_kv(
    __half* Kh, __half* Kl, __half* Vh, __half* Vl,
    int p, size_t gbase, int tid)
{
    #pragma unroll
    for (int j = 0; j < 12; j++) {
        int c = tid + j * 256;
        int arr = c / 768;
        int rem = c - arr * 768;
        int row = rem / 12;
        int off = (rem - row * 12) * 8;
        const __half* sp = (arr == 0) ? g_Kh : (arr == 1) ? g_Kl : (arr == 2) ? g_Vh : g_Vl;
        __half* dp = (arr == 0) ? Kh : (arr == 1) ? Kl : (arr == 2) ? Vh : Vl;
        CPA(su32(dp + p * KV_STG + row * AT_LD + off), sp + (gbase + row) * DHH + off);
    }
}

__global__ __launch_bounds__(256) void attn_kernel()
{
    extern __shared__ __half smh[];
    __half* Qh = smh;                 // [128][104]
    __half* Ql = Qh + 128 * AT_LD;
    __half* Kh = Ql + 128 * AT_LD;    // 2 stages x [64][104]
    __half* Kl = Kh + 2 * KV_STG;
    __half* Vh = Kl + 2 * KV_STG;
    __half* Vl = Vh + 2 * KV_STG;

    const int b  = blockIdx.z, h = blockIdx.y;
    const int s0 = blockIdx.x * 128;
    const int tid = threadIdx.x, wid = tid >> 5, lane = tid & 31;
    const size_t base = ((size_t)(b * HH + h)) * SS;
    const float scale = rsqrtf(96.0f);

    {   // load Q tile (hi/lo), plain loads
        int r = tid >> 1, c0 = (tid & 1) * 48;
        size_t go = (base + s0 + r) * DHH + c0;
        __half* dh = Qh + r * AT_LD + c0;
        __half* dl = Ql + r * AT_LD + c0;
        #pragma unroll
        for (int i = 0; i < 6; i++) {
            *(uint4*)(dh + i*8) = *(const uint4*)(g_Qh + go + i*8);
            *(uint4*)(dl + i*8) = *(const uint4*)(g_Ql + go + i*8);
        }
    }

    attn_load_kv(Kh, Kl, Vh, Vl, 0, base, tid);
    CP_COMMIT;

    float oacc[12][4];
    #pragma unroll
    for (int j = 0; j < 12; j++)
        #pragma unroll
        for (int t = 0; t < 4; t++) oacc[j][t] = 0.f;
    float m0r = -1e30f, m1r = -1e30f, l0r = 0.f, l1r = 0.f;

    const int lrow = lane & 15, lcol8 = (lane >> 4) << 3;
    const int krow_off = (lane & 7) + ((lane & 16) >> 1);
    const int kcol_off = (lane & 8);

    const int NT = SS / 64;  // 32
    for (int it = 0; it < NT; it++) {
        int p = it & 1;
        if (it + 1 < NT) {
            attn_load_kv(Kh, Kl, Vh, Vl, (it+1)&1, base + (size_t)(it+1)*64, tid);
            CP_COMMIT;
            CP_WAIT1;
        } else {
            CP_WAIT0;
        }
        __syncthreads();

        __half* Khp = Kh + p * KV_STG;
        __half* Klp = Kl + p * KV_STG;
        __half* Vhp = Vh + p * KV_STG;
        __half* Vlp = Vl + p * KV_STG;

        // S = Q @ K^T
        float sacc[8][4];
        #pragma unroll
        for (int j = 0; j < 8; j++)
            #pragma unroll
            for (int t = 0; t < 4; t++) sacc[j][t] = 0.f;

        #pragma unroll
        for (int dk = 0; dk < 6; dk++) {
            int d0 = dk * 16;
            unsigned ah[4], al[4];
            int qrow = wid * 16 + lrow;
            ldsm4(ah, su32(Qh + qrow * AT_LD + d0 + lcol8));
            ldsm4(al, su32(Ql + qrow * AT_LD + d0 + lcol8));
            #pragma unroll
            for (int nf2 = 0; nf2 < 4; nf2++) {
                unsigned bh[4], bl[4];
                int n0 = nf2 * 16;
                ldsm4(bh, su32(Khp + (n0 + krow_off) * AT_LD + d0 + kcol_off));
                ldsm4(bl, su32(Klp + (n0 + krow_off) * AT_LD + d0 + kcol_off));
                #pragma unroll
                for (int hn = 0; hn < 2; hn++) {
                    float* c = sacc[nf2*2 + hn];
                    mma16816(c, ah, bh + hn*2);
                    mma16816(c, ah, bl + hn*2);
                    mma16816(c, al, bh + hn*2);
                }
            }
        }

        // online softmax
        float mx0 = -1e30f, mx1 = -1e30f;
        #pragma unroll
        for (int j = 0; j < 8; j++) {
            #pragma unroll
            for (int t = 0; t < 4; t++) sacc[j][t] *= scale;
            mx0 = fmaxf(mx0, fmaxf(sacc[j][0], sacc[j][1]));
            mx1 = fmaxf(mx1, fmaxf(sacc[j][2], sacc[j][3]));
        }
        mx0 = fmaxf(mx0, __shfl_xor_sync(0xffffffffu, mx0, 1));
        mx0 = fmaxf(mx0, __shfl_xor_sync(0xffffffffu, mx0, 2));
        mx1 = fmaxf(mx1, __shfl_xor_sync(0xffffffffu, mx1, 1));
        mx1 = fmaxf(mx1, __shfl_xor_sync(0xffffffffu, mx1, 2));
        float mn0 = fmaxf(m0r, mx0), mn1 = fmaxf(m1r, mx1);
        float corr0 = __expf(m0r - mn0), corr1 = __expf(m1r - mn1);
        m0r = mn0; m1r = mn1;
        float sum0 = 0.f, sum1 = 0.f;
        #pragma unroll
        for (int j = 0; j < 8; j++) {
            sacc[j][0] = __expf(sacc[j][0] - mn0);
            sacc[j][1] = __expf(sacc[j][1] - mn0);
            sacc[j][2] = __expf(sacc[j][2] - mn1);
            sacc[j][3] = __expf(sacc[j][3] - mn1);
            sum0 += sacc[j][0] + sacc[j][1];
            sum1 += sacc[j][2] + sacc[j][3];
        }
        sum0 += __shfl_xor_sync(0xffffffffu, sum0, 1);
        sum0 += __shfl_xor_sync(0xffffffffu, sum0, 2);
        sum1 += __shfl_xor_sync(0xffffffffu, sum1, 1);
        sum1 += __shfl_xor_sync(0xffffffffu, sum1, 2);
        l0r = l0r * corr0 + sum0;
        l1r = l1r * corr1 + sum1;

        #pragma unroll
        for (int j = 0; j < 12; j++) {
            oacc[j][0] *= corr0; oacc[j][1] *= corr0;
            oacc[j][2] *= corr1; oacc[j][3] *= corr1;
        }

        // P fragments (register pass, split hi/lo)
        unsigned ph[4][4], pl[4][4];
        #pragma unroll
        for (int kf = 0; kf < 4; kf++) {
            #pragma unroll
            for (int q = 0; q < 4; q++) {
                int fj = kf*2 + (q >> 1);
                int t0 = (q & 1) * 2;
                float v0 = sacc[fj][t0], v1 = sacc[fj][t0 + 1];
                __half h0,l0,h1,l1; splitf(v0,h0,l0); splitf(v1,h1,l1);
                ph[kf][q] = h2u(__halves2half2(h0,h1));
                pl[kf][q] = h2u(__halves2half2(l0,l1));
            }
        }

        // O += P @ V
        #pragma unroll
        for (int kf = 0; kf < 4; kf++) {
            int k0 = kf * 16;
            #pragma unroll
            for (int nf2 = 0; nf2 < 6; nf2++) {
                unsigned bh[4], bl[4];
                int n0 = nf2 * 16;
                int vrow = k0 + lrow;
                ldsm4t(bh, su32(Vhp + vrow * AT_LD + n0 + lcol8));
                ldsm4t(bl, su32(Vlp + vrow * AT_LD + n0 + lcol8));
                #pragma unroll
                for (int hn = 0; hn < 2; hn++) {
                    float* c = oacc[nf2*2 + hn];
                    mma16816(c, ph[kf], bh + hn*2);
                    mma16816(c, ph[kf], bl + hn*2);
                    mma16816(c, pl[kf], bh + hn*2);
                }
            }
        }
        __syncthreads();
    }

    // Epilogue: normalize, split-store to cat [M][768] hi/lo
    float inv0 = 1.0f / l0r, inv1 = 1.0f / l1r;
    #pragma unroll
    for (int nf = 0; nf < 12; nf++) {
        int col = h * DHH + nf * 8 + (lane & 3) * 2;
        #pragma unroll
        for (int hr = 0; hr < 2; hr++) {
            int s = s0 + wid * 16 + (lane >> 2) + hr * 8;
            size_t off = ((size_t)b * SS + s) * DD + col;
            float inv = hr ? inv1 : inv0;
            float v0 = oacc[nf][hr*2 + 0] * inv;
            float v1 = oacc[nf][hr*2 + 1] * inv;
            __half h0,l0,h1,l1; splitf(v0,h0,l0); splitf(v1,h1,l1);
            *(half2*)(g_cath + off) = __halves2half2(h0,h1);
            *(half2*)(g_catl + off) = __halves2half2(l0,l1);
        }
    }
}

// ---------------------------------------------------------------------------
// Output projection: out[128x128] = cat[128x768] @ Wo[768x128] + bo.
// cp.async double-buffered. 8 warps (4m x 2n). grid=(64, 6).
// ---------------------------------------------------------------------------
#define OP_LDA 40
#define OP_LDB 136

__device__ __forceinline__ void oproj_load(
    __half* Ah, __half* Al, __half* Bh, __half* Bl,
    int p, int m0, int n0b, int kt, int tid)
{
    #pragma unroll
    for (int j = 0; j < 8; j++) {
        int c = tid + j * 256;
        if (c < 1024) {
            int arr = c >> 9, rem = c & 511, row = rem >> 2, off = (rem & 3) * 8;
            const __half* sp = (arr ? g_catl : g_cath) + (size_t)(m0 + row) * DD + kt + off;
            __half* dp = (arr ? Al : Ah) + p * (128*OP_LDA) + row * OP_LDA + off;
            CPA(su32(dp), sp);
        } else {
            int c2 = c - 1024;
            int arr = c2 >> 9, rem = c2 & 511, row = rem >> 4, off = (rem & 15) * 8;
            const __half* sp = (arr ? g_Wol : g_Woh) + (size_t)(kt + row) * DD + n0b + off;
            __half* dp = (arr ? Bl : Bh) + p * (32*OP_LDB) + row * OP_LDB + off;
            CPA(su32(dp), sp);
        }
    }
}

__global__ __launch_bounds__(256) void oproj_kernel(
    const float* __restrict__ bo, float* __restrict__ out)
{
    extern __shared__ __half smo[];
    __half* Ah = smo;
    __half* Al = Ah + 2*128*OP_LDA;
    __half* Bh = Al + 2*128*OP_LDA;
    __half* Bl = Bh + 2*32*OP_LDB;

    const int m0  = blockIdx.x * 128;
    const int n0b = blockIdx.y * 128;
    const int tid = threadIdx.x, wid = tid >> 5, lane = tid & 31;
    const int wm = wid >> 1, wn = wid & 1;

    float acc[2][8][4];
    #pragma unroll
    for (int i = 0; i < 2; i++)
        #pragma unroll
        for (int j = 0; j < 8; j++)
            #pragma unroll
            for (int k = 0; k < 4; k++) acc[i][j][k] = 0.f;

    const int lrow = lane & 15, lcol8 = (lane >> 4) << 3;

    oproj_load(Ah, Al, Bh, Bl, 0, m0, n0b, 0, tid);
    CP_COMMIT;

    const int NT = DD / 32;
    for (int it = 0; it < NT; it++) {
        int p = it & 1;
        if (it + 1 < NT) {
            oproj_load(Ah, Al, Bh, Bl, (it+1)&1, m0, n0b, (it+1)*32, tid);
            CP_COMMIT;
            CP_WAIT1;
        } else {
            CP_WAIT0;
        }
        __syncthreads();

        __half* Ahp = Ah + p * (128*OP_LDA);
        __half* Alp = Al + p * (128*OP_LDA);
        __half* Bhp = Bh + p * (32*OP_LDB);
        __half* Blp = Bl + p * (32*OP_LDB);

        #pragma unroll
        for (int ks = 0; ks < 2; ks++) {
            int k0 = ks * 16;
            unsigned ah[2][4], al[2][4];
            #pragma unroll
            for (int mf = 0; mf < 2; mf++) {
                int row = wm * 32 + mf * 16 + lrow;
                ldsm4(ah[mf], su32(Ahp + row * OP_LDA + k0 + lcol8));
                ldsm4(al[mf], su32(Alp + row * OP_LDA + k0 + lcol8));
            }
            #pragma unroll
            for (int nf2 = 0; nf2 < 4; nf2++) {
                unsigned bh[4], bl[4];
                int n0 = wn * 64 + nf2 * 16;
                int brow = k0 + lrow;
                ldsm4t(bh, su32(Bhp + brow * OP_LDB + n0 + lcol8));
                ldsm4t(bl, su32(Blp + brow * OP_LDB + n0 + lcol8));
                #pragma unroll
                for (int hn = 0; hn < 2; hn++) {
                    #pragma unroll
                    for (int mf = 0; mf < 2; mf++) {
                        float* c = acc[mf][nf2*2 + hn];
                        mma16816(c, ah[mf], bh + hn*2);
                        mma16816(c, ah[mf], bl + hn*2);
                        mma16816(c, al[mf], bh + hn*2);
                    }
                }
            }
        }
        __syncthreads();
    }

    #pragma unroll
    for (int mf = 0; mf < 2; mf++) {
        #pragma unroll
        for (int nf = 0; nf < 8; nf++) {
            int col = n0b + wn * 64 + nf * 8 + (lane & 3) * 2;
            float b0 = bo[col], b1 = bo[col + 1];
            #pragma unroll
            for (int hr = 0; hr < 2; hr++) {
                int m = m0 + wm * 32 + mf * 16 + (lane >> 2) + hr * 8;
                float2 v = make_float2(acc[mf][nf][hr*2+0] + b0,
                                       acc[mf][nf][hr*2+1] + b1);
                *(float2*)(out + (size_t)m * DD + col) = v;
            }
        }
    }
}

// ---------------------------------------------------------------------------
extern "C" void kernel_launch(void* const* d_in, const int* in_sizes, int n_in,
                              void* d_out, int out_size)
{
    (void)in_sizes; (void)n_in; (void)out_size;
    const float* Xq = (const float*)d_in[0];
    const float* Xk = (const float*)d_in[1];
    const float* Xv = (const float*)d_in[2];
    const float* Wq = (const float*)d_in[3];
    const float* bq = (const float*)d_in[4];
    const float* Wk = (const float*)d_in[5];
    const float* bk = (const float*)d_in[6];
    const float* Wv = (const float*)d_in[7];
    const float* bv = (const float*)d_in[8];
    const float* Wo = (const float*)d_in[9];
    const float* bo = (const float*)d_in[10];
    float* out = (float*)d_out;

    const int nX4 = MM * DD / 4;          // 1572864
    const int nW4 = HH * DD * DHH / 4;    // 147456
    const int nWo4 = DD * DD / 4;         // 147456
    split_kernel<<<(nX4 + 255) / 256, 256>>>(Xq, 0, nX4);
    split_kernel<<<(nX4 + 255) / 256, 256>>>(Xk, 1, nX4);
    split_kernel<<<(nX4 + 255) / 256, 256>>>(Xv, 2, nX4);
    split_kernel<<<(nW4 + 255) / 256, 256>>>(Wq, 3, nW4);
    split_kernel<<<(nW4 + 255) / 256, 256>>>(Wk, 4, nW4);
    split_kernel<<<(nW4 + 255) / 256, 256>>>(Wv, 5, nW4);
    split_kernel<<<(nWo4 + 255) / 256, 256>>>(Wo, 6, nWo4);

    const int smem_qkv = (2*128*QK_LDA*2 + 2*32*QK_LDB*2) * (int)sizeof(__half);
    cudaFuncSetAttribute(qkv_kernel, cudaFuncAttributeMaxDynamicSharedMemorySize, smem_qkv);
    dim3 gq(MM / 128, HH, 3);
    qkv_kernel<<<gq, 256, smem_qkv>>>(bq, bk, bv);

    const int smem_attn = (2*128*AT_LD + 4*2*KV_STG) * (int)sizeof(__half);
    cudaFuncSetAttribute(attn_kernel, cudaFuncAttributeMaxDynamicSharedMemorySize, smem_attn);
    dim3 ga(SS / 128, HH, BB);
    attn_kernel<<<ga, 256, smem_attn>>>();

    const int smem_op = (2*128*OP_LDA*2 + 2*32*OP_LDB*2) * (int)sizeof(__half);
    cudaFuncSetAttribute(oproj_kernel, cudaFuncAttributeMaxDynamicSharedMemorySize, smem_op);
    dim3 go(MM / 128, DD / 128);
    oproj_kernel<<<go, 256, smem_op>>>(bo, out);
}

// round 5
// speedup vs baseline: 3.0334x; 1.0372x over previous
#include <cuda_runtime.h>
#include <cuda_fp16.h>

#define BB 4
#define SS 2048
#define DD 768
#define HH 8
#define DHH 96
#define MM (BB*SS)   // 8192

// Split hi/lo fp16 scratch
__device__ __half g_Xqh[(size_t)MM*DD], g_Xql[(size_t)MM*DD];
__device__ __half g_Xkh[(size_t)MM*DD], g_Xkl[(size_t)MM*DD];
__device__ __half g_Xvh[(size_t)MM*DD], g_Xvl[(size_t)MM*DD];
__device__ __half g_Wqh[(size_t)HH*DD*DHH], g_Wql[(size_t)HH*DD*DHH];
__device__ __half g_Wkh[(size_t)HH*DD*DHH], g_Wkl[(size_t)HH*DD*DHH];
__device__ __half g_Wvh[(size_t)HH*DD*DHH], g_Wvl[(size_t)HH*DD*DHH];
__device__ __half g_Woh[(size_t)DD*DD],     g_Wol[(size_t)DD*DD];
__device__ __half g_Qh[(size_t)BB*HH*SS*DHH], g_Ql[(size_t)BB*HH*SS*DHH];
__device__ __half g_Kh[(size_t)BB*HH*SS*DHH], g_Kl[(size_t)BB*HH*SS*DHH];
__device__ __half g_Vh[(size_t)BB*HH*SS*DHH], g_Vl[(size_t)BB*HH*SS*DHH];
__device__ __half g_cath[(size_t)MM*DD],      g_catl[(size_t)MM*DD];

__device__ __forceinline__ unsigned su32(const void* p) {
    return (unsigned)__cvta_generic_to_shared(p);
}
__device__ __forceinline__ unsigned h2u(half2 v) {
    union { half2 h; unsigned u; } x; x.h = v; return x.u;
}
__device__ __forceinline__ void ldsm4(unsigned r[4], unsigned addr) {
    asm volatile("ldmatrix.sync.aligned.m8n8.x4.shared.b16 {%0,%1,%2,%3},[%4];\n"
        : "=r"(r[0]), "=r"(r[1]), "=r"(r[2]), "=r"(r[3]) : "r"(addr));
}
__device__ __forceinline__ void ldsm4t(unsigned r[4], unsigned addr) {
    asm volatile("ldmatrix.sync.aligned.m8n8.x4.trans.shared.b16 {%0,%1,%2,%3},[%4];\n"
        : "=r"(r[0]), "=r"(r[1]), "=r"(r[2]), "=r"(r[3]) : "r"(addr));
}
__device__ __forceinline__ void mma16816(float* c, const unsigned* a, const unsigned* b) {
    asm volatile("mma.sync.aligned.m16n8k16.row.col.f32.f16.f16.f32 "
        "{%0,%1,%2,%3},{%4,%5,%6,%7},{%8,%9},{%0,%1,%2,%3};\n"
        : "+f"(c[0]), "+f"(c[1]), "+f"(c[2]), "+f"(c[3])
        : "r"(a[0]), "r"(a[1]), "r"(a[2]), "r"(a[3]), "r"(b[0]), "r"(b[1]));
}
__device__ __forceinline__ void splitf(float x, __half& h, __half& l) {
    h = __float2half_rn(x);
    l = __float2half_rn(x - __half2float(h));
}
#define CPA(dst, src) asm volatile("cp.async.cg.shared.global [%0], [%1], 16;\n" :: "r"(dst), "l"(src))
#define CP_COMMIT asm volatile("cp.async.commit_group;\n")
#define CP_WAIT1  asm volatile("cp.async.wait_group 1;\n")
#define CP_WAIT0  asm volatile("cp.async.wait_group 0;\n")

// ---------------------------------------------------------------------------
// Fused preconvert fp32 -> split hi/lo fp16 (one launch for all 7 tensors)
// ---------------------------------------------------------------------------
#define NX4 (MM*DD/4)          // 1572864
#define NW4 (HH*DD*DHH/4)      // 147456

__global__ __launch_bounds__(256) void split_all(
    const float* __restrict__ Xq, const float* __restrict__ Xk, const float* __restrict__ Xv,
    const float* __restrict__ Wq, const float* __restrict__ Wk, const float* __restrict__ Wv,
    const float* __restrict__ Wo)
{
    int i = blockIdx.x * 256 + threadIdx.x;
    const float* src; __half *dh, *dl; int off;
    if (i < 3 * NX4) {
        int t = i / NX4; off = i - t * NX4;
        src = (t == 0) ? Xq : (t == 1) ? Xk : Xv;
        dh  = (t == 0) ? g_Xqh : (t == 1) ? g_Xkh : g_Xvh;
        dl  = (t == 0) ? g_Xql : (t == 1) ? g_Xkl : g_Xvl;
    } else {
        int j = i - 3 * NX4;
        int t = j / NW4; off = j - t * NW4;
        src = (t == 0) ? Wq : (t == 1) ? Wk : (t == 2) ? Wv : Wo;
        dh  = (t == 0) ? g_Wqh : (t == 1) ? g_Wkh : (t == 2) ? g_Wvh : g_Woh;
        dl  = (t == 0) ? g_Wql : (t == 1) ? g_Wkl : (t == 2) ? g_Wvl : g_Wol;
    }
    float4 v = ((const float4*)src)[off];
    union { __half h[4]; uint2 u; } ph, pl;
    splitf(v.x, ph.h[0], pl.h[0]);
    splitf(v.y, ph.h[1], pl.h[1]);
    splitf(v.z, ph.h[2], pl.h[2]);
    splitf(v.w, ph.h[3], pl.h[3]);
    ((uint2*)dh)[off] = ph.u;
    ((uint2*)dl)[off] = pl.u;
}

// ---------------------------------------------------------------------------
// QKV GEMM: C[128x96] = X[128x768] @ W[768x96] + bias. Split-fp16 HMMA.
// cp.async double-buffered BK=32. Q output pre-scaled by 1/sqrt(96).
// ---------------------------------------------------------------------------
#define QK_LDA 40
#define QK_LDB 104

__device__ __forceinline__ void qkv_load(
    __half* Ah, __half* Al, __half* Bh, __half* Bl,
    const __half* gXh, const __half* gXl, const __half* gWh, const __half* gWl,
    int p, int m0, int kt, size_t wbase, int tid)
{
    #pragma unroll
    for (int j = 0; j < 7; j++) {
        int c = tid + j * 256;
        if (c < 1024) {
            int arr = c >> 9, rem = c & 511, row = rem >> 2, off = (rem & 3) * 8;
            const __half* sp = (arr ? gXl : gXh) + (size_t)(m0 + row) * DD + kt + off;
            __half* dp = (arr ? Al : Ah) + p * (128*QK_LDA) + row * QK_LDA + off;
            CPA(su32(dp), sp);
        } else {
            int c2 = c - 1024;
            int arr = (c2 >= 384) ? 1 : 0;
            int rem = c2 - arr * 384;
            int row = rem / 12, off = (rem - row * 12) * 8;
            const __half* sp = (arr ? gWl : gWh) + wbase + (size_t)(kt + row) * DHH + off;
            __half* dp = (arr ? Bl : Bh) + p * (32*QK_LDB) + row * QK_LDB + off;
            CPA(su32(dp), sp);
        }
    }
}

__global__ __launch_bounds__(256) void qkv_kernel(
    const float* __restrict__ bq, const float* __restrict__ bk, const float* __restrict__ bv)
{
    extern __shared__ __half smq[];
    __half* Ah = smq;
    __half* Al = Ah + 2*128*QK_LDA;
    __half* Bh = Al + 2*128*QK_LDA;
    __half* Bl = Bh + 2*32*QK_LDB;

    const __half *gXh, *gXl, *gWh, *gWl; const float* bias; __half *oh, *ol;
    if (blockIdx.z == 0)      { gXh=g_Xqh; gXl=g_Xql; gWh=g_Wqh; gWl=g_Wql; bias=bq; oh=g_Qh; ol=g_Ql; }
    else if (blockIdx.z == 1) { gXh=g_Xkh; gXl=g_Xkl; gWh=g_Wkh; gWl=g_Wkl; bias=bk; oh=g_Kh; ol=g_Kl; }
    else                      { gXh=g_Xvh; gXl=g_Xvl; gWh=g_Wvh; gWl=g_Wvl; bias=bv; oh=g_Vh; ol=g_Vl; }
    const float oscale = (blockIdx.z == 0) ? rsqrtf(96.0f) : 1.0f;

    const int h   = blockIdx.y;
    const int m0  = blockIdx.x * 128;
    const int tid = threadIdx.x;
    const int wid = tid >> 5, lane = tid & 31;
    const int wm  = wid >> 1, wn = wid & 1;
    const size_t wbase = (size_t)h * DD * DHH;

    float acc[2][6][4];
    #pragma unroll
    for (int i = 0; i < 2; i++)
        #pragma unroll
        for (int j = 0; j < 6; j++)
            #pragma unroll
            for (int k = 0; k < 4; k++) acc[i][j][k] = 0.f;

    const int lrow = lane & 15, lcol8 = (lane >> 4) << 3;

    qkv_load(Ah, Al, Bh, Bl, gXh, gXl, gWh, gWl, 0, m0, 0, wbase, tid);
    CP_COMMIT;

    const int NT = DD / 32;
    for (int it = 0; it < NT; it++) {
        int p = it & 1;
        if (it + 1 < NT) {
            qkv_load(Ah, Al, Bh, Bl, gXh, gXl, gWh, gWl, (it+1)&1, m0, (it+1)*32, wbase, tid);
            CP_COMMIT;
            CP_WAIT1;
        } else {
            CP_WAIT0;
        }
        __syncthreads();

        __half* Ahp = Ah + p * (128*QK_LDA);
        __half* Alp = Al + p * (128*QK_LDA);
        __half* Bhp = Bh + p * (32*QK_LDB);
        __half* Blp = Bl + p * (32*QK_LDB);

        #pragma unroll
        for (int ks = 0; ks < 2; ks++) {
            int k0 = ks * 16;
            unsigned ah[2][4], al[2][4];
            #pragma unroll
            for (int mf = 0; mf < 2; mf++) {
                int row = wm * 32 + mf * 16 + lrow;
                ldsm4(ah[mf], su32(Ahp + row * QK_LDA + k0 + lcol8));
                ldsm4(al[mf], su32(Alp + row * QK_LDA + k0 + lcol8));
            }
            #pragma unroll
            for (int nf2 = 0; nf2 < 3; nf2++) {
                unsigned bh[4], bl[4];
                int n0 = wn * 48 + nf2 * 16;
                int brow = k0 + lrow;
                ldsm4t(bh, su32(Bhp + brow * QK_LDB + n0 + lcol8));
                ldsm4t(bl, su32(Blp + brow * QK_LDB + n0 + lcol8));
                #pragma unroll
                for (int hn = 0; hn < 2; hn++) {
                    #pragma unroll
                    for (int mf = 0; mf < 2; mf++) {
                        float* c = acc[mf][nf2*2 + hn];
                        mma16816(c, ah[mf], bh + hn*2);
                        mma16816(c, ah[mf], bl + hn*2);
                        mma16816(c, al[mf], bh + hn*2);
                    }
                }
            }
        }
        __syncthreads();
    }

    #pragma unroll
    for (int mf = 0; mf < 2; mf++) {
        #pragma unroll
        for (int nf = 0; nf < 6; nf++) {
            int col = wn * 48 + nf * 8 + (lane & 3) * 2;
            float b0 = bias[h*DHH + col], b1 = bias[h*DHH + col + 1];
            #pragma unroll
            for (int hr = 0; hr < 2; hr++) {
                int m = m0 + wm * 32 + mf * 16 + (lane >> 2) + hr * 8;
                int bb = m >> 11, s = m & 2047;
                size_t off = (((size_t)(bb * HH + h)) * SS + s) * DHH + col;
                float v0 = (acc[mf][nf][hr*2 + 0] + b0) * oscale;
                float v1 = (acc[mf][nf][hr*2 + 1] + b1) * oscale;
                __half h0,l0,h1,l1; splitf(v0,h0,l0); splitf(v1,h1,l1);
                *(half2*)(oh + off) = __halves2half2(h0,h1);
                *(half2*)(ol + off) = __halves2half2(l0,l1);
            }
        }
    }
}

// ---------------------------------------------------------------------------
// Flash attention. Single K and V buffers, split-group cp.async pipelining:
//   wait K(i) -> S -> sync -> issue K(i+1) -> softmax/P (regs) -> wait V(i)
//   -> PV -> sync -> issue V(i+1).
// smem = 104 KB -> 2 blocks/SM. __launch_bounds__(256,2).
// ---------------------------------------------------------------------------
#define AT_LD 104

__device__ __forceinline__ void attn_load_k(__half* Kh, __half* Kl, size_t gbase, int tid)
{
    #pragma unroll
    for (int j = 0; j < 6; j++) {
        int c = tid + j * 256;            // 0..1535
        int arr = (c >= 768) ? 1 : 0;
        int rem = c - arr * 768;
        int row = rem / 12;
        int off = (rem - row * 12) * 8;
        const __half* sp = (arr ? g_Kl : g_Kh) + (gbase + row) * DHH + off;
        __half* dp = (arr ? Kl : Kh) + row * AT_LD + off;
        CPA(su32(dp), sp);
    }
}
__device__ __forceinline__ void attn_load_v(__half* Vh, __half* Vl, size_t gbase, int tid)
{
    #pragma unroll
    for (int j = 0; j < 6; j++) {
        int c = tid + j * 256;
        int arr = (c >= 768) ? 1 : 0;
        int rem = c - arr * 768;
        int row = rem / 12;
        int off = (rem - row * 12) * 8;
        const __half* sp = (arr ? g_Vl : g_Vh) + (gbase + row) * DHH + off;
        __half* dp = (arr ? Vl : Vh) + row * AT_LD + off;
        CPA(su32(dp), sp);
    }
}

__global__ __launch_bounds__(256, 2) void attn_kernel()
{
    extern __shared__ __half smh[];
    __half* Qh = smh;                 // [128][104]
    __half* Ql = Qh + 128 * AT_LD;
    __half* Kh = Ql + 128 * AT_LD;    // [64][104]
    __half* Kl = Kh + 64 * AT_LD;
    __half* Vh = Kl + 64 * AT_LD;     // [64][104]
    __half* Vl = Vh + 64 * AT_LD;

    const int b  = blockIdx.z, h = blockIdx.y;
    const int s0 = blockIdx.x * 128;
    const int tid = threadIdx.x, wid = tid >> 5, lane = tid & 31;
    const size_t base = ((size_t)(b * HH + h)) * SS;

    {   // load Q tile (hi/lo; pre-scaled by qkv)
        int r = tid >> 1, c0 = (tid & 1) * 48;
        size_t go = (base + s0 + r) * DHH + c0;
        __half* dh = Qh + r * AT_LD + c0;
        __half* dl = Ql + r * AT_LD + c0;
        #pragma unroll
        for (int i = 0; i < 6; i++) {
            *(uint4*)(dh + i*8) = *(const uint4*)(g_Qh + go + i*8);
            *(uint4*)(dl + i*8) = *(const uint4*)(g_Ql + go + i*8);
        }
    }

    attn_load_k(Kh, Kl, base, tid); CP_COMMIT;
    attn_load_v(Vh, Vl, base, tid); CP_COMMIT;

    float oacc[12][4];
    #pragma unroll
    for (int j = 0; j < 12; j++)
        #pragma unroll
        for (int t = 0; t < 4; t++) oacc[j][t] = 0.f;
    float m0r = -1e30f, m1r = -1e30f, l0r = 0.f, l1r = 0.f;

    const int lrow = lane & 15, lcol8 = (lane >> 4) << 3;
    const int krow_off = (lane & 7) + ((lane & 16) >> 1);
    const int kcol_off = (lane & 8);

    const int NT = SS / 64;  // 32
    for (int it = 0; it < NT; it++) {
        // K(it) arrived (all but newest group done; newest is V(it))
        CP_WAIT1;
        __syncthreads();

        // S = Q @ K^T
        float sacc[8][4];
        #pragma unroll
        for (int j = 0; j < 8; j++)
            #pragma unroll
            for (int t = 0; t < 4; t++) sacc[j][t] = 0.f;

        #pragma unroll
        for (int dk = 0; dk < 6; dk++) {
            int d0 = dk * 16;
            unsigned ah[4], al[4];
            int qrow = wid * 16 + lrow;
            ldsm4(ah, su32(Qh + qrow * AT_LD + d0 + lcol8));
            ldsm4(al, su32(Ql + qrow * AT_LD + d0 + lcol8));
            #pragma unroll
            for (int nf2 = 0; nf2 < 4; nf2++) {
                unsigned bh[4], bl[4];
                int n0 = nf2 * 16;
                ldsm4(bh, su32(Kh + (n0 + krow_off) * AT_LD + d0 + kcol_off));
                ldsm4(bl, su32(Kl + (n0 + krow_off) * AT_LD + d0 + kcol_off));
                #pragma unroll
                for (int hn = 0; hn < 2; hn++) {
                    float* c = sacc[nf2*2 + hn];
                    mma16816(c, ah, bh + hn*2);
                    mma16816(c, ah, bl + hn*2);
                    mma16816(c, al, bh + hn*2);
                }
            }
        }
        __syncthreads();   // all warps done reading K
        if (it + 1 < NT) { attn_load_k(Kh, Kl, base + (size_t)(it+1)*64, tid); CP_COMMIT; }

        // online softmax (registers only; covers V latency)
        float mx0 = -1e30f, mx1 = -1e30f;
        #pragma unroll
        for (int j = 0; j < 8; j++) {
            mx0 = fmaxf(mx0, fmaxf(sacc[j][0], sacc[j][1]));
            mx1 = fmaxf(mx1, fmaxf(sacc[j][2], sacc[j][3]));
        }
        mx0 = fmaxf(mx0, __shfl_xor_sync(0xffffffffu, mx0, 1));
        mx0 = fmaxf(mx0, __shfl_xor_sync(0xffffffffu, mx0, 2));
        mx1 = fmaxf(mx1, __shfl_xor_sync(0xffffffffu, mx1, 1));
        mx1 = fmaxf(mx1, __shfl_xor_sync(0xffffffffu, mx1, 2));
        float mn0 = fmaxf(m0r, mx0), mn1 = fmaxf(m1r, mx1);
        float corr0 = __expf(m0r - mn0), corr1 = __expf(m1r - mn1);
        m0r = mn0; m1r = mn1;
        float sum0 = 0.f, sum1 = 0.f;
        #pragma unroll
        for (int j = 0; j < 8; j++) {
            sacc[j][0] = __expf(sacc[j][0] - mn0);
            sacc[j][1] = __expf(sacc[j][1] - mn0);
            sacc[j][2] = __expf(sacc[j][2] - mn1);
            sacc[j][3] = __expf(sacc[j][3] - mn1);
            sum0 += sacc[j][0] + sacc[j][1];
            sum1 += sacc[j][2] + sacc[j][3];
        }
        sum0 += __shfl_xor_sync(0xffffffffu, sum0, 1);
        sum0 += __shfl_xor_sync(0xffffffffu, sum0, 2);
        sum1 += __shfl_xor_sync(0xffffffffu, sum1, 1);
        sum1 += __shfl_xor_sync(0xffffffffu, sum1, 2);
        l0r = l0r * corr0 + sum0;
        l1r = l1r * corr1 + sum1;

        #pragma unroll
        for (int j = 0; j < 12; j++) {
            oacc[j][0] *= corr0; oacc[j][1] *= corr0;
            oacc[j][2] *= corr1; oacc[j][3] *= corr1;
        }

        // P fragments (register pass, split hi/lo)
        unsigned ph[4][4], pl[4][4];
        #pragma unroll
        for (int kf = 0; kf < 4; kf++) {
            #pragma unroll
            for (int q = 0; q < 4; q++) {
                int fj = kf*2 + (q >> 1);
                int t0 = (q & 1) * 2;
                float v0 = sacc[fj][t0], v1 = sacc[fj][t0 + 1];
                __half h0,l0,h1,l1; splitf(v0,h0,l0); splitf(v1,h1,l1);
                ph[kf][q] = h2u(__halves2half2(h0,h1));
                pl[kf][q] = h2u(__halves2half2(l0,l1));
            }
        }

        // V(it) arrived
        if (it + 1 < NT) { CP_WAIT1; } else { CP_WAIT0; }
        __syncthreads();

        // O += P @ V
        #pragma unroll
        for (int kf = 0; kf < 4; kf++) {
            int k0 = kf * 16;
            #pragma unroll
            for (int nf2 = 0; nf2 < 6; nf2++) {
                unsigned bh[4], bl[4];
                int n0 = nf2 * 16;
                int vrow = k0 + lrow;
                ldsm4t(bh, su32(Vh + vrow * AT_LD + n0 + lcol8));
                ldsm4t(bl, su32(Vl + vrow * AT_LD + n0 + lcol8));
                #pragma unroll
                for (int hn = 0; hn < 2; hn++) {
                    float* c = oacc[nf2*2 + hn];
                    mma16816(c, ph[kf], bh + hn*2);
                    mma16816(c, ph[kf], bl + hn*2);
                    mma16816(c, pl[kf], bh + hn*2);
                }
            }
        }
        __syncthreads();   // all warps done reading V
        if (it + 1 < NT) { attn_load_v(Vh, Vl, base + (size_t)(it+1)*64, tid); CP_COMMIT; }
    }

    // Epilogue: normalize, split-store to cat [M][768] hi/lo
    float inv0 = 1.0f / l0r, inv1 = 1.0f / l1r;
    #pragma unroll
    for (int nf = 0; nf < 12; nf++) {
        int col = h * DHH + nf * 8 + (lane & 3) * 2;
        #pragma unroll
        for (int hr = 0; hr < 2; hr++) {
            int s = s0 + wid * 16 + (lane >> 2) + hr * 8;
            size_t off = ((size_t)b * SS + s) * DD + col;
            float inv = hr ? inv1 : inv0;
            float v0 = oacc[nf][hr*2 + 0] * inv;
            float v1 = oacc[nf][hr*2 + 1] * inv;
            __half h0,l0,h1,l1; splitf(v0,h0,l0); splitf(v1,h1,l1);
            *(half2*)(g_cath + off) = __halves2half2(h0,h1);
            *(half2*)(g_catl + off) = __halves2half2(l0,l1);
        }
    }
}

// ---------------------------------------------------------------------------
// Output projection: out[128x128] = cat[128x768] @ Wo[768x128] + bo.
// ---------------------------------------------------------------------------
#define OP_LDA 40
#define OP_LDB 136

__device__ __forceinline__ void oproj_load(
    __half* Ah, __half* Al, __half* Bh, __half* Bl,
    int p, int m0, int n0b, int kt, int tid)
{
    #pragma unroll
    for (int j = 0; j < 8; j++) {
        int c = tid + j * 256;
        if (c < 1024) {
            int arr = c >> 9, rem = c & 511, row = rem >> 2, off = (rem & 3) * 8;
            const __half* sp = (arr ? g_catl : g_cath) + (size_t)(m0 + row) * DD + kt + off;
            __half* dp = (arr ? Al : Ah) + p * (128*OP_LDA) + row * OP_LDA + off;
            CPA(su32(dp), sp);
        } else {
            int c2 = c - 1024;
            int arr = c2 >> 9, rem = c2 & 511, row = rem >> 4, off = (rem & 15) * 8;
            const __half* sp = (arr ? g_Wol : g_Woh) + (size_t)(kt + row) * DD + n0b + off;
            __half* dp = (arr ? Bl : Bh) + p * (32*OP_LDB) + row * OP_LDB + off;
            CPA(su32(dp), sp);
        }
    }
}

__global__ __launch_bounds__(256) void oproj_kernel(
    const float* __restrict__ bo, float* __restrict__ out)
{
    extern __shared__ __half smo[];
    __half* Ah = smo;
    __half* Al = Ah + 2*128*OP_LDA;
    __half* Bh = Al + 2*128*OP_LDA;
    __half* Bl = Bh + 2*32*OP_LDB;

    const int m0  = blockIdx.x * 128;
    const int n0b = blockIdx.y * 128;
    const int tid = threadIdx.x, wid = tid >> 5, lane = tid & 31;
    const int wm = wid >> 1, wn = wid & 1;

    float acc[2][8][4];
    #pragma unroll
    for (int i = 0; i < 2; i++)
        #pragma unroll
        for (int j = 0; j < 8; j++)
            #pragma unroll
            for (int k = 0; k < 4; k++) acc[i][j][k] = 0.f;

    const int lrow = lane & 15, lcol8 = (lane >> 4) << 3;

    oproj_load(Ah, Al, Bh, Bl, 0, m0, n0b, 0, tid);
    CP_COMMIT;

    const int NT = DD / 32;
    for (int it = 0; it < NT; it++) {
        int p = it & 1;
        if (it + 1 < NT) {
            oproj_load(Ah, Al, Bh, Bl, (it+1)&1, m0, n0b, (it+1)*32, tid);
            CP_COMMIT;
            CP_WAIT1;
        } else {
            CP_WAIT0;
        }
        __syncthreads();

        __half* Ahp = Ah + p * (128*OP_LDA);
        __half* Alp = Al + p * (128*OP_LDA);
        __half* Bhp = Bh + p * (32*OP_LDB);
        __half* Blp = Bl + p * (32*OP_LDB);

        #pragma unroll
        for (int ks = 0; ks < 2; ks++) {
            int k0 = ks * 16;
            unsigned ah[2][4], al[2][4];
            #pragma unroll
            for (int mf = 0; mf < 2; mf++) {
                int row = wm * 32 + mf * 16 + lrow;
                ldsm4(ah[mf], su32(Ahp + row * OP_LDA + k0 + lcol8));
                ldsm4(al[mf], su32(Alp + row * OP_LDA + k0 + lcol8));
            }
            #pragma unroll
            for (int nf2 = 0; nf2 < 4; nf2++) {
                unsigned bh[4], bl[4];
                int n0 = wn * 64 + nf2 * 16;
                int brow = k0 + lrow;
                ldsm4t(bh, su32(Bhp + brow * OP_LDB + n0 + lcol8));
                ldsm4t(bl, su32(Blp + brow * OP_LDB + n0 + lcol8));
                #pragma unroll
                for (int hn = 0; hn < 2; hn++) {
                    #pragma unroll
                    for (int mf = 0; mf < 2; mf++) {
                        float* c = acc[mf][nf2*2 + hn];
                        mma16816(c, ah[mf], bh + hn*2);
                        mma16816(c, ah[mf], bl + hn*2);
                        mma16816(c, al[mf], bh + hn*2);
                    }
                }
            }
        }
        __syncthreads();
    }

    #pragma unroll
    for (int mf = 0; mf < 2; mf++) {
        #pragma unroll
        for (int nf = 0; nf < 8; nf++) {
            int col = n0b + wn * 64 + nf * 8 + (lane & 3) * 2;
            float b0 = bo[col], b1 = bo[col + 1];
            #pragma unroll
            for (int hr = 0; hr < 2; hr++) {
                int m = m0 + wm * 32 + mf * 16 + (lane >> 2) + hr * 8;
                float2 v = make_float2(acc[mf][nf][hr*2+0] + b0,
                                       acc[mf][nf][hr*2+1] + b1);
                *(float2*)(out + (size_t)m * DD + col) = v;
            }
        }
    }
}

// ---------------------------------------------------------------------------
extern "C" void kernel_launch(void* const* d_in, const int* in_sizes, int n_in,
                              void* d_out, int out_size)
{
    (void)in_sizes; (void)n_in; (void)out_size;
    const float* Xq = (const float*)d_in[0];
    const float* Xk = (const float*)d_in[1];
    const float* Xv = (const float*)d_in[2];
    const float* Wq = (const float*)d_in[3];
    const float* bq = (const float*)d_in[4];
    const float* Wk = (const float*)d_in[5];
    const float* bk = (const float*)d_in[6];
    const float* Wv = (const float*)d_in[7];
    const float* bv = (const float*)d_in[8];
    const float* Wo = (const float*)d_in[9];
    const float* bo = (const float*)d_in[10];
    float* out = (float*)d_out;

    const int total4 = 3*NX4 + 4*NW4;
    split_all<<<(total4 + 255) / 256, 256>>>(Xq, Xk, Xv, Wq, Wk, Wv, Wo);

    const int smem_qkv = (2*128*QK_LDA*2 + 2*32*QK_LDB*2) * (int)sizeof(__half);
    cudaFuncSetAttribute(qkv_kernel, cudaFuncAttributeMaxDynamicSharedMemorySize, smem_qkv);
    dim3 gq(MM / 128, HH, 3);
    qkv_kernel<<<gq, 256, smem_qkv>>>(bq, bk, bv);

    const int smem_attn = (2*128*AT_LD + 4*64*AT_LD) * (int)sizeof(__half);  // 104 KB
    cudaFuncSetAttribute(attn_kernel, cudaFuncAttributeMaxDynamicSharedMemorySize, smem_attn);
    dim3 ga(SS / 128, HH, BB);
    attn_kernel<<<ga, 256, smem_attn>>>();

    const int smem_op = (2*128*OP_LDA*2 + 2*32*OP_LDB*2) * (int)sizeof(__half);
    cudaFuncSetAttribute(oproj_kernel, cudaFuncAttributeMaxDynamicSharedMemorySize, smem_op);
    dim3 go(MM / 128, DD / 128);
    oproj_kernel<<<go, 256, smem_op>>>(bo, out);
}

// round 7
// speedup vs baseline: 3.6808x; 1.2134x over previous
#include <cuda_runtime.h>
#include <cuda_fp16.h>

#define BB 4
#define SS 2048
#define DD 768
#define HH 8
#define DHH 96
#define MM (BB*SS)   // 8192

// Split hi/lo fp16 scratch
__device__ __half g_Xqh[(size_t)MM*DD], g_Xql[(size_t)MM*DD];
__device__ __half g_Xkh[(size_t)MM*DD], g_Xkl[(size_t)MM*DD];
__device__ __half g_Xvh[(size_t)MM*DD], g_Xvl[(size_t)MM*DD];
__device__ __half g_Wqh[(size_t)HH*DD*DHH], g_Wql[(size_t)HH*DD*DHH];
__device__ __half g_Wkh[(size_t)HH*DD*DHH], g_Wkl[(size_t)HH*DD*DHH];
__device__ __half g_Wvh[(size_t)HH*DD*DHH], g_Wvl[(size_t)HH*DD*DHH];
__device__ __half g_Woh[(size_t)DD*DD],     g_Wol[(size_t)DD*DD];
__device__ __half g_Qh[(size_t)BB*HH*SS*DHH], g_Ql[(size_t)BB*HH*SS*DHH];
__device__ __half g_Kh[(size_t)BB*HH*SS*DHH];   // K: hi only (2-term S)
__device__ __half g_Vh[(size_t)BB*HH*SS*DHH];   // V: hi only (2-term PV)
__device__ __half g_cath[(size_t)MM*DD],      g_catl[(size_t)MM*DD];

__device__ __forceinline__ unsigned su32(const void* p) {
    return (unsigned)__cvta_generic_to_shared(p);
}
__device__ __forceinline__ unsigned h2u(half2 v) {
    union { half2 h; unsigned u; } x; x.h = v; return x.u;
}
__device__ __forceinline__ void ldsm4(unsigned r[4], unsigned addr) {
    asm volatile("ldmatrix.sync.aligned.m8n8.x4.shared.b16 {%0,%1,%2,%3},[%4];\n"
        : "=r"(r[0]), "=r"(r[1]), "=r"(r[2]), "=r"(r[3]) : "r"(addr));
}
__device__ __forceinline__ void ldsm4t(unsigned r[4], unsigned addr) {
    asm volatile("ldmatrix.sync.aligned.m8n8.x4.trans.shared.b16 {%0,%1,%2,%3},[%4];\n"
        : "=r"(r[0]), "=r"(r[1]), "=r"(r[2]), "=r"(r[3]) : "r"(addr));
}
__device__ __forceinline__ void mma16816(float* c, const unsigned* a, const unsigned* b) {
    asm volatile("mma.sync.aligned.m16n8k16.row.col.f32.f16.f16.f32 "
        "{%0,%1,%2,%3},{%4,%5,%6,%7},{%8,%9},{%0,%1,%2,%3};\n"
        : "+f"(c[0]), "+f"(c[1]), "+f"(c[2]), "+f"(c[3])
        : "r"(a[0]), "r"(a[1]), "r"(a[2]), "r"(a[3]), "r"(b[0]), "r"(b[1]));
}
__device__ __forceinline__ void splitf(float x, __half& h, __half& l) {
    h = __float2half_rn(x);
    l = __float2half_rn(x - __half2float(h));
}
#define CPA(dst, src) asm volatile("cp.async.cg.shared.global [%0], [%1], 16;\n" :: "r"(dst), "l"(src))
#define CP_COMMIT asm volatile("cp.async.commit_group;\n")
#define CP_WAIT1  asm volatile("cp.async.wait_group 1;\n")
#define CP_WAIT0  asm volatile("cp.async.wait_group 0;\n")

// ---------------------------------------------------------------------------
// Fused preconvert fp32 -> split hi/lo fp16 (one launch for all 7 tensors)
// ---------------------------------------------------------------------------
#define NX4 (MM*DD/4)          // 1572864
#define NW4 (HH*DD*DHH/4)      // 147456

__global__ __launch_bounds__(256) void split_all(
    const float* __restrict__ Xq, const float* __restrict__ Xk, const float* __restrict__ Xv,
    const float* __restrict__ Wq, const float* __restrict__ Wk, const float* __restrict__ Wv,
    const float* __restrict__ Wo)
{
    int i = blockIdx.x * 256 + threadIdx.x;
    const float* src; __half *dh, *dl; int off;
    if (i < 3 * NX4) {
        int t = i / NX4; off = i - t * NX4;
        src = (t == 0) ? Xq : (t == 1) ? Xk : Xv;
        dh  = (t == 0) ? g_Xqh : (t == 1) ? g_Xkh : g_Xvh;
        dl  = (t == 0) ? g_Xql : (t == 1) ? g_Xkl : g_Xvl;
    } else {
        int j = i - 3 * NX4;
        if (j >= 4 * NW4) return;
        int t = j / NW4; off = j - t * NW4;
        src = (t == 0) ? Wq : (t == 1) ? Wk : (t == 2) ? Wv : Wo;
        dh  = (t == 0) ? g_Wqh : (t == 1) ? g_Wkh : (t == 2) ? g_Wvh : g_Woh;
        dl  = (t == 0) ? g_Wql : (t == 1) ? g_Wkl : (t == 2) ? g_Wvl : g_Wol;
    }
    float4 v = ((const float4*)src)[off];
    union { __half h[4]; uint2 u; } ph, pl;
    splitf(v.x, ph.h[0], pl.h[0]);
    splitf(v.y, ph.h[1], pl.h[1]);
    splitf(v.z, ph.h[2], pl.h[2]);
    splitf(v.w, ph.h[3], pl.h[3]);
    ((uint2*)dh)[off] = ph.u;
    ((uint2*)dl)[off] = pl.u;
}

// ---------------------------------------------------------------------------
// QKV GEMM: C[128x96] = X[128x768] @ W[768x96] + bias. Split-fp16 HMMA (3-term).
// Q output pre-scaled by 1/sqrt(96) and stored hi+lo; K/V stored hi only.
// ---------------------------------------------------------------------------
#define QK_LDA 40
#define QK_LDB 104

__device__ __forceinline__ void qkv_load(
    __half* Ah, __half* Al, __half* Bh, __half* Bl,
    const __half* gXh, const __half* gXl, const __half* gWh, const __half* gWl,
    int p, int m0, int kt, size_t wbase, int tid)
{
    #pragma unroll
    for (int j = 0; j < 7; j++) {
        int c = tid + j * 256;
        if (c < 1024) {
            int arr = c >> 9, rem = c & 511, row = rem >> 2, off = (rem & 3) * 8;
            const __half* sp = (arr ? gXl : gXh) + (size_t)(m0 + row) * DD + kt + off;
            __half* dp = (arr ? Al : Ah) + p * (128*QK_LDA) + row * QK_LDA + off;
            CPA(su32(dp), sp);
        } else {
            int c2 = c - 1024;
            int arr = (c2 >= 384) ? 1 : 0;
            int rem = c2 - arr * 384;
            int row = rem / 12, off = (rem - row * 12) * 8;
            const __half* sp = (arr ? gWl : gWh) + wbase + (size_t)(kt + row) * DHH + off;
            __half* dp = (arr ? Bl : Bh) + p * (32*QK_LDB) + row * QK_LDB + off;
            CPA(su32(dp), sp);
        }
    }
}

__global__ __launch_bounds__(256) void qkv_kernel(
    const float* __restrict__ bq, const float* __restrict__ bk, const float* __restrict__ bv)
{
    extern __shared__ __half smq[];
    __half* Ah = smq;
    __half* Al = Ah + 2*128*QK_LDA;
    __half* Bh = Al + 2*128*QK_LDA;
    __half* Bl = Bh + 2*32*QK_LDB;

    const __half *gXh, *gXl, *gWh, *gWl; const float* bias; __half *oh, *ol;
    bool write_lo;
    if (blockIdx.z == 0)      { gXh=g_Xqh; gXl=g_Xql; gWh=g_Wqh; gWl=g_Wql; bias=bq; oh=g_Qh; ol=g_Ql; write_lo=true; }
    else if (blockIdx.z == 1) { gXh=g_Xkh; gXl=g_Xkl; gWh=g_Wkh; gWl=g_Wkl; bias=bk; oh=g_Kh; ol=0;    write_lo=false; }
    else                      { gXh=g_Xvh; gXl=g_Xvl; gWh=g_Wvh; gWl=g_Wvl; bias=bv; oh=g_Vh; ol=0;    write_lo=false; }
    const float oscale = (blockIdx.z == 0) ? rsqrtf(96.0f) : 1.0f;

    const int h   = blockIdx.y;
    const int m0  = blockIdx.x * 128;
    const int tid = threadIdx.x;
    const int wid = tid >> 5, lane = tid & 31;
    const int wm  = wid >> 1, wn = wid & 1;
    const size_t wbase = (size_t)h * DD * DHH;

    float acc[2][6][4];
    #pragma unroll
    for (int i = 0; i < 2; i++)
        #pragma unroll
        for (int j = 0; j < 6; j++)
            #pragma unroll
            for (int k = 0; k < 4; k++) acc[i][j][k] = 0.f;

    const int lrow = lane & 15, lcol8 = (lane >> 4) << 3;

    qkv_load(Ah, Al, Bh, Bl, gXh, gXl, gWh, gWl, 0, m0, 0, wbase, tid);
    CP_COMMIT;

    const int NT = DD / 32;
    for (int it = 0; it < NT; it++) {
        int p = it & 1;
        if (it + 1 < NT) {
            qkv_load(Ah, Al, Bh, Bl, gXh, gXl, gWh, gWl, (it+1)&1, m0, (it+1)*32, wbase, tid);
            CP_COMMIT;
            CP_WAIT1;
        } else {
            CP_WAIT0;
        }
        __syncthreads();

        __half* Ahp = Ah + p * (128*QK_LDA);
        __half* Alp = Al + p * (128*QK_LDA);
        __half* Bhp = Bh + p * (32*QK_LDB);
        __half* Blp = Bl + p * (32*QK_LDB);

        #pragma unroll
        for (int ks = 0; ks < 2; ks++) {
            int k0 = ks * 16;
            unsigned ah[2][4], al[2][4];
            #pragma unroll
            for (int mf = 0; mf < 2; mf++) {
                int row = wm * 32 + mf * 16 + lrow;
                ldsm4(ah[mf], su32(Ahp + row * QK_LDA + k0 + lcol8));
                ldsm4(al[mf], su32(Alp + row * QK_LDA + k0 + lcol8));
            }
            #pragma unroll
            for (int nf2 = 0; nf2 < 3; nf2++) {
                unsigned bh[4], bl[4];
                int n0 = wn * 48 + nf2 * 16;
                int brow = k0 + lrow;
                ldsm4t(bh, su32(Bhp + brow * QK_LDB + n0 + lcol8));
                ldsm4t(bl, su32(Blp + brow * QK_LDB + n0 + lcol8));
                #pragma unroll
                for (int hn = 0; hn < 2; hn++) {
                    #pragma unroll
                    for (int mf = 0; mf < 2; mf++) {
                        float* c = acc[mf][nf2*2 + hn];
                        mma16816(c, ah[mf], bh + hn*2);
                        mma16816(c, ah[mf], bl + hn*2);
                        mma16816(c, al[mf], bh + hn*2);
                    }
                }
            }
        }
        __syncthreads();
    }

    #pragma unroll
    for (int mf = 0; mf < 2; mf++) {
        #pragma unroll
        for (int nf = 0; nf < 6; nf++) {
            int col = wn * 48 + nf * 8 + (lane & 3) * 2;
            float b0 = bias[h*DHH + col], b1 = bias[h*DHH + col + 1];
            #pragma unroll
            for (int hr = 0; hr < 2; hr++) {
                int m = m0 + wm * 32 + mf * 16 + (lane >> 2) + hr * 8;
                int bb = m >> 11, s = m & 2047;
                size_t off = (((size_t)(bb * HH + h)) * SS + s) * DHH + col;
                float v0 = (acc[mf][nf][hr*2 + 0] + b0) * oscale;
                float v1 = (acc[mf][nf][hr*2 + 1] + b1) * oscale;
                __half h0,l0,h1,l1; splitf(v0,h0,l0); splitf(v1,h1,l1);
                *(half2*)(oh + off) = __halves2half2(h0,h1);
                if (write_lo) *(half2*)(ol + off) = __halves2half2(l0,l1);
            }
        }
    }
}

// ---------------------------------------------------------------------------
// Flash attention. Q split hi/lo; K,V hi-only (2-term mma).
//   S  = qh*kh + ql*kh     PV = ph*vh + pl*vh
// smem = Qh,Ql [128][104] + Kh,Vh [64][104] = 80 KB -> 2 blocks/SM.
// Split-group cp.async pipeline (K group, V group) as in round 5.
// ---------------------------------------------------------------------------
#define AT_LD 104

__device__ __forceinline__ void attn_load_k(__half* Kh, size_t gbase, int tid)
{
    #pragma unroll
    for (int j = 0; j < 3; j++) {
        int c = tid + j * 256;            // 0..767
        int row = c / 12;
        int off = (c - row * 12) * 8;
        CPA(su32(Kh + row * AT_LD + off), g_Kh + (gbase + row) * DHH + off);
    }
}
__device__ __forceinline__ void attn_load_v(__half* Vh, size_t gbase, int tid)
{
    #pragma unroll
    for (int j = 0; j < 3; j++) {
        int c = tid + j * 256;
        int row = c / 12;
        int off = (c - row * 12) * 8;
        CPA(su32(Vh + row * AT_LD + off), g_Vh + (gbase + row) * DHH + off);
    }
}

__global__ __launch_bounds__(256, 2) void attn_kernel()
{
    extern __shared__ __half smh[];
    __half* Qh = smh;                 // [128][104]
    __half* Ql = Qh + 128 * AT_LD;
    __half* Kh = Ql + 128 * AT_LD;    // [64][104]
    __half* Vh = Kh + 64 * AT_LD;     // [64][104]

    const int b  = blockIdx.z, h = blockIdx.y;
    const int s0 = blockIdx.x * 128;
    const int tid = threadIdx.x, wid = tid >> 5, lane = tid & 31;
    const size_t base = ((size_t)(b * HH + h)) * SS;

    {   // load Q tile (hi/lo; pre-scaled by qkv)
        int r = tid >> 1, c0 = (tid & 1) * 48;
        size_t go = (base + s0 + r) * DHH + c0;
        __half* dh = Qh + r * AT_LD + c0;
        __half* dl = Ql + r * AT_LD + c0;
        #pragma unroll
        for (int i = 0; i < 6; i++) {
            *(uint4*)(dh + i*8) = *(const uint4*)(g_Qh + go + i*8);
            *(uint4*)(dl + i*8) = *(const uint4*)(g_Ql + go + i*8);
        }
    }

    attn_load_k(Kh, base, tid); CP_COMMIT;
    attn_load_v(Vh, base, tid); CP_COMMIT;

    float oacc[12][4];
    #pragma unroll
    for (int j = 0; j < 12; j++)
        #pragma unroll
        for (int t = 0; t < 4; t++) oacc[j][t] = 0.f;
    float m0r = -1e30f, m1r = -1e30f, l0r = 0.f, l1r = 0.f;

    const int lrow = lane & 15, lcol8 = (lane >> 4) << 3;
    const int krow_off = (lane & 7) + ((lane & 16) >> 1);
    const int kcol_off = (lane & 8);

    const int NT = SS / 64;  // 32
    for (int it = 0; it < NT; it++) {
        // K(it) arrived (newest outstanding group is V(it))
        CP_WAIT1;
        __syncthreads();

        // S = Q @ K^T  (2-term: qh*kh + ql*kh)
        float sacc[8][4];
        #pragma unroll
        for (int j = 0; j < 8; j++)
            #pragma unroll
            for (int t = 0; t < 4; t++) sacc[j][t] = 0.f;

        #pragma unroll
        for (int dk = 0; dk < 6; dk++) {
            int d0 = dk * 16;
            unsigned ah[4], al[4];
            int qrow = wid * 16 + lrow;
            ldsm4(ah, su32(Qh + qrow * AT_LD + d0 + lcol8));
            ldsm4(al, su32(Ql + qrow * AT_LD + d0 + lcol8));
            #pragma unroll
            for (int nf2 = 0; nf2 < 4; nf2++) {
                unsigned bh[4];
                int n0 = nf2 * 16;
                ldsm4(bh, su32(Kh + (n0 + krow_off) * AT_LD + d0 + kcol_off));
                #pragma unroll
                for (int hn = 0; hn < 2; hn++) {
                    float* c = sacc[nf2*2 + hn];
                    mma16816(c, ah, bh + hn*2);
                    mma16816(c, al, bh + hn*2);
                }
            }
        }
        __syncthreads();   // all warps done reading K
        if (it + 1 < NT) { attn_load_k(Kh, base + (size_t)(it+1)*64, tid); CP_COMMIT; }

        // online softmax (registers; covers V latency)
        float mx0 = -1e30f, mx1 = -1e30f;
        #pragma unroll
        for (int j = 0; j < 8; j++) {
            mx0 = fmaxf(mx0, fmaxf(sacc[j][0], sacc[j][1]));
            mx1 = fmaxf(mx1, fmaxf(sacc[j][2], sacc[j][3]));
        }
        mx0 = fmaxf(mx0, __shfl_xor_sync(0xffffffffu, mx0, 1));
        mx0 = fmaxf(mx0, __shfl_xor_sync(0xffffffffu, mx0, 2));
        mx1 = fmaxf(mx1, __shfl_xor_sync(0xffffffffu, mx1, 1));
        mx1 = fmaxf(mx1, __shfl_xor_sync(0xffffffffu, mx1, 2));
        float mn0 = fmaxf(m0r, mx0), mn1 = fmaxf(m1r, mx1);
        float corr0 = __expf(m0r - mn0), corr1 = __expf(m1r - mn1);
        m0r = mn0; m1r = mn1;
        float sum0 = 0.f, sum1 = 0.f;
        #pragma unroll
        for (int j = 0; j < 8; j++) {
            sacc[j][0] = __expf(sacc[j][0] - mn0);
            sacc[j][1] = __expf(sacc[j][1] - mn0);
            sacc[j][2] = __expf(sacc[j][2] - mn1);
            sacc[j][3] = __expf(sacc[j][3] - mn1);
            sum0 += sacc[j][0] + sacc[j][1];
            sum1 += sacc[j][2] + sacc[j][3];
        }
        sum0 += __shfl_xor_sync(0xffffffffu, sum0, 1);
        sum0 += __shfl_xor_sync(0xffffffffu, sum0, 2);
        sum1 += __shfl_xor_sync(0xffffffffu, sum1, 1);
        sum1 += __shfl_xor_sync(0xffffffffu, sum1, 2);
        l0r = l0r * corr0 + sum0;
        l1r = l1r * corr1 + sum1;

        #pragma unroll
        for (int j = 0; j < 12; j++) {
            oacc[j][0] *= corr0; oacc[j][1] *= corr0;
            oacc[j][2] *= corr1; oacc[j][3] *= corr1;
        }

        // P fragments (register pass, split hi/lo)
        unsigned ph[4][4], pl[4][4];
        #pragma unroll
        for (int kf = 0; kf < 4; kf++) {
            #pragma unroll
            for (int q = 0; q < 4; q++) {
                int fj = kf*2 + (q >> 1);
                int t0 = (q & 1) * 2;
                float v0 = sacc[fj][t0], v1 = sacc[fj][t0 + 1];
                __half h0,l0,h1,l1; splitf(v0,h0,l0); splitf(v1,h1,l1);
                ph[kf][q] = h2u(__halves2half2(h0,h1));
                pl[kf][q] = h2u(__halves2half2(l0,l1));
            }
        }

        // V(it) arrived
        if (it + 1 < NT) { CP_WAIT1; } else { CP_WAIT0; }
        __syncthreads();

        // O += P @ V (2-term: ph*vh + pl*vh)
        #pragma unroll
        for (int kf = 0; kf < 4; kf++) {
            int k0 = kf * 16;
            #pragma unroll
            for (int nf2 = 0; nf2 < 6; nf2++) {
                unsigned bh[4];
                int n0 = nf2 * 16;
                int vrow = k0 + lrow;
                ldsm4t(bh, su32(Vh + vrow * AT_LD + n0 + lcol8));
                #pragma unroll
                for (int hn = 0; hn < 2; hn++) {
                    float* c = oacc[nf2*2 + hn];
                    mma16816(c, ph[kf], bh + hn*2);
                    mma16816(c, pl[kf], bh + hn*2);
                }
            }
        }
        __syncthreads();   // all warps done reading V
        if (it + 1 < NT) { attn_load_v(Vh, base + (size_t)(it+1)*64, tid); CP_COMMIT; }
    }

    // Epilogue: normalize, split-store to cat [M][768] hi/lo
    float inv0 = 1.0f / l0r, inv1 = 1.0f / l1r;
    #pragma unroll
    for (int nf = 0; nf < 12; nf++) {
        int col = h * DHH + nf * 8 + (lane & 3) * 2;
        #pragma unroll
        for (int hr = 0; hr < 2; hr++) {
            int s = s0 + wid * 16 + (lane >> 2) + hr * 8;
            size_t off = ((size_t)b * SS + s) * DD + col;
            float inv = hr ? inv1 : inv0;
            float v0 = oacc[nf][hr*2 + 0] * inv;
            float v1 = oacc[nf][hr*2 + 1] * inv;
            __half h0,l0,h1,l1; splitf(v0,h0,l0); splitf(v1,h1,l1);
            *(half2*)(g_cath + off) = __halves2half2(h0,h1);
            *(half2*)(g_catl + off) = __halves2half2(l0,l1);
        }
    }
}

// ---------------------------------------------------------------------------
// Output projection: out[128x128] = cat[128x768] @ Wo[768x128] + bo (3-term).
// ---------------------------------------------------------------------------
#define OP_LDA 40
#define OP_LDB 136

__device__ __forceinline__ void oproj_load(
    __half* Ah, __half* Al, __half* Bh, __half* Bl,
    int p, int m0, int n0b, int kt, int tid)
{
    #pragma unroll
    for (int j = 0; j < 8; j++) {
        int c = tid + j * 256;
        if (c < 1024) {
            int arr = c >> 9, rem = c & 511, row = rem >> 2, off = (rem & 3) * 8;
            const __half* sp = (arr ? g_catl : g_cath) + (size_t)(m0 + row) * DD + kt + off;
            __half* dp = (arr ? Al : Ah) + p * (128*OP_LDA) + row * OP_LDA + off;
            CPA(su32(dp), sp);
        } else {
            int c2 = c - 1024;
            int arr = c2 >> 9, rem = c2 & 511, row = rem >> 4, off = (rem & 15) * 8;
            const __half* sp = (arr ? g_Wol : g_Woh) + (size_t)(kt + row) * DD + n0b + off;
            __half* dp = (arr ? Bl : Bh) + p * (32*OP_LDB) + row * OP_LDB + off;
            CPA(su32(dp), sp);
        }
    }
}

__global__ __launch_bounds__(256) void oproj_kernel(
    const float* __restrict__ bo, float* __restrict__ out)
{
    extern __shared__ __half smo[];
    __half* Ah = smo;
    __half* Al = Ah + 2*128*OP_LDA;
    __half* Bh = Al + 2*128*OP_LDA;
    __half* Bl = Bh + 2*32*OP_LDB;

    const int m0  = blockIdx.x * 128;
    const int n0b = blockIdx.y * 128;
    const int tid = threadIdx.x, wid = tid >> 5, lane = tid & 31;
    const int wm = wid >> 1, wn = wid & 1;

    float acc[2][8][4];
    #pragma unroll
    for (int i = 0; i < 2; i++)
        #pragma unroll
        for (int j = 0; j < 8; j++)
            #pragma unroll
            for (int k = 0; k < 4; k++) acc[i][j][k] = 0.f;

    const int lrow = lane & 15, lcol8 = (lane >> 4) << 3;

    oproj_load(Ah, Al, Bh, Bl, 0, m0, n0b, 0, tid);
    CP_COMMIT;

    const int NT = DD / 32;
    for (int it = 0; it < NT; it++) {
        int p = it & 1;
        if (it + 1 < NT) {
            oproj_load(Ah, Al, Bh, Bl, (it+1)&1, m0, n0b, (it+1)*32, tid);
            CP_COMMIT;
            CP_WAIT1;
        } else {
            CP_WAIT0;
        }
        __syncthreads();

        __half* Ahp = Ah + p * (128*OP_LDA);
        __half* Alp = Al + p * (128*OP_LDA);
        __half* Bhp = Bh + p * (32*OP_LDB);
        __half* Blp = Bl + p * (32*OP_LDB);

        #pragma unroll
        for (int ks = 0; ks < 2; ks++) {
            int k0 = ks * 16;
            unsigned ah[2][4], al[2][4];
            #pragma unroll
            for (int mf = 0; mf < 2; mf++) {
                int row = wm * 32 + mf * 16 + lrow;
                ldsm4(ah[mf], su32(Ahp + row * OP_LDA + k0 + lcol8));
                ldsm4(al[mf], su32(Alp + row * OP_LDA + k0 + lcol8));
            }
            #pragma unroll
            for (int nf2 = 0; nf2 < 4; nf2++) {
                unsigned bh[4], bl[4];
                int n0 = wn * 64 + nf2 * 16;
                int brow = k0 + lrow;
                ldsm4t(bh, su32(Bhp + brow * OP_LDB + n0 + lcol8));
                ldsm4t(bl, su32(Blp + brow * OP_LDB + n0 + lcol8));
                #pragma unroll
                for (int hn = 0; hn < 2; hn++) {
                    #pragma unroll
                    for (int mf = 0; mf < 2; mf++) {
                        float* c = acc[mf][nf2*2 + hn];
                        mma16816(c, ah[mf], bh + hn*2);
                        mma16816(c, ah[mf], bl + hn*2);
                        mma16816(c, al[mf], bh + hn*2);
                    }
                }
            }
        }
        __syncthreads();
    }

    #pragma unroll
    for (int mf = 0; mf < 2; mf++) {
        #pragma unroll
        for (int nf = 0; nf < 8; nf++) {
            int col = n0b + wn * 64 + nf * 8 + (lane & 3) * 2;
            float b0 = bo[col], b1 = bo[col + 1];
            #pragma unroll
            for (int hr = 0; hr < 2; hr++) {
                int m = m0 + wm * 32 + mf * 16 + (lane >> 2) + hr * 8;
                float2 v = make_float2(acc[mf][nf][hr*2+0] + b0,
                                       acc[mf][nf][hr*2+1] + b1);
                *(float2*)(out + (size_t)m * DD + col) = v;
            }
        }
    }
}

// ---------------------------------------------------------------------------
extern "C" void kernel_launch(void* const* d_in, const int* in_sizes, int n_in,
                              void* d_out, int out_size)
{
    (void)in_sizes; (void)n_in; (void)out_size;
    const float* Xq = (const float*)d_in[0];
    const float* Xk = (const float*)d_in[1];
    const float* Xv = (const float*)d_in[2];
    const float* Wq = (const float*)d_in[3];
    const float* bq = (const float*)d_in[4];
    const float* Wk = (const float*)d_in[5];
    const float* bk = (const float*)d_in[6];
    const float* Wv = (const float*)d_in[7];
    const float* bv = (const float*)d_in[8];
    const float* Wo = (const float*)d_in[9];
    const float* bo = (const float*)d_in[10];
    float* out = (float*)d_out;

    const int total4 = 3*NX4 + 4*NW4;
    split_all<<<(total4 + 255) / 256, 256>>>(Xq, Xk, Xv, Wq, Wk, Wv, Wo);

    const int smem_qkv = (2*128*QK_LDA*2 + 2*32*QK_LDB*2) * (int)sizeof(__half);
    cudaFuncSetAttribute(qkv_kernel, cudaFuncAttributeMaxDynamicSharedMemorySize, smem_qkv);
    dim3 gq(MM / 128, HH, 3);
    qkv_kernel<<<gq, 256, smem_qkv>>>(bq, bk, bv);

    const int smem_attn = (2*128*AT_LD + 2*64*AT_LD) * (int)sizeof(__half);  // 80 KB
    cudaFuncSetAttribute(attn_kernel, cudaFuncAttributeMaxDynamicSharedMemorySize, smem_attn);
    dim3 ga(SS / 128, HH, BB);
    attn_kernel<<<ga, 256, smem_attn>>>();

    const int smem_op = (2*128*OP_LDA*2 + 2*32*OP_LDB*2) * (int)sizeof(__half);
    cudaFuncSetAttribute(oproj_kernel, cudaFuncAttributeMaxDynamicSharedMemorySize, smem_op);
    dim3 go(MM / 128, DD / 128);
    oproj_kernel<<<go, 256, smem_op>>>(bo, out);
}

// round 8
// speedup vs baseline: 4.4722x; 1.2150x over previous
#include <cuda_runtime.h>
#include <cuda_fp16.h>

#define BB 4
#define SS 2048
#define DD 768
#define HH 8
#define DHH 96
#define MM (BB*SS)   // 8192

// Split hi/lo fp16 scratch. W tensors: hi only (2-term GEMMs).
__device__ __half g_Xqh[(size_t)MM*DD], g_Xql[(size_t)MM*DD];
__device__ __half g_Xkh[(size_t)MM*DD], g_Xkl[(size_t)MM*DD];
__device__ __half g_Xvh[(size_t)MM*DD], g_Xvl[(size_t)MM*DD];
__device__ __half g_Wqh[(size_t)HH*DD*DHH];
__device__ __half g_Wkh[(size_t)HH*DD*DHH];
__device__ __half g_Wvh[(size_t)HH*DD*DHH];
__device__ __half g_Woh[(size_t)DD*DD];
__device__ __half g_Qh[(size_t)BB*HH*SS*DHH], g_Ql[(size_t)BB*HH*SS*DHH];
__device__ __half g_Kh[(size_t)BB*HH*SS*DHH];   // K: hi only
__device__ __half g_Vh[(size_t)BB*HH*SS*DHH];   // V: hi only
__device__ __half g_cath[(size_t)MM*DD],      g_catl[(size_t)MM*DD];

__device__ __forceinline__ unsigned su32(const void* p) {
    return (unsigned)__cvta_generic_to_shared(p);
}
__device__ __forceinline__ unsigned h2u(half2 v) {
    union { half2 h; unsigned u; } x; x.h = v; return x.u;
}
__device__ __forceinline__ void ldsm4(unsigned r[4], unsigned addr) {
    asm volatile("ldmatrix.sync.aligned.m8n8.x4.shared.b16 {%0,%1,%2,%3},[%4];\n"
        : "=r"(r[0]), "=r"(r[1]), "=r"(r[2]), "=r"(r[3]) : "r"(addr));
}
__device__ __forceinline__ void ldsm4t(unsigned r[4], unsigned addr) {
    asm volatile("ldmatrix.sync.aligned.m8n8.x4.trans.shared.b16 {%0,%1,%2,%3},[%4];\n"
        : "=r"(r[0]), "=r"(r[1]), "=r"(r[2]), "=r"(r[3]) : "r"(addr));
}
__device__ __forceinline__ void mma16816(float* c, const unsigned* a, const unsigned* b) {
    asm volatile("mma.sync.aligned.m16n8k16.row.col.f32.f16.f16.f32 "
        "{%0,%1,%2,%3},{%4,%5,%6,%7},{%8,%9},{%0,%1,%2,%3};\n"
        : "+f"(c[0]), "+f"(c[1]), "+f"(c[2]), "+f"(c[3])
        : "r"(a[0]), "r"(a[1]), "r"(a[2]), "r"(a[3]), "r"(b[0]), "r"(b[1]));
}
__device__ __forceinline__ void splitf(float x, __half& h, __half& l) {
    h = __float2half_rn(x);
    l = __float2half_rn(x - __half2float(h));
}
#define CPA(dst, src) asm volatile("cp.async.cg.shared.global [%0], [%1], 16;\n" :: "r"(dst), "l"(src))
#define CP_COMMIT asm volatile("cp.async.commit_group;\n")
#define CP_WAIT1  asm volatile("cp.async.wait_group 1;\n")
#define CP_WAIT0  asm volatile("cp.async.wait_group 0;\n")

// ---------------------------------------------------------------------------
// Fused preconvert: X -> split hi/lo; W -> hi only.
// ---------------------------------------------------------------------------
#define NX4 (MM*DD/4)          // 1572864
#define NW4 (HH*DD*DHH/4)      // 147456

__global__ __launch_bounds__(256) void split_all(
    const float* __restrict__ Xq, const float* __restrict__ Xk, const float* __restrict__ Xv,
    const float* __restrict__ Wq, const float* __restrict__ Wk, const float* __restrict__ Wv,
    const float* __restrict__ Wo)
{
    int i = blockIdx.x * 256 + threadIdx.x;
    if (i < 3 * NX4) {
        int t = i / NX4; int off = i - t * NX4;
        const float* src = (t == 0) ? Xq : (t == 1) ? Xk : Xv;
        __half* dh = (t == 0) ? g_Xqh : (t == 1) ? g_Xkh : g_Xvh;
        __half* dl = (t == 0) ? g_Xql : (t == 1) ? g_Xkl : g_Xvl;
        float4 v = ((const float4*)src)[off];
        union { __half h[4]; uint2 u; } ph, pl;
        splitf(v.x, ph.h[0], pl.h[0]);
        splitf(v.y, ph.h[1], pl.h[1]);
        splitf(v.z, ph.h[2], pl.h[2]);
        splitf(v.w, ph.h[3], pl.h[3]);
        ((uint2*)dh)[off] = ph.u;
        ((uint2*)dl)[off] = pl.u;
    } else {
        int j = i - 3 * NX4;
        if (j >= 4 * NW4) return;
        int t = j / NW4; int off = j - t * NW4;
        const float* src = (t == 0) ? Wq : (t == 1) ? Wk : (t == 2) ? Wv : Wo;
        __half* dh = (t == 0) ? g_Wqh : (t == 1) ? g_Wkh : (t == 2) ? g_Wvh : g_Woh;
        float4 v = ((const float4*)src)[off];
        union { __half h[4]; uint2 u; } ph;
        ph.h[0] = __float2half_rn(v.x);
        ph.h[1] = __float2half_rn(v.y);
        ph.h[2] = __float2half_rn(v.z);
        ph.h[3] = __float2half_rn(v.w);
        ((uint2*)dh)[off] = ph.u;
    }
}

// ---------------------------------------------------------------------------
// QKV GEMM (2-term: xh*wh + xl*wh). W hi-only. smem 53 KB -> 2 blocks/SM.
// Q output pre-scaled by 1/sqrt(96), stored hi+lo; K/V stored hi only.
// ---------------------------------------------------------------------------
#define QK_LDA 40
#define QK_LDB 104

__device__ __forceinline__ void qkv_load(
    __half* Ah, __half* Al, __half* Bh,
    const __half* gXh, const __half* gXl, const __half* gWh,
    int p, int m0, int kt, size_t wbase, int tid)
{
    #pragma unroll
    for (int j = 0; j < 6; j++) {
        int c = tid + j * 256;
        if (c < 1024) {
            int arr = c >> 9, rem = c & 511, row = rem >> 2, off = (rem & 3) * 8;
            const __half* sp = (arr ? gXl : gXh) + (size_t)(m0 + row) * DD + kt + off;
            __half* dp = (arr ? Al : Ah) + p * (128*QK_LDA) + row * QK_LDA + off;
            CPA(su32(dp), sp);
        } else if (c < 1408) {
            int c2 = c - 1024;                 // 0..383
            int row = c2 / 12, off = (c2 - row * 12) * 8;
            const __half* sp = gWh + wbase + (size_t)(kt + row) * DHH + off;
            __half* dp = Bh + p * (32*QK_LDB) + row * QK_LDB + off;
            CPA(su32(dp), sp);
        }
    }
}

__global__ __launch_bounds__(256, 2) void qkv_kernel(
    const float* __restrict__ bq, const float* __restrict__ bk, const float* __restrict__ bv)
{
    extern __shared__ __half smq[];
    __half* Ah = smq;                      // 2 x 128 x 40
    __half* Al = Ah + 2*128*QK_LDA;
    __half* Bh = Al + 2*128*QK_LDA;        // 2 x 32 x 104

    const __half *gXh, *gXl, *gWh; const float* bias; __half *oh, *ol;
    bool write_lo;
    if (blockIdx.z == 0)      { gXh=g_Xqh; gXl=g_Xql; gWh=g_Wqh; bias=bq; oh=g_Qh; ol=g_Ql; write_lo=true; }
    else if (blockIdx.z == 1) { gXh=g_Xkh; gXl=g_Xkl; gWh=g_Wkh; bias=bk; oh=g_Kh; ol=0;    write_lo=false; }
    else                      { gXh=g_Xvh; gXl=g_Xvl; gWh=g_Wvh; bias=bv; oh=g_Vh; ol=0;    write_lo=false; }
    const float oscale = (blockIdx.z == 0) ? rsqrtf(96.0f) : 1.0f;

    const int h   = blockIdx.y;
    const int m0  = blockIdx.x * 128;
    const int tid = threadIdx.x;
    const int wid = tid >> 5, lane = tid & 31;
    const int wm  = wid >> 1, wn = wid & 1;
    const size_t wbase = (size_t)h * DD * DHH;

    float acc[2][6][4];
    #pragma unroll
    for (int i = 0; i < 2; i++)
        #pragma unroll
        for (int j = 0; j < 6; j++)
            #pragma unroll
            for (int k = 0; k < 4; k++) acc[i][j][k] = 0.f;

    const int lrow = lane & 15, lcol8 = (lane >> 4) << 3;

    qkv_load(Ah, Al, Bh, gXh, gXl, gWh, 0, m0, 0, wbase, tid);
    CP_COMMIT;

    const int NT = DD / 32;
    for (int it = 0; it < NT; it++) {
        int p = it & 1;
        if (it + 1 < NT) {
            qkv_load(Ah, Al, Bh, gXh, gXl, gWh, (it+1)&1, m0, (it+1)*32, wbase, tid);
            CP_COMMIT;
            CP_WAIT1;
        } else {
            CP_WAIT0;
        }
        __syncthreads();

        __half* Ahp = Ah + p * (128*QK_LDA);
        __half* Alp = Al + p * (128*QK_LDA);
        __half* Bhp = Bh + p * (32*QK_LDB);

        #pragma unroll
        for (int ks = 0; ks < 2; ks++) {
            int k0 = ks * 16;
            unsigned ah[2][4], al[2][4];
            #pragma unroll
            for (int mf = 0; mf < 2; mf++) {
                int row = wm * 32 + mf * 16 + lrow;
                ldsm4(ah[mf], su32(Ahp + row * QK_LDA + k0 + lcol8));
                ldsm4(al[mf], su32(Alp + row * QK_LDA + k0 + lcol8));
            }
            #pragma unroll
            for (int nf2 = 0; nf2 < 3; nf2++) {
                unsigned bh[4];
                int n0 = wn * 48 + nf2 * 16;
                int brow = k0 + lrow;
                ldsm4t(bh, su32(Bhp + brow * QK_LDB + n0 + lcol8));
                #pragma unroll
                for (int hn = 0; hn < 2; hn++) {
                    #pragma unroll
                    for (int mf = 0; mf < 2; mf++) {
                        float* c = acc[mf][nf2*2 + hn];
                        mma16816(c, ah[mf], bh + hn*2);
                        mma16816(c, al[mf], bh + hn*2);
                    }
                }
            }
        }
        __syncthreads();
    }

    #pragma unroll
    for (int mf = 0; mf < 2; mf++) {
        #pragma unroll
        for (int nf = 0; nf < 6; nf++) {
            int col = wn * 48 + nf * 8 + (lane & 3) * 2;
            float b0 = bias[h*DHH + col], b1 = bias[h*DHH + col + 1];
            #pragma unroll
            for (int hr = 0; hr < 2; hr++) {
                int m = m0 + wm * 32 + mf * 16 + (lane >> 2) + hr * 8;
                int bb = m >> 11, s = m & 2047;
                size_t off = (((size_t)(bb * HH + h)) * SS + s) * DHH + col;
                float v0 = (acc[mf][nf][hr*2 + 0] + b0) * oscale;
                float v1 = (acc[mf][nf][hr*2 + 1] + b1) * oscale;
                __half h0,l0,h1,l1; splitf(v0,h0,l0); splitf(v1,h1,l1);
                *(half2*)(oh + off) = __halves2half2(h0,h1);
                if (write_lo) *(half2*)(ol + off) = __halves2half2(l0,l1);
            }
        }
    }
}

// ---------------------------------------------------------------------------
// Flash attention (unchanged from round 7). Q split; K,V hi-only.
// ---------------------------------------------------------------------------
#define AT_LD 104

__device__ __forceinline__ void attn_load_k(__half* Kh, size_t gbase, int tid)
{
    #pragma unroll
    for (int j = 0; j < 3; j++) {
        int c = tid + j * 256;
        int row = c / 12;
        int off = (c - row * 12) * 8;
        CPA(su32(Kh + row * AT_LD + off), g_Kh + (gbase + row) * DHH + off);
    }
}
__device__ __forceinline__ void attn_load_v(__half* Vh, size_t gbase, int tid)
{
    #pragma unroll
    for (int j = 0; j < 3; j++) {
        int c = tid + j * 256;
        int row = c / 12;
        int off = (c - row * 12) * 8;
        CPA(su32(Vh + row * AT_LD + off), g_Vh + (gbase + row) * DHH + off);
    }
}

__global__ __launch_bounds__(256, 2) void attn_kernel()
{
    extern __shared__ __half smh[];
    __half* Qh = smh;                 // [128][104]
    __half* Ql = Qh + 128 * AT_LD;
    __half* Kh = Ql + 128 * AT_LD;    // [64][104]
    __half* Vh = Kh + 64 * AT_LD;     // [64][104]

    const int b  = blockIdx.z, h = blockIdx.y;
    const int s0 = blockIdx.x * 128;
    const int tid = threadIdx.x, wid = tid >> 5, lane = tid & 31;
    const size_t base = ((size_t)(b * HH + h)) * SS;

    {
        int r = tid >> 1, c0 = (tid & 1) * 48;
        size_t go = (base + s0 + r) * DHH + c0;
        __half* dh = Qh + r * AT_LD + c0;
        __half* dl = Ql + r * AT_LD + c0;
        #pragma unroll
        for (int i = 0; i < 6; i++) {
            *(uint4*)(dh + i*8) = *(const uint4*)(g_Qh + go + i*8);
            *(uint4*)(dl + i*8) = *(const uint4*)(g_Ql + go + i*8);
        }
    }

    attn_load_k(Kh, base, tid); CP_COMMIT;
    attn_load_v(Vh, base, tid); CP_COMMIT;

    float oacc[12][4];
    #pragma unroll
    for (int j = 0; j < 12; j++)
        #pragma unroll
        for (int t = 0; t < 4; t++) oacc[j][t] = 0.f;
    float m0r = -1e30f, m1r = -1e30f, l0r = 0.f, l1r = 0.f;

    const int lrow = lane & 15, lcol8 = (lane >> 4) << 3;
    const int krow_off = (lane & 7) + ((lane & 16) >> 1);
    const int kcol_off = (lane & 8);

    const int NT = SS / 64;
    for (int it = 0; it < NT; it++) {
        CP_WAIT1;
        __syncthreads();

        float sacc[8][4];
        #pragma unroll
        for (int j = 0; j < 8; j++)
            #pragma unroll
            for (int t = 0; t < 4; t++) sacc[j][t] = 0.f;

        #pragma unroll
        for (int dk = 0; dk < 6; dk++) {
            int d0 = dk * 16;
            unsigned ah[4], al[4];
            int qrow = wid * 16 + lrow;
            ldsm4(ah, su32(Qh + qrow * AT_LD + d0 + lcol8));
            ldsm4(al, su32(Ql + qrow * AT_LD + d0 + lcol8));
            #pragma unroll
            for (int nf2 = 0; nf2 < 4; nf2++) {
                unsigned bh[4];
                int n0 = nf2 * 16;
                ldsm4(bh, su32(Kh + (n0 + krow_off) * AT_LD + d0 + kcol_off));
                #pragma unroll
                for (int hn = 0; hn < 2; hn++) {
                    float* c = sacc[nf2*2 + hn];
                    mma16816(c, ah, bh + hn*2);
                    mma16816(c, al, bh + hn*2);
                }
            }
        }
        __syncthreads();
        if (it + 1 < NT) { attn_load_k(Kh, base + (size_t)(it+1)*64, tid); CP_COMMIT; }

        float mx0 = -1e30f, mx1 = -1e30f;
        #pragma unroll
        for (int j = 0; j < 8; j++) {
            mx0 = fmaxf(mx0, fmaxf(sacc[j][0], sacc[j][1]));
            mx1 = fmaxf(mx1, fmaxf(sacc[j][2], sacc[j][3]));
        }
        mx0 = fmaxf(mx0, __shfl_xor_sync(0xffffffffu, mx0, 1));
        mx0 = fmaxf(mx0, __shfl_xor_sync(0xffffffffu, mx0, 2));
        mx1 = fmaxf(mx1, __shfl_xor_sync(0xffffffffu, mx1, 1));
        mx1 = fmaxf(mx1, __shfl_xor_sync(0xffffffffu, mx1, 2));
        float mn0 = fmaxf(m0r, mx0), mn1 = fmaxf(m1r, mx1);
        float corr0 = __expf(m0r - mn0), corr1 = __expf(m1r - mn1);
        m0r = mn0; m1r = mn1;
        float sum0 = 0.f, sum1 = 0.f;
        #pragma unroll
        for (int j = 0; j < 8; j++) {
            sacc[j][0] = __expf(sacc[j][0] - mn0);
            sacc[j][1] = __expf(sacc[j][1] - mn0);
            sacc[j][2] = __expf(sacc[j][2] - mn1);
            sacc[j][3] = __expf(sacc[j][3] - mn1);
            sum0 += sacc[j][0] + sacc[j][1];
            sum1 += sacc[j][2] + sacc[j][3];
        }
        sum0 += __shfl_xor_sync(0xffffffffu, sum0, 1);
        sum0 += __shfl_xor_sync(0xffffffffu, sum0, 2);
        sum1 += __shfl_xor_sync(0xffffffffu, sum1, 1);
        sum1 += __shfl_xor_sync(0xffffffffu, sum1, 2);
        l0r = l0r * corr0 + sum0;
        l1r = l1r * corr1 + sum1;

        #pragma unroll
        for (int j = 0; j < 12; j++) {
            oacc[j][0] *= corr0; oacc[j][1] *= corr0;
            oacc[j][2] *= corr1; oacc[j][3] *= corr1;
        }

        unsigned ph[4][4], pl[4][4];
        #pragma unroll
        for (int kf = 0; kf < 4; kf++) {
            #pragma unroll
            for (int q = 0; q < 4; q++) {
                int fj = kf*2 + (q >> 1);
                int t0 = (q & 1) * 2;
                float v0 = sacc[fj][t0], v1 = sacc[fj][t0 + 1];
                __half h0,l0,h1,l1; splitf(v0,h0,l0); splitf(v1,h1,l1);
                ph[kf][q] = h2u(__halves2half2(h0,h1));
                pl[kf][q] = h2u(__halves2half2(l0,l1));
            }
        }

        if (it + 1 < NT) { CP_WAIT1; } else { CP_WAIT0; }
        __syncthreads();

        #pragma unroll
        for (int kf = 0; kf < 4; kf++) {
            int k0 = kf * 16;
            #pragma unroll
            for (int nf2 = 0; nf2 < 6; nf2++) {
                unsigned bh[4];
                int n0 = nf2 * 16;
                int vrow = k0 + lrow;
                ldsm4t(bh, su32(Vh + vrow * AT_LD + n0 + lcol8));
                #pragma unroll
                for (int hn = 0; hn < 2; hn++) {
                    float* c = oacc[nf2*2 + hn];
                    mma16816(c, ph[kf], bh + hn*2);
                    mma16816(c, pl[kf], bh + hn*2);
                }
            }
        }
        __syncthreads();
        if (it + 1 < NT) { attn_load_v(Vh, base + (size_t)(it+1)*64, tid); CP_COMMIT; }
    }

    float inv0 = 1.0f / l0r, inv1 = 1.0f / l1r;
    #pragma unroll
    for (int nf = 0; nf < 12; nf++) {
        int col = h * DHH + nf * 8 + (lane & 3) * 2;
        #pragma unroll
        for (int hr = 0; hr < 2; hr++) {
            int s = s0 + wid * 16 + (lane >> 2) + hr * 8;
            size_t off = ((size_t)b * SS + s) * DD + col;
            float inv = hr ? inv1 : inv0;
            float v0 = oacc[nf][hr*2 + 0] * inv;
            float v1 = oacc[nf][hr*2 + 1] * inv;
            __half h0,l0,h1,l1; splitf(v0,h0,l0); splitf(v1,h1,l1);
            *(half2*)(g_cath + off) = __halves2half2(h0,h1);
            *(half2*)(g_catl + off) = __halves2half2(l0,l1);
        }
    }
}

// ---------------------------------------------------------------------------
// Output projection (2-term: (cath+catl)*woh). Wo hi-only. smem 57 KB.
// ---------------------------------------------------------------------------
#define OP_LDA 40
#define OP_LDB 136

__device__ __forceinline__ void oproj_load(
    __half* Ah, __half* Al, __half* Bh,
    int p, int m0, int n0b, int kt, int tid)
{
    #pragma unroll
    for (int j = 0; j < 6; j++) {
        int c = tid + j * 256;
        if (c < 1024) {
            int arr = c >> 9, rem = c & 511, row = rem >> 2, off = (rem & 3) * 8;
            const __half* sp = (arr ? g_catl : g_cath) + (size_t)(m0 + row) * DD + kt + off;
            __half* dp = (arr ? Al : Ah) + p * (128*OP_LDA) + row * OP_LDA + off;
            CPA(su32(dp), sp);
        } else {
            int c2 = c - 1024;                // 0..511
            int row = c2 >> 4, off = (c2 & 15) * 8;
            const __half* sp = g_Woh + (size_t)(kt + row) * DD + n0b + off;
            __half* dp = Bh + p * (32*OP_LDB) + row * OP_LDB + off;
            CPA(su32(dp), sp);
        }
    }
}

__global__ __launch_bounds__(256, 2) void oproj_kernel(
    const float* __restrict__ bo, float* __restrict__ out)
{
    extern __shared__ __half smo[];
    __half* Ah = smo;
    __half* Al = Ah + 2*128*OP_LDA;
    __half* Bh = Al + 2*128*OP_LDA;

    const int m0  = blockIdx.x * 128;
    const int n0b = blockIdx.y * 128;
    const int tid = threadIdx.x, wid = tid >> 5, lane = tid & 31;
    const int wm = wid >> 1, wn = wid & 1;

    float acc[2][8][4];
    #pragma unroll
    for (int i = 0; i < 2; i++)
        #pragma unroll
        for (int j = 0; j < 8; j++)
            #pragma unroll
            for (int k = 0; k < 4; k++) acc[i][j][k] = 0.f;

    const int lrow = lane & 15, lcol8 = (lane >> 4) << 3;

    oproj_load(Ah, Al, Bh, 0, m0, n0b, 0, tid);
    CP_COMMIT;

    const int NT = DD / 32;
    for (int it = 0; it < NT; it++) {
        int p = it & 1;
        if (it + 1 < NT) {
            oproj_load(Ah, Al, Bh, (it+1)&1, m0, n0b, (it+1)*32, tid);
            CP_COMMIT;
            CP_WAIT1;
        } else {
            CP_WAIT0;
        }
        __syncthreads();

        __half* Ahp = Ah + p * (128*OP_LDA);
        __half* Alp = Al + p * (128*OP_LDA);
        __half* Bhp = Bh + p * (32*OP_LDB);

        #pragma unroll
        for (int ks = 0; ks < 2; ks++) {
            int k0 = ks * 16;
            unsigned ah[2][4], al[2][4];
            #pragma unroll
            for (int mf = 0; mf < 2; mf++) {
                int row = wm * 32 + mf * 16 + lrow;
                ldsm4(ah[mf], su32(Ahp + row * OP_LDA + k0 + lcol8));
                ldsm4(al[mf], su32(Alp + row * OP_LDA + k0 + lcol8));
            }
            #pragma unroll
            for (int nf2 = 0; nf2 < 4; nf2++) {
                unsigned bh[4];
                int n0 = wn * 64 + nf2 * 16;
                int brow = k0 + lrow;
                ldsm4t(bh, su32(Bhp + brow * OP_LDB + n0 + lcol8));
                #pragma unroll
                for (int hn = 0; hn < 2; hn++) {
                    #pragma unroll
                    for (int mf = 0; mf < 2; mf++) {
                        float* c = acc[mf][nf2*2 + hn];
                        mma16816(c, ah[mf], bh + hn*2);
                        mma16816(c, al[mf], bh + hn*2);
                    }
                }
            }
        }
        __syncthreads();
    }

    #pragma unroll
    for (int mf = 0; mf < 2; mf++) {
        #pragma unroll
        for (int nf = 0; nf < 8; nf++) {
            int col = n0b + wn * 64 + nf * 8 + (lane & 3) * 2;
            float b0 = bo[col], b1 = bo[col + 1];
            #pragma unroll
            for (int hr = 0; hr < 2; hr++) {
                int m = m0 + wm * 32 + mf * 16 + (lane >> 2) + hr * 8;
                float2 v = make_float2(acc[mf][nf][hr*2+0] + b0,
                                       acc[mf][nf][hr*2+1] + b1);
                *(float2*)(out + (size_t)m * DD + col) = v;
            }
        }
    }
}

// ---------------------------------------------------------------------------
extern "C" void kernel_launch(void* const* d_in, const int* in_sizes, int n_in,
                              void* d_out, int out_size)
{
    (void)in_sizes; (void)n_in; (void)out_size;
    const float* Xq = (const float*)d_in[0];
    const float* Xk = (const float*)d_in[1];
    const float* Xv = (const float*)d_in[2];
    const float* Wq = (const float*)d_in[3];
    const float* bq = (const float*)d_in[4];
    const float* Wk = (const float*)d_in[5];
    const float* bk = (const float*)d_in[6];
    const float* Wv = (const float*)d_in[7];
    const float* bv = (const float*)d_in[8];
    const float* Wo = (const float*)d_in[9];
    const float* bo = (const float*)d_in[10];
    float* out = (float*)d_out;

    const int total4 = 3*NX4 + 4*NW4;
    split_all<<<(total4 + 255) / 256, 256>>>(Xq, Xk, Xv, Wq, Wk, Wv, Wo);

    const int smem_qkv = (2*128*QK_LDA*2 + 2*32*QK_LDB) * (int)sizeof(__half);
    cudaFuncSetAttribute(qkv_kernel, cudaFuncAttributeMaxDynamicSharedMemorySize, smem_qkv);
    dim3 gq(MM / 128, HH, 3);
    qkv_kernel<<<gq, 256, smem_qkv>>>(bq, bk, bv);

    const int smem_attn = (2*128*AT_LD + 2*64*AT_LD) * (int)sizeof(__half);  // 80 KB
    cudaFuncSetAttribute(attn_kernel, cudaFuncAttributeMaxDynamicSharedMemorySize, smem_attn);
    dim3 ga(SS / 128, HH, BB);
    attn_kernel<<<ga, 256, smem_attn>>>();

    const int smem_op = (2*128*OP_LDA*2 + 2*32*OP_LDB) * (int)sizeof(__half);
    cudaFuncSetAttribute(oproj_kernel, cudaFuncAttributeMaxDynamicSharedMemorySize, smem_op);
    dim3 go(MM / 128, DD / 128);
    oproj_kernel<<<go, 256, smem_op>>>(bo, out);
}

// round 9
// speedup vs baseline: 5.5843x; 1.2487x over previous
#include <cuda_runtime.h>
#include <cuda_fp16.h>

#define BB 4
#define SS 2048
#define DD 768
#define HH 8
#define DHH 96
#define MM (BB*SS)   // 8192

// fp16 scratch. X: split hi/lo (2-term GEMMs). W, Q, K, V: hi only.
__device__ __half g_Xqh[(size_t)MM*DD], g_Xql[(size_t)MM*DD];
__device__ __half g_Xkh[(size_t)MM*DD], g_Xkl[(size_t)MM*DD];
__device__ __half g_Xvh[(size_t)MM*DD], g_Xvl[(size_t)MM*DD];
__device__ __half g_Wqh[(size_t)HH*DD*DHH];
__device__ __half g_Wkh[(size_t)HH*DD*DHH];
__device__ __half g_Wvh[(size_t)HH*DD*DHH];
__device__ __half g_Woh[(size_t)DD*DD];
__device__ __half g_Qh[(size_t)BB*HH*SS*DHH];
__device__ __half g_Kh[(size_t)BB*HH*SS*DHH];
__device__ __half g_Vh[(size_t)BB*HH*SS*DHH];
__device__ __half g_cath[(size_t)MM*DD], g_catl[(size_t)MM*DD];

__device__ __forceinline__ unsigned su32(const void* p) {
    return (unsigned)__cvta_generic_to_shared(p);
}
__device__ __forceinline__ unsigned h2u(half2 v) {
    union { half2 h; unsigned u; } x; x.h = v; return x.u;
}
__device__ __forceinline__ void ldsm4(unsigned r[4], unsigned addr) {
    asm volatile("ldmatrix.sync.aligned.m8n8.x4.shared.b16 {%0,%1,%2,%3},[%4];\n"
        : "=r"(r[0]), "=r"(r[1]), "=r"(r[2]), "=r"(r[3]) : "r"(addr));
}
__device__ __forceinline__ void ldsm4t(unsigned r[4], unsigned addr) {
    asm volatile("ldmatrix.sync.aligned.m8n8.x4.trans.shared.b16 {%0,%1,%2,%3},[%4];\n"
        : "=r"(r[0]), "=r"(r[1]), "=r"(r[2]), "=r"(r[3]) : "r"(addr));
}
__device__ __forceinline__ void mma16816(float* c, const unsigned* a, const unsigned* b) {
    asm volatile("mma.sync.aligned.m16n8k16.row.col.f32.f16.f16.f32 "
        "{%0,%1,%2,%3},{%4,%5,%6,%7},{%8,%9},{%0,%1,%2,%3};\n"
        : "+f"(c[0]), "+f"(c[1]), "+f"(c[2]), "+f"(c[3])
        : "r"(a[0]), "r"(a[1]), "r"(a[2]), "r"(a[3]), "r"(b[0]), "r"(b[1]));
}
__device__ __forceinline__ void splitf(float x, __half& h, __half& l) {
    h = __float2half_rn(x);
    l = __float2half_rn(x - __half2float(h));
}
#define CPA(dst, src) asm volatile("cp.async.cg.shared.global [%0], [%1], 16;\n" :: "r"(dst), "l"(src))
#define CP_COMMIT asm volatile("cp.async.commit_group;\n")
#define CP_WAIT1  asm volatile("cp.async.wait_group 1;\n")
#define CP_WAIT0  asm volatile("cp.async.wait_group 0;\n")

// ---------------------------------------------------------------------------
// Fused preconvert: X -> split hi/lo; W -> hi only.
// ---------------------------------------------------------------------------
#define NX4 (MM*DD/4)          // 1572864
#define NW4 (HH*DD*DHH/4)      // 147456

__global__ __launch_bounds__(256) void split_all(
    const float* __restrict__ Xq, const float* __restrict__ Xk, const float* __restrict__ Xv,
    const float* __restrict__ Wq, const float* __restrict__ Wk, const float* __restrict__ Wv,
    const float* __restrict__ Wo)
{
    int i = blockIdx.x * 256 + threadIdx.x;
    if (i < 3 * NX4) {
        int t = i / NX4; int off = i - t * NX4;
        const float* src = (t == 0) ? Xq : (t == 1) ? Xk : Xv;
        __half* dh = (t == 0) ? g_Xqh : (t == 1) ? g_Xkh : g_Xvh;
        __half* dl = (t == 0) ? g_Xql : (t == 1) ? g_Xkl : g_Xvl;
        float4 v = ((const float4*)src)[off];
        union { __half h[4]; uint2 u; } ph, pl;
        splitf(v.x, ph.h[0], pl.h[0]);
        splitf(v.y, ph.h[1], pl.h[1]);
        splitf(v.z, ph.h[2], pl.h[2]);
        splitf(v.w, ph.h[3], pl.h[3]);
        ((uint2*)dh)[off] = ph.u;
        ((uint2*)dl)[off] = pl.u;
    } else {
        int j = i - 3 * NX4;
        if (j >= 4 * NW4) return;
        int t = j / NW4; int off = j - t * NW4;
        const float* src = (t == 0) ? Wq : (t == 1) ? Wk : (t == 2) ? Wv : Wo;
        __half* dh = (t == 0) ? g_Wqh : (t == 1) ? g_Wkh : (t == 2) ? g_Wvh : g_Woh;
        float4 v = ((const float4*)src)[off];
        union { __half h[4]; uint2 u; } ph;
        ph.h[0] = __float2half_rn(v.x);
        ph.h[1] = __float2half_rn(v.y);
        ph.h[2] = __float2half_rn(v.z);
        ph.h[3] = __float2half_rn(v.w);
        ((uint2*)dh)[off] = ph.u;
    }
}

// ---------------------------------------------------------------------------
// QKV GEMM (2-term: xh*wh + xl*wh). W hi-only, outputs all hi-only.
// Q pre-scaled by 1/sqrt(96).
// ---------------------------------------------------------------------------
#define QK_LDA 40
#define QK_LDB 104

__device__ __forceinline__ void qkv_load(
    __half* Ah, __half* Al, __half* Bh,
    const __half* gXh, const __half* gXl, const __half* gWh,
    int p, int m0, int kt, size_t wbase, int tid)
{
    #pragma unroll
    for (int j = 0; j < 6; j++) {
        int c = tid + j * 256;
        if (c < 1024) {
            int arr = c >> 9, rem = c & 511, row = rem >> 2, off = (rem & 3) * 8;
            const __half* sp = (arr ? gXl : gXh) + (size_t)(m0 + row) * DD + kt + off;
            __half* dp = (arr ? Al : Ah) + p * (128*QK_LDA) + row * QK_LDA + off;
            CPA(su32(dp), sp);
        } else if (c < 1408) {
            int c2 = c - 1024;                 // 0..383
            int row = c2 / 12, off = (c2 - row * 12) * 8;
            const __half* sp = gWh + wbase + (size_t)(kt + row) * DHH + off;
            __half* dp = Bh + p * (32*QK_LDB) + row * QK_LDB + off;
            CPA(su32(dp), sp);
        }
    }
}

__global__ __launch_bounds__(256, 2) void qkv_kernel(
    const float* __restrict__ bq, const float* __restrict__ bk, const float* __restrict__ bv)
{
    extern __shared__ __half smq[];
    __half* Ah = smq;                      // 2 x 128 x 40
    __half* Al = Ah + 2*128*QK_LDA;
    __half* Bh = Al + 2*128*QK_LDA;        // 2 x 32 x 104

    const __half *gXh, *gXl, *gWh; const float* bias; __half *oh;
    if (blockIdx.z == 0)      { gXh=g_Xqh; gXl=g_Xql; gWh=g_Wqh; bias=bq; oh=g_Qh; }
    else if (blockIdx.z == 1) { gXh=g_Xkh; gXl=g_Xkl; gWh=g_Wkh; bias=bk; oh=g_Kh; }
    else                      { gXh=g_Xvh; gXl=g_Xvl; gWh=g_Wvh; bias=bv; oh=g_Vh; }
    const float oscale = (blockIdx.z == 0) ? rsqrtf(96.0f) : 1.0f;

    const int h   = blockIdx.y;
    const int m0  = blockIdx.x * 128;
    const int tid = threadIdx.x;
    const int wid = tid >> 5, lane = tid & 31;
    const int wm  = wid >> 1, wn = wid & 1;
    const size_t wbase = (size_t)h * DD * DHH;

    float acc[2][6][4];
    #pragma unroll
    for (int i = 0; i < 2; i++)
        #pragma unroll
        for (int j = 0; j < 6; j++)
            #pragma unroll
            for (int k = 0; k < 4; k++) acc[i][j][k] = 0.f;

    const int lrow = lane & 15, lcol8 = (lane >> 4) << 3;

    qkv_load(Ah, Al, Bh, gXh, gXl, gWh, 0, m0, 0, wbase, tid);
    CP_COMMIT;

    const int NT = DD / 32;
    for (int it = 0; it < NT; it++) {
        int p = it & 1;
        if (it + 1 < NT) {
            qkv_load(Ah, Al, Bh, gXh, gXl, gWh, (it+1)&1, m0, (it+1)*32, wbase, tid);
            CP_COMMIT;
            CP_WAIT1;
        } else {
            CP_WAIT0;
        }
        __syncthreads();

        __half* Ahp = Ah + p * (128*QK_LDA);
        __half* Alp = Al + p * (128*QK_LDA);
        __half* Bhp = Bh + p * (32*QK_LDB);

        #pragma unroll
        for (int ks = 0; ks < 2; ks++) {
            int k0 = ks * 16;
            unsigned ah[2][4], al[2][4];
            #pragma unroll
            for (int mf = 0; mf < 2; mf++) {
                int row = wm * 32 + mf * 16 + lrow;
                ldsm4(ah[mf], su32(Ahp + row * QK_LDA + k0 + lcol8));
                ldsm4(al[mf], su32(Alp + row * QK_LDA + k0 + lcol8));
            }
            #pragma unroll
            for (int nf2 = 0; nf2 < 3; nf2++) {
                unsigned bh[4];
                int n0 = wn * 48 + nf2 * 16;
                int brow = k0 + lrow;
                ldsm4t(bh, su32(Bhp + brow * QK_LDB + n0 + lcol8));
                #pragma unroll
                for (int hn = 0; hn < 2; hn++) {
                    #pragma unroll
                    for (int mf = 0; mf < 2; mf++) {
                        float* c = acc[mf][nf2*2 + hn];
                        mma16816(c, ah[mf], bh + hn*2);
                        mma16816(c, al[mf], bh + hn*2);
                    }
                }
            }
        }
        __syncthreads();
    }

    #pragma unroll
    for (int mf = 0; mf < 2; mf++) {
        #pragma unroll
        for (int nf = 0; nf < 6; nf++) {
            int col = wn * 48 + nf * 8 + (lane & 3) * 2;
            float b0 = bias[h*DHH + col], b1 = bias[h*DHH + col + 1];
            #pragma unroll
            for (int hr = 0; hr < 2; hr++) {
                int m = m0 + wm * 32 + mf * 16 + (lane >> 2) + hr * 8;
                int bb = m >> 11, s = m & 2047;
                size_t off = (((size_t)(bb * HH + h)) * SS + s) * DHH + col;
                float v0 = (acc[mf][nf][hr*2 + 0] + b0) * oscale;
                float v1 = (acc[mf][nf][hr*2 + 1] + b1) * oscale;
                *(half2*)(oh + off) = __halves2half2(__float2half_rn(v0), __float2half_rn(v1));
            }
        }
    }
}

// ---------------------------------------------------------------------------
// Flash attention, pure fp16 mma (1-term S and PV). Q frags hoisted to regs.
// smem = Qh[128][104] + Kh[64][104] + Vh[64][104] = 52 KB -> 2 blocks/SM.
// ---------------------------------------------------------------------------
#define AT_LD 104

__device__ __forceinline__ void attn_load_k(__half* Kh, size_t gbase, int tid)
{
    #pragma unroll
    for (int j = 0; j < 3; j++) {
        int c = tid + j * 256;
        int row = c / 12;
        int off = (c - row * 12) * 8;
        CPA(su32(Kh + row * AT_LD + off), g_Kh + (gbase + row) * DHH + off);
    }
}
__device__ __forceinline__ void attn_load_v(__half* Vh, size_t gbase, int tid)
{
    #pragma unroll
    for (int j = 0; j < 3; j++) {
        int c = tid + j * 256;
        int row = c / 12;
        int off = (c - row * 12) * 8;
        CPA(su32(Vh + row * AT_LD + off), g_Vh + (gbase + row) * DHH + off);
    }
}

__global__ __launch_bounds__(256, 2) void attn_kernel()
{
    extern __shared__ __half smh[];
    __half* Qh = smh;                 // [128][104]
    __half* Kh = Qh + 128 * AT_LD;    // [64][104]
    __half* Vh = Kh + 64 * AT_LD;     // [64][104]

    const int b  = blockIdx.z, h = blockIdx.y;
    const int s0 = blockIdx.x * 128;
    const int tid = threadIdx.x, wid = tid >> 5, lane = tid & 31;
    const size_t base = ((size_t)(b * HH + h)) * SS;

    {   // load Q tile (hi-only; pre-scaled by qkv)
        int r = tid >> 1, c0 = (tid & 1) * 48;
        size_t go = (base + s0 + r) * DHH + c0;
        __half* dh = Qh + r * AT_LD + c0;
        #pragma unroll
        for (int i = 0; i < 6; i++)
            *(uint4*)(dh + i*8) = *(const uint4*)(g_Qh + go + i*8);
    }

    attn_load_k(Kh, base, tid); CP_COMMIT;
    attn_load_v(Vh, base, tid); CP_COMMIT;

    const int lrow = lane & 15, lcol8 = (lane >> 4) << 3;
    const int krow_off = (lane & 7) + ((lane & 16) >> 1);
    const int kcol_off = (lane & 8);

    __syncthreads();   // Q smem ready
    // Hoist Q fragments (constant across all key tiles)
    unsigned qf[6][4];
    {
        int qrow = wid * 16 + lrow;
        #pragma unroll
        for (int dk = 0; dk < 6; dk++)
            ldsm4(qf[dk], su32(Qh + qrow * AT_LD + dk * 16 + lcol8));
    }

    float oacc[12][4];
    #pragma unroll
    for (int j = 0; j < 12; j++)
        #pragma unroll
        for (int t = 0; t < 4; t++) oacc[j][t] = 0.f;
    float m0r = -1e30f, m1r = -1e30f, l0r = 0.f, l1r = 0.f;

    const int NT = SS / 64;
    for (int it = 0; it < NT; it++) {
        // K(it) arrived (newest outstanding group is V(it))
        CP_WAIT1;
        __syncthreads();

        // S = Qh @ Kh^T (1-term)
        float sacc[8][4];
        #pragma unroll
        for (int j = 0; j < 8; j++)
            #pragma unroll
            for (int t = 0; t < 4; t++) sacc[j][t] = 0.f;

        #pragma unroll
        for (int dk = 0; dk < 6; dk++) {
            int d0 = dk * 16;
            #pragma unroll
            for (int nf2 = 0; nf2 < 4; nf2++) {
                unsigned bh[4];
                int n0 = nf2 * 16;
                ldsm4(bh, su32(Kh + (n0 + krow_off) * AT_LD + d0 + kcol_off));
                mma16816(sacc[nf2*2 + 0], qf[dk], bh + 0);
                mma16816(sacc[nf2*2 + 1], qf[dk], bh + 2);
            }
        }
        __syncthreads();   // all warps done reading K
        if (it + 1 < NT) { attn_load_k(Kh, base + (size_t)(it+1)*64, tid); CP_COMMIT; }

        // online softmax (registers; covers V latency)
        float mx0 = -1e30f, mx1 = -1e30f;
        #pragma unroll
        for (int j = 0; j < 8; j++) {
            mx0 = fmaxf(mx0, fmaxf(sacc[j][0], sacc[j][1]));
            mx1 = fmaxf(mx1, fmaxf(sacc[j][2], sacc[j][3]));
        }
        mx0 = fmaxf(mx0, __shfl_xor_sync(0xffffffffu, mx0, 1));
        mx0 = fmaxf(mx0, __shfl_xor_sync(0xffffffffu, mx0, 2));
        mx1 = fmaxf(mx1, __shfl_xor_sync(0xffffffffu, mx1, 1));
        mx1 = fmaxf(mx1, __shfl_xor_sync(0xffffffffu, mx1, 2));
        float mn0 = fmaxf(m0r, mx0), mn1 = fmaxf(m1r, mx1);
        float corr0 = __expf(m0r - mn0), corr1 = __expf(m1r - mn1);
        m0r = mn0; m1r = mn1;
        float sum0 = 0.f, sum1 = 0.f;
        #pragma unroll
        for (int j = 0; j < 8; j++) {
            sacc[j][0] = __expf(sacc[j][0] - mn0);
            sacc[j][1] = __expf(sacc[j][1] - mn0);
            sacc[j][2] = __expf(sacc[j][2] - mn1);
            sacc[j][3] = __expf(sacc[j][3] - mn1);
            sum0 += sacc[j][0] + sacc[j][1];
            sum1 += sacc[j][2] + sacc[j][3];
        }
        sum0 += __shfl_xor_sync(0xffffffffu, sum0, 1);
        sum0 += __shfl_xor_sync(0xffffffffu, sum0, 2);
        sum1 += __shfl_xor_sync(0xffffffffu, sum1, 1);
        sum1 += __shfl_xor_sync(0xffffffffu, sum1, 2);
        l0r = l0r * corr0 + sum0;
        l1r = l1r * corr1 + sum1;

        #pragma unroll
        for (int j = 0; j < 12; j++) {
            oacc[j][0] *= corr0; oacc[j][1] *= corr0;
            oacc[j][2] *= corr1; oacc[j][3] *= corr1;
        }

        // P fragments (hi-only)
        unsigned ph[4][4];
        #pragma unroll
        for (int kf = 0; kf < 4; kf++) {
            #pragma unroll
            for (int q = 0; q < 4; q++) {
                int fj = kf*2 + (q >> 1);
                int t0 = (q & 1) * 2;
                ph[kf][q] = h2u(__halves2half2(__float2half_rn(sacc[fj][t0]),
                                               __float2half_rn(sacc[fj][t0 + 1])));
            }
        }

        // V(it) arrived
        if (it + 1 < NT) { CP_WAIT1; } else { CP_WAIT0; }
        __syncthreads();

        // O += Ph @ Vh (1-term)
        #pragma unroll
        for (int kf = 0; kf < 4; kf++) {
            int k0 = kf * 16;
            #pragma unroll
            for (int nf2 = 0; nf2 < 6; nf2++) {
                unsigned bh[4];
                int n0 = nf2 * 16;
                ldsm4t(bh, su32(Vh + (k0 + lrow) * AT_LD + n0 + lcol8));
                mma16816(oacc[nf2*2 + 0], ph[kf], bh + 0);
                mma16816(oacc[nf2*2 + 1], ph[kf], bh + 2);
            }
        }
        __syncthreads();   // all warps done reading V
        if (it + 1 < NT) { attn_load_v(Vh, base + (size_t)(it+1)*64, tid); CP_COMMIT; }
    }

    // Epilogue: normalize, split-store to cat [M][768] hi/lo
    float inv0 = 1.0f / l0r, inv1 = 1.0f / l1r;
    #pragma unroll
    for (int nf = 0; nf < 12; nf++) {
        int col = h * DHH + nf * 8 + (lane & 3) * 2;
        #pragma unroll
        for (int hr = 0; hr < 2; hr++) {
            int s = s0 + wid * 16 + (lane >> 2) + hr * 8;
            size_t off = ((size_t)b * SS + s) * DD + col;
            float inv = hr ? inv1 : inv0;
            float v0 = oacc[nf][hr*2 + 0] * inv;
            float v1 = oacc[nf][hr*2 + 1] * inv;
            __half h0,l0,h1,l1; splitf(v0,h0,l0); splitf(v1,h1,l1);
            *(half2*)(g_cath + off) = __halves2half2(h0,h1);
            *(half2*)(g_catl + off) = __halves2half2(l0,l1);
        }
    }
}

// ---------------------------------------------------------------------------
// Output projection (2-term: (cath+catl)*woh). Wo hi-only.
// ---------------------------------------------------------------------------
#define OP_LDA 40
#define OP_LDB 136

__device__ __forceinline__ void oproj_load(
    __half* Ah, __half* Al, __half* Bh,
    int p, int m0, int n0b, int kt, int tid)
{
    #pragma unroll
    for (int j = 0; j < 6; j++) {
        int c = tid + j * 256;
        if (c < 1024) {
            int arr = c >> 9, rem = c & 511, row = rem >> 2, off = (rem & 3) * 8;
            const __half* sp = (arr ? g_catl : g_cath) + (size_t)(m0 + row) * DD + kt + off;
            __half* dp = (arr ? Al : Ah) + p * (128*OP_LDA) + row * OP_LDA + off;
            CPA(su32(dp), sp);
        } else {
            int c2 = c - 1024;                // 0..511
            int row = c2 >> 4, off = (c2 & 15) * 8;
            const __half* sp = g_Woh + (size_t)(kt + row) * DD + n0b + off;
            __half* dp = Bh + p * (32*OP_LDB) + row * OP_LDB + off;
            CPA(su32(dp), sp);
        }
    }
}

__global__ __launch_bounds__(256, 2) void oproj_kernel(
    const float* __restrict__ bo, float* __restrict__ out)
{
    extern __shared__ __half smo[];
    __half* Ah = smo;
    __half* Al = Ah + 2*128*OP_LDA;
    __half* Bh = Al + 2*128*OP_LDA;

    const int m0  = blockIdx.x * 128;
    const int n0b = blockIdx.y * 128;
    const int tid = threadIdx.x, wid = tid >> 5, lane = tid & 31;
    const int wm = wid >> 1, wn = wid & 1;

    float acc[2][8][4];
    #pragma unroll
    for (int i = 0; i < 2; i++)
        #pragma unroll
        for (int j = 0; j < 8; j++)
            #pragma unroll
            for (int k = 0; k < 4; k++) acc[i][j][k] = 0.f;

    const int lrow = lane & 15, lcol8 = (lane >> 4) << 3;

    oproj_load(Ah, Al, Bh, 0, m0, n0b, 0, tid);
    CP_COMMIT;

    const int NT = DD / 32;
    for (int it = 0; it < NT; it++) {
        int p = it & 1;
        if (it + 1 < NT) {
            oproj_load(Ah, Al, Bh, (it+1)&1, m0, n0b, (it+1)*32, tid);
            CP_COMMIT;
            CP_WAIT1;
        } else {
            CP_WAIT0;
        }
        __syncthreads();

        __half* Ahp = Ah + p * (128*OP_LDA);
        __half* Alp = Al + p * (128*OP_LDA);
        __half* Bhp = Bh + p * (32*OP_LDB);

        #pragma unroll
        for (int ks = 0; ks < 2; ks++) {
            int k0 = ks * 16;
            unsigned ah[2][4], al[2][4];
            #pragma unroll
            for (int mf = 0; mf < 2; mf++) {
                int row = wm * 32 + mf * 16 + lrow;
                ldsm4(ah[mf], su32(Ahp + row * OP_LDA + k0 + lcol8));
                ldsm4(al[mf], su32(Alp + row * OP_LDA + k0 + lcol8));
            }
            #pragma unroll
            for (int nf2 = 0; nf2 < 4; nf2++) {
                unsigned bh[4];
                int n0 = wn * 64 + nf2 * 16;
                int brow = k0 + lrow;
                ldsm4t(bh, su32(Bhp + brow * OP_LDB + n0 + lcol8));
                #pragma unroll
                for (int hn = 0; hn < 2; hn++) {
                    #pragma unroll
                    for (int mf = 0; mf < 2; mf++) {
                        float* c = acc[mf][nf2*2 + hn];
                        mma16816(c, ah[mf], bh + hn*2);
                        mma16816(c, al[mf], bh + hn*2);
                    }
                }
            }
        }
        __syncthreads();
    }

    #pragma unroll
    for (int mf = 0; mf < 2; mf++) {
        #pragma unroll
        for (int nf = 0; nf < 8; nf++) {
            int col = n0b + wn * 64 + nf * 8 + (lane & 3) * 2;
            float b0 = bo[col], b1 = bo[col + 1];
            #pragma unroll
            for (int hr = 0; hr < 2; hr++) {
                int m = m0 + wm * 32 + mf * 16 + (lane >> 2) + hr * 8;
                float2 v = make_float2(acc[mf][nf][hr*2+0] + b0,
                                       acc[mf][nf][hr*2+1] + b1);
                *(float2*)(out + (size_t)m * DD + col) = v;
            }
        }
    }
}

// ---------------------------------------------------------------------------
extern "C" void kernel_launch(void* const* d_in, const int* in_sizes, int n_in,
                              void* d_out, int out_size)
{
    (void)in_sizes; (void)n_in; (void)out_size;
    const float* Xq = (const float*)d_in[0];
    const float* Xk = (const float*)d_in[1];
    const float* Xv = (const float*)d_in[2];
    const float* Wq = (const float*)d_in[3];
    const float* bq = (const float*)d_in[4];
    const float* Wk = (const float*)d_in[5];
    const float* bk = (const float*)d_in[6];
    const float* Wv = (const float*)d_in[7];
    const float* bv = (const float*)d_in[8];
    const float* Wo = (const float*)d_in[9];
    const float* bo = (const float*)d_in[10];
    float* out = (float*)d_out;

    const int total4 = 3*NX4 + 4*NW4;
    split_all<<<(total4 + 255) / 256, 256>>>(Xq, Xk, Xv, Wq, Wk, Wv, Wo);

    const int smem_qkv = (2*128*QK_LDA*2 + 2*32*QK_LDB) * (int)sizeof(__half);
    cudaFuncSetAttribute(qkv_kernel, cudaFuncAttributeMaxDynamicSharedMemorySize, smem_qkv);
    dim3 gq(MM / 128, HH, 3);
    qkv_kernel<<<gq, 256, smem_qkv>>>(bq, bk, bv);

    const int smem_attn = (128*AT_LD + 2*64*AT_LD) * (int)sizeof(__half);  // 52 KB
    cudaFuncSetAttribute(attn_kernel, cudaFuncAttributeMaxDynamicSharedMemorySize, smem_attn);
    dim3 ga(SS / 128, HH, BB);
    attn_kernel<<<ga, 256, smem_attn>>>();

    const int smem_op = (2*128*OP_LDA*2 + 2*32*OP_LDB) * (int)sizeof(__half);
    cudaFuncSetAttribute(oproj_kernel, cudaFuncAttributeMaxDynamicSharedMemorySize, smem_op);
    dim3 go(MM / 128, DD / 128);
    oproj_kernel<<<go, 256, smem_op>>>(bo, out);
}

// round 10
// speedup vs baseline: 7.1119x; 1.2736x over previous
#include <cuda_runtime.h>
#include <cuda_fp16.h>

#define BB 4
#define SS 2048
#define DD 768
#define HH 8
#define DHH 96
#define MM (BB*SS)   // 8192

// Pure fp16 scratch (hi-only everywhere; fp32 accumulate in mma)
__device__ __half g_Xqh[(size_t)MM*DD];
__device__ __half g_Xkh[(size_t)MM*DD];
__device__ __half g_Xvh[(size_t)MM*DD];
__device__ __half g_Wqh[(size_t)HH*DD*DHH];
__device__ __half g_Wkh[(size_t)HH*DD*DHH];
__device__ __half g_Wvh[(size_t)HH*DD*DHH];
__device__ __half g_Woh[(size_t)DD*DD];
__device__ __half g_Qh[(size_t)BB*HH*SS*DHH];
__device__ __half g_Kh[(size_t)BB*HH*SS*DHH];
__device__ __half g_Vh[(size_t)BB*HH*SS*DHH];
__device__ __half g_cath[(size_t)MM*DD];

__device__ __forceinline__ unsigned su32(const void* p) {
    return (unsigned)__cvta_generic_to_shared(p);
}
__device__ __forceinline__ unsigned h2u(half2 v) {
    union { half2 h; unsigned u; } x; x.h = v; return x.u;
}
__device__ __forceinline__ void ldsm4(unsigned r[4], unsigned addr) {
    asm volatile("ldmatrix.sync.aligned.m8n8.x4.shared.b16 {%0,%1,%2,%3},[%4];\n"
        : "=r"(r[0]), "=r"(r[1]), "=r"(r[2]), "=r"(r[3]) : "r"(addr));
}
__device__ __forceinline__ void ldsm4t(unsigned r[4], unsigned addr) {
    asm volatile("ldmatrix.sync.aligned.m8n8.x4.trans.shared.b16 {%0,%1,%2,%3},[%4];\n"
        : "=r"(r[0]), "=r"(r[1]), "=r"(r[2]), "=r"(r[3]) : "r"(addr));
}
__device__ __forceinline__ void mma16816(float* c, const unsigned* a, const unsigned* b) {
    asm volatile("mma.sync.aligned.m16n8k16.row.col.f32.f16.f16.f32 "
        "{%0,%1,%2,%3},{%4,%5,%6,%7},{%8,%9},{%0,%1,%2,%3};\n"
        : "+f"(c[0]), "+f"(c[1]), "+f"(c[2]), "+f"(c[3])
        : "r"(a[0]), "r"(a[1]), "r"(a[2]), "r"(a[3]), "r"(b[0]), "r"(b[1]));
}
#define CPA(dst, src) asm volatile("cp.async.cg.shared.global [%0], [%1], 16;\n" :: "r"(dst), "l"(src))
#define CP_COMMIT asm volatile("cp.async.commit_group;\n")
#define CP_WAIT1  asm volatile("cp.async.wait_group 1;\n")
#define CP_WAIT0  asm volatile("cp.async.wait_group 0;\n")

// ---------------------------------------------------------------------------
// Preconvert fp32 -> fp16 (all 7 tensors, one launch)
// ---------------------------------------------------------------------------
#define NX4 (MM*DD/4)          // 1572864
#define NW4 (HH*DD*DHH/4)      // 147456

__global__ __launch_bounds__(256) void convert_all(
    const float* __restrict__ Xq, const float* __restrict__ Xk, const float* __restrict__ Xv,
    const float* __restrict__ Wq, const float* __restrict__ Wk, const float* __restrict__ Wv,
    const float* __restrict__ Wo)
{
    int i = blockIdx.x * 256 + threadIdx.x;
    const float* src; __half* dh; int off;
    if (i < 3 * NX4) {
        int t = i / NX4; off = i - t * NX4;
        src = (t == 0) ? Xq : (t == 1) ? Xk : Xv;
        dh  = (t == 0) ? g_Xqh : (t == 1) ? g_Xkh : g_Xvh;
    } else {
        int j = i - 3 * NX4;
        if (j >= 4 * NW4) return;
        int t = j / NW4; off = j - t * NW4;
        src = (t == 0) ? Wq : (t == 1) ? Wk : (t == 2) ? Wv : Wo;
        dh  = (t == 0) ? g_Wqh : (t == 1) ? g_Wkh : (t == 2) ? g_Wvh : g_Woh;
    }
    float4 v = ((const float4*)src)[off];
    union { __half h[4]; uint2 u; } ph;
    ph.h[0] = __float2half_rn(v.x);
    ph.h[1] = __float2half_rn(v.y);
    ph.h[2] = __float2half_rn(v.z);
    ph.h[3] = __float2half_rn(v.w);
    ((uint2*)dh)[off] = ph.u;
}

// ---------------------------------------------------------------------------
// QKV GEMM (pure fp16, fp32 accum). Q pre-scaled by 1/sqrt(96).
// BM=128, BN=96, BK=32, double-buffered cp.async. grid=(64, 8, 3).
// ---------------------------------------------------------------------------
#define QK_LDA 40
#define QK_LDB 104

__device__ __forceinline__ void qkv_load(
    __half* Ah, __half* Bh,
    const __half* gXh, const __half* gWh,
    int p, int m0, int kt, size_t wbase, int tid)
{
    #pragma unroll
    for (int j = 0; j < 4; j++) {
        int c = tid + j * 256;
        if (c < 512) {
            int row = c >> 2, off = (c & 3) * 8;
            CPA(su32(Ah + p * (128*QK_LDA) + row * QK_LDA + off),
                gXh + (size_t)(m0 + row) * DD + kt + off);
        } else if (c < 896) {
            int c2 = c - 512;                  // 0..383
            int row = c2 / 12, off = (c2 - row * 12) * 8;
            CPA(su32(Bh + p * (32*QK_LDB) + row * QK_LDB + off),
                gWh + wbase + (size_t)(kt + row) * DHH + off);
        }
    }
}

__global__ __launch_bounds__(256, 2) void qkv_kernel(
    const float* __restrict__ bq, const float* __restrict__ bk, const float* __restrict__ bv)
{
    extern __shared__ __half smq[];
    __half* Ah = smq;                      // 2 x 128 x 40
    __half* Bh = Ah + 2*128*QK_LDA;        // 2 x 32 x 104

    const __half *gXh, *gWh; const float* bias; __half *oh;
    if (blockIdx.z == 0)      { gXh=g_Xqh; gWh=g_Wqh; bias=bq; oh=g_Qh; }
    else if (blockIdx.z == 1) { gXh=g_Xkh; gWh=g_Wkh; bias=bk; oh=g_Kh; }
    else                      { gXh=g_Xvh; gWh=g_Wvh; bias=bv; oh=g_Vh; }
    const float oscale = (blockIdx.z == 0) ? rsqrtf(96.0f) : 1.0f;

    const int h   = blockIdx.y;
    const int m0  = blockIdx.x * 128;
    const int tid = threadIdx.x;
    const int wid = tid >> 5, lane = tid & 31;
    const int wm  = wid >> 1, wn = wid & 1;
    const size_t wbase = (size_t)h * DD * DHH;

    float acc[2][6][4];
    #pragma unroll
    for (int i = 0; i < 2; i++)
        #pragma unroll
        for (int j = 0; j < 6; j++)
            #pragma unroll
            for (int k = 0; k < 4; k++) acc[i][j][k] = 0.f;

    const int lrow = lane & 15, lcol8 = (lane >> 4) << 3;

    qkv_load(Ah, Bh, gXh, gWh, 0, m0, 0, wbase, tid);
    CP_COMMIT;

    const int NT = DD / 32;
    for (int it = 0; it < NT; it++) {
        int p = it & 1;
        if (it + 1 < NT) {
            qkv_load(Ah, Bh, gXh, gWh, (it+1)&1, m0, (it+1)*32, wbase, tid);
            CP_COMMIT;
            CP_WAIT1;
        } else {
            CP_WAIT0;
        }
        __syncthreads();

        __half* Ahp = Ah + p * (128*QK_LDA);
        __half* Bhp = Bh + p * (32*QK_LDB);

        #pragma unroll
        for (int ks = 0; ks < 2; ks++) {
            int k0 = ks * 16;
            unsigned ah[2][4];
            #pragma unroll
            for (int mf = 0; mf < 2; mf++) {
                int row = wm * 32 + mf * 16 + lrow;
                ldsm4(ah[mf], su32(Ahp + row * QK_LDA + k0 + lcol8));
            }
            #pragma unroll
            for (int nf2 = 0; nf2 < 3; nf2++) {
                unsigned bh[4];
                int n0 = wn * 48 + nf2 * 16;
                ldsm4t(bh, su32(Bhp + (k0 + lrow) * QK_LDB + n0 + lcol8));
                #pragma unroll
                for (int hn = 0; hn < 2; hn++) {
                    #pragma unroll
                    for (int mf = 0; mf < 2; mf++)
                        mma16816(acc[mf][nf2*2 + hn], ah[mf], bh + hn*2);
                }
            }
        }
        __syncthreads();
    }

    #pragma unroll
    for (int mf = 0; mf < 2; mf++) {
        #pragma unroll
        for (int nf = 0; nf < 6; nf++) {
            int col = wn * 48 + nf * 8 + (lane & 3) * 2;
            float b0 = bias[h*DHH + col], b1 = bias[h*DHH + col + 1];
            #pragma unroll
            for (int hr = 0; hr < 2; hr++) {
                int m = m0 + wm * 32 + mf * 16 + (lane >> 2) + hr * 8;
                int bb = m >> 11, s = m & 2047;
                size_t off = (((size_t)(bb * HH + h)) * SS + s) * DHH + col;
                float v0 = (acc[mf][nf][hr*2 + 0] + b0) * oscale;
                float v1 = (acc[mf][nf][hr*2 + 1] + b1) * oscale;
                *(half2*)(oh + off) = __halves2half2(__float2half_rn(v0), __float2half_rn(v1));
            }
        }
    }
}

// ---------------------------------------------------------------------------
// Flash attention, pure fp16 mma, double-buffered K+V (one group per tile).
// smem = Q[128][104] + 2 x (K[64][104] + V[64][104]) = 78 KB -> 2 blocks/SM.
// 2 barriers per tile.
// ---------------------------------------------------------------------------
#define AT_LD 104
#define KV_STG (64*AT_LD)

__device__ __forceinline__ void attn_load_kv(
    __half* Kbuf, __half* Vbuf, size_t gbase, int tid)
{
    #pragma unroll
    for (int j = 0; j < 6; j++) {
        int c = tid + j * 256;            // 0..1535
        int arr = (c >= 768) ? 1 : 0;
        int rem = c - arr * 768;
        int row = rem / 12;
        int off = (rem - row * 12) * 8;
        const __half* sp = (arr ? g_Vh : g_Kh) + (gbase + row) * DHH + off;
        __half* dp = (arr ? Vbuf : Kbuf) + row * AT_LD + off;
        CPA(su32(dp), sp);
    }
}

__global__ __launch_bounds__(256, 2) void attn_kernel()
{
    extern __shared__ __half smh[];
    __half* Qh  = smh;                    // [128][104]
    __half* KV0 = Qh + 128 * AT_LD;       // stage 0: K | V
    __half* KV1 = KV0 + 2 * KV_STG;       // stage 1: K | V

    const int b  = blockIdx.z, h = blockIdx.y;
    const int s0 = blockIdx.x * 128;
    const int tid = threadIdx.x, wid = tid >> 5, lane = tid & 31;
    const size_t base = ((size_t)(b * HH + h)) * SS;

    {   // load Q tile
        int r = tid >> 1, c0 = (tid & 1) * 48;
        size_t go = (base + s0 + r) * DHH + c0;
        __half* dh = Qh + r * AT_LD + c0;
        #pragma unroll
        for (int i = 0; i < 6; i++)
            *(uint4*)(dh + i*8) = *(const uint4*)(g_Qh + go + i*8);
    }

    attn_load_kv(KV0, KV0 + KV_STG, base, tid);      CP_COMMIT;
    attn_load_kv(KV1, KV1 + KV_STG, base + 64, tid); CP_COMMIT;

    const int lrow = lane & 15, lcol8 = (lane >> 4) << 3;
    const int krow_off = (lane & 7) + ((lane & 16) >> 1);
    const int kcol_off = (lane & 8);

    __syncthreads();   // Q smem ready
    unsigned qf[6][4];
    {
        int qrow = wid * 16 + lrow;
        #pragma unroll
        for (int dk = 0; dk < 6; dk++)
            ldsm4(qf[dk], su32(Qh + qrow * AT_LD + dk * 16 + lcol8));
    }

    float oacc[12][4];
    #pragma unroll
    for (int j = 0; j < 12; j++)
        #pragma unroll
        for (int t = 0; t < 4; t++) oacc[j][t] = 0.f;
    float m0r = -1e30f, m1r = -1e30f, l0r = 0.f, l1r = 0.f;

    const int NT = SS / 64;   // 32
    for (int it = 0; it < NT; it++) {
        if (it + 1 < NT) { CP_WAIT1; } else { CP_WAIT0; }
        __syncthreads();

        __half* Kp = ((it & 1) ? KV1 : KV0);
        __half* Vp = Kp + KV_STG;

        // S = Q @ K^T
        float sacc[8][4];
        #pragma unroll
        for (int j = 0; j < 8; j++)
            #pragma unroll
            for (int t = 0; t < 4; t++) sacc[j][t] = 0.f;

        #pragma unroll
        for (int dk = 0; dk < 6; dk++) {
            int d0 = dk * 16;
            #pragma unroll
            for (int nf2 = 0; nf2 < 4; nf2++) {
                unsigned bh[4];
                ldsm4(bh, su32(Kp + (nf2 * 16 + krow_off) * AT_LD + d0 + kcol_off));
                mma16816(sacc[nf2*2 + 0], qf[dk], bh + 0);
                mma16816(sacc[nf2*2 + 1], qf[dk], bh + 2);
            }
        }

        // online softmax (registers)
        float mx0 = -1e30f, mx1 = -1e30f;
        #pragma unroll
        for (int j = 0; j < 8; j++) {
            mx0 = fmaxf(mx0, fmaxf(sacc[j][0], sacc[j][1]));
            mx1 = fmaxf(mx1, fmaxf(sacc[j][2], sacc[j][3]));
        }
        mx0 = fmaxf(mx0, __shfl_xor_sync(0xffffffffu, mx0, 1));
        mx0 = fmaxf(mx0, __shfl_xor_sync(0xffffffffu, mx0, 2));
        mx1 = fmaxf(mx1, __shfl_xor_sync(0xffffffffu, mx1, 1));
        mx1 = fmaxf(mx1, __shfl_xor_sync(0xffffffffu, mx1, 2));
        float mn0 = fmaxf(m0r, mx0), mn1 = fmaxf(m1r, mx1);
        float corr0 = __expf(m0r - mn0), corr1 = __expf(m1r - mn1);
        m0r = mn0; m1r = mn1;
        float sum0 = 0.f, sum1 = 0.f;
        #pragma unroll
        for (int j = 0; j < 8; j++) {
            sacc[j][0] = __expf(sacc[j][0] - mn0);
            sacc[j][1] = __expf(sacc[j][1] - mn0);
            sacc[j][2] = __expf(sacc[j][2] - mn1);
            sacc[j][3] = __expf(sacc[j][3] - mn1);
            sum0 += sacc[j][0] + sacc[j][1];
            sum1 += sacc[j][2] + sacc[j][3];
        }
        sum0 += __shfl_xor_sync(0xffffffffu, sum0, 1);
        sum0 += __shfl_xor_sync(0xffffffffu, sum0, 2);
        sum1 += __shfl_xor_sync(0xffffffffu, sum1, 1);
        sum1 += __shfl_xor_sync(0xffffffffu, sum1, 2);
        l0r = l0r * corr0 + sum0;
        l1r = l1r * corr1 + sum1;

        #pragma unroll
        for (int j = 0; j < 12; j++) {
            oacc[j][0] *= corr0; oacc[j][1] *= corr0;
            oacc[j][2] *= corr1; oacc[j][3] *= corr1;
        }

        // P fragments
        unsigned ph[4][4];
        #pragma unroll
        for (int kf = 0; kf < 4; kf++) {
            #pragma unroll
            for (int q = 0; q < 4; q++) {
                int fj = kf*2 + (q >> 1);
                int t0 = (q & 1) * 2;
                ph[kf][q] = h2u(__halves2half2(__float2half_rn(sacc[fj][t0]),
                                               __float2half_rn(sacc[fj][t0 + 1])));
            }
        }

        // O += P @ V
        #pragma unroll
        for (int kf = 0; kf < 4; kf++) {
            int k0 = kf * 16;
            #pragma unroll
            for (int nf2 = 0; nf2 < 6; nf2++) {
                unsigned bh[4];
                ldsm4t(bh, su32(Vp + (k0 + lrow) * AT_LD + nf2 * 16 + lcol8));
                mma16816(oacc[nf2*2 + 0], ph[kf], bh + 0);
                mma16816(oacc[nf2*2 + 1], ph[kf], bh + 2);
            }
        }
        __syncthreads();   // all warps done with this stage's K and V
        if (it + 2 < NT) {
            attn_load_kv(Kp, Vp, base + (size_t)(it+2)*64, tid);
            CP_COMMIT;
        }
    }

    // Epilogue: normalize, store cat (fp16 hi-only)
    float inv0 = 1.0f / l0r, inv1 = 1.0f / l1r;
    #pragma unroll
    for (int nf = 0; nf < 12; nf++) {
        int col = h * DHH + nf * 8 + (lane & 3) * 2;
        #pragma unroll
        for (int hr = 0; hr < 2; hr++) {
            int s = s0 + wid * 16 + (lane >> 2) + hr * 8;
            size_t off = ((size_t)b * SS + s) * DD + col;
            float inv = hr ? inv1 : inv0;
            float v0 = oacc[nf][hr*2 + 0] * inv;
            float v1 = oacc[nf][hr*2 + 1] * inv;
            *(half2*)(g_cath + off) = __halves2half2(__float2half_rn(v0), __float2half_rn(v1));
        }
    }
}

// ---------------------------------------------------------------------------
// Output projection (pure fp16): out = cath @ Woh + bo. BM=128, BN=128, BK=32.
// ---------------------------------------------------------------------------
#define OP_LDA 40
#define OP_LDB 136

__device__ __forceinline__ void oproj_load(
    __half* Ah, __half* Bh, int p, int m0, int n0b, int kt, int tid)
{
    #pragma unroll
    for (int j = 0; j < 4; j++) {
        int c = tid + j * 256;
        if (c < 512) {
            int row = c >> 2, off = (c & 3) * 8;
            CPA(su32(Ah + p * (128*OP_LDA) + row * OP_LDA + off),
                g_cath + (size_t)(m0 + row) * DD + kt + off);
        } else {
            int c2 = c - 512;                 // 0..511
            int row = c2 >> 4, off = (c2 & 15) * 8;
            CPA(su32(Bh + p * (32*OP_LDB) + row * OP_LDB + off),
                g_Woh + (size_t)(kt + row) * DD + n0b + off);
        }
    }
}

__global__ __launch_bounds__(256, 2) void oproj_kernel(
    const float* __restrict__ bo, float* __restrict__ out)
{
    extern __shared__ __half smo[];
    __half* Ah = smo;
    __half* Bh = Ah + 2*128*OP_LDA;

    const int m0  = blockIdx.x * 128;
    const int n0b = blockIdx.y * 128;
    const int tid = threadIdx.x, wid = tid >> 5, lane = tid & 31;
    const int wm = wid >> 1, wn = wid & 1;

    float acc[2][8][4];
    #pragma unroll
    for (int i = 0; i < 2; i++)
        #pragma unroll
        for (int j = 0; j < 8; j++)
            #pragma unroll
            for (int k = 0; k < 4; k++) acc[i][j][k] = 0.f;

    const int lrow = lane & 15, lcol8 = (lane >> 4) << 3;

    oproj_load(Ah, Bh, 0, m0, n0b, 0, tid);
    CP_COMMIT;

    const int NT = DD / 32;
    for (int it = 0; it < NT; it++) {
        int p = it & 1;
        if (it + 1 < NT) {
            oproj_load(Ah, Bh, (it+1)&1, m0, n0b, (it+1)*32, tid);
            CP_COMMIT;
            CP_WAIT1;
        } else {
            CP_WAIT0;
        }
        __syncthreads();

        __half* Ahp = Ah + p * (128*OP_LDA);
        __half* Bhp = Bh + p * (32*OP_LDB);

        #pragma unroll
        for (int ks = 0; ks < 2; ks++) {
            int k0 = ks * 16;
            unsigned ah[2][4];
            #pragma unroll
            for (int mf = 0; mf < 2; mf++) {
                int row = wm * 32 + mf * 16 + lrow;
                ldsm4(ah[mf], su32(Ahp + row * OP_LDA + k0 + lcol8));
            }
            #pragma unroll
            for (int nf2 = 0; nf2 < 4; nf2++) {
                unsigned bh[4];
                int n0 = wn * 64 + nf2 * 16;
                ldsm4t(bh, su32(Bhp + (k0 + lrow) * OP_LDB + n0 + lcol8));
                #pragma unroll
                for (int hn = 0; hn < 2; hn++) {
                    #pragma unroll
                    for (int mf = 0; mf < 2; mf++)
                        mma16816(acc[mf][nf2*2 + hn], ah[mf], bh + hn*2);
                }
            }
        }
        __syncthreads();
    }

    #pragma unroll
    for (int mf = 0; mf < 2; mf++) {
        #pragma unroll
        for (int nf = 0; nf < 8; nf++) {
            int col = n0b + wn * 64 + nf * 8 + (lane & 3) * 2;
            float b0 = bo[col], b1 = bo[col + 1];
            #pragma unroll
            for (int hr = 0; hr < 2; hr++) {
                int m = m0 + wm * 32 + mf * 16 + (lane >> 2) + hr * 8;
                float2 v = make_float2(acc[mf][nf][hr*2+0] + b0,
                                       acc[mf][nf][hr*2+1] + b1);
                *(float2*)(out + (size_t)m * DD + col) = v;
            }
        }
    }
}

// ---------------------------------------------------------------------------
extern "C" void kernel_launch(void* const* d_in, const int* in_sizes, int n_in,
                              void* d_out, int out_size)
{
    (void)in_sizes; (void)n_in; (void)out_size;
    const float* Xq = (const float*)d_in[0];
    const float* Xk = (const float*)d_in[1];
    const float* Xv = (const float*)d_in[2];
    const float* Wq = (const float*)d_in[3];
    const float* bq = (const float*)d_in[4];
    const float* Wk = (const float*)d_in[5];
    const float* bk = (const float*)d_in[6];
    const float* Wv = (const float*)d_in[7];
    const float* bv = (const float*)d_in[8];
    const float* Wo = (const float*)d_in[9];
    const float* bo = (const float*)d_in[10];
    float* out = (float*)d_out;

    const int total4 = 3*NX4 + 4*NW4;
    convert_all<<<(total4 + 255) / 256, 256>>>(Xq, Xk, Xv, Wq, Wk, Wv, Wo);

    const int smem_qkv = (2*128*QK_LDA + 2*32*QK_LDB) * (int)sizeof(__half);   // 33792
    cudaFuncSetAttribute(qkv_kernel, cudaFuncAttributeMaxDynamicSharedMemorySize, smem_qkv);
    dim3 gq(MM / 128, HH, 3);
    qkv_kernel<<<gq, 256, smem_qkv>>>(bq, bk, bv);

    const int smem_attn = (128*AT_LD + 4*64*AT_LD) * (int)sizeof(__half);      // 79872
    cudaFuncSetAttribute(attn_kernel, cudaFuncAttributeMaxDynamicSharedMemorySize, smem_attn);
    dim3 ga(SS / 128, HH, BB);
    attn_kernel<<<ga, 256, smem_attn>>>();

    const int smem_op = (2*128*OP_LDA + 2*32*OP_LDB) * (int)sizeof(__half);    // 37888
    cudaFuncSetAttribute(oproj_kernel, cudaFuncAttributeMaxDynamicSharedMemorySize, smem_op);
    dim3 go(MM / 128, DD / 128);
    oproj_kernel<<<go, 256, smem_op>>>(bo, out);
}

// round 11
// speedup vs baseline: 7.4090x; 1.0418x over previous
#include <cuda_runtime.h>
#include <cuda_fp16.h>

#define BB 4
#define SS 2048
#define DD 768
#define HH 8
#define DHH 96
#define MM (BB*SS)   // 8192

// Pure fp16 scratch (fp32 accumulate in mma)
__device__ __half g_Xqh[(size_t)MM*DD];
__device__ __half g_Xkh[(size_t)MM*DD];
__device__ __half g_Xvh[(size_t)MM*DD];
__device__ __half g_Wqh[(size_t)HH*DD*DHH];
__device__ __half g_Wkh[(size_t)HH*DD*DHH];
__device__ __half g_Wvh[(size_t)HH*DD*DHH];
__device__ __half g_Woh[(size_t)DD*DD];
__device__ __half g_Qh[(size_t)BB*HH*SS*DHH];
__device__ __half g_Kh[(size_t)BB*HH*SS*DHH];
__device__ __half g_Vh[(size_t)BB*HH*SS*DHH];
__device__ __half g_cath[(size_t)MM*DD];

__device__ __forceinline__ unsigned su32(const void* p) {
    return (unsigned)__cvta_generic_to_shared(p);
}
__device__ __forceinline__ unsigned h2u(half2 v) {
    union { half2 h; unsigned u; } x; x.h = v; return x.u;
}
__device__ __forceinline__ void ldsm4(unsigned r[4], unsigned addr) {
    asm volatile("ldmatrix.sync.aligned.m8n8.x4.shared.b16 {%0,%1,%2,%3},[%4];\n"
        : "=r"(r[0]), "=r"(r[1]), "=r"(r[2]), "=r"(r[3]) : "r"(addr));
}
__device__ __forceinline__ void ldsm4t(unsigned r[4], unsigned addr) {
    asm volatile("ldmatrix.sync.aligned.m8n8.x4.trans.shared.b16 {%0,%1,%2,%3},[%4];\n"
        : "=r"(r[0]), "=r"(r[1]), "=r"(r[2]), "=r"(r[3]) : "r"(addr));
}
__device__ __forceinline__ void mma16816(float* c, const unsigned* a, const unsigned* b) {
    asm volatile("mma.sync.aligned.m16n8k16.row.col.f32.f16.f16.f32 "
        "{%0,%1,%2,%3},{%4,%5,%6,%7},{%8,%9},{%0,%1,%2,%3};\n"
        : "+f"(c[0]), "+f"(c[1]), "+f"(c[2]), "+f"(c[3])
        : "r"(a[0]), "r"(a[1]), "r"(a[2]), "r"(a[3]), "r"(b[0]), "r"(b[1]));
}
#define CPA(dst, src) asm volatile("cp.async.cg.shared.global [%0], [%1], 16;\n" :: "r"(dst), "l"(src))
#define CP_COMMIT asm volatile("cp.async.commit_group;\n")
#define CP_WAIT2  asm volatile("cp.async.wait_group 2;\n")
#define CP_WAIT1  asm volatile("cp.async.wait_group 1;\n")
#define CP_WAIT0  asm volatile("cp.async.wait_group 0;\n")

// ---------------------------------------------------------------------------
// Preconvert fp32 -> fp16 (all 7 tensors, one launch)
// ---------------------------------------------------------------------------
#define NX4 (MM*DD/4)          // 1572864
#define NW4 (HH*DD*DHH/4)      // 147456

__global__ __launch_bounds__(256) void convert_all(
    const float* __restrict__ Xq, const float* __restrict__ Xk, const float* __restrict__ Xv,
    const float* __restrict__ Wq, const float* __restrict__ Wk, const float* __restrict__ Wv,
    const float* __restrict__ Wo)
{
    int i = blockIdx.x * 256 + threadIdx.x;
    const float* src; __half* dh; int off;
    if (i < 3 * NX4) {
        int t = i / NX4; off = i - t * NX4;
        src = (t == 0) ? Xq : (t == 1) ? Xk : Xv;
        dh  = (t == 0) ? g_Xqh : (t == 1) ? g_Xkh : g_Xvh;
    } else {
        int j = i - 3 * NX4;
        if (j >= 4 * NW4) return;
        int t = j / NW4; off = j - t * NW4;
        src = (t == 0) ? Wq : (t == 1) ? Wk : (t == 2) ? Wv : Wo;
        dh  = (t == 0) ? g_Wqh : (t == 1) ? g_Wkh : (t == 2) ? g_Wvh : g_Woh;
    }
    float4 v = ((const float4*)src)[off];
    union { __half h[4]; uint2 u; } ph;
    ph.h[0] = __float2half_rn(v.x);
    ph.h[1] = __float2half_rn(v.y);
    ph.h[2] = __float2half_rn(v.z);
    ph.h[3] = __float2half_rn(v.w);
    ((uint2*)dh)[off] = ph.u;
}

// ---------------------------------------------------------------------------
// QKV GEMM (fp16, fp32 accum). BM=128, BN=96, BK=64, 2-stage cp.async.
// Q pre-scaled by 1/sqrt(96). grid=(64, 8, 3).
// ---------------------------------------------------------------------------
#define QK_LDA 72
#define QK_LDB 104

__device__ __forceinline__ void qkv_load(
    __half* Ah, __half* Bh,
    const __half* gXh, const __half* gWh,
    int p, int m0, int kt, size_t wbase, int tid)
{
    #pragma unroll
    for (int j = 0; j < 7; j++) {
        int c = tid + j * 256;             // 0..1791
        if (c < 1024) {
            int row = c >> 3, off = (c & 7) * 8;
            CPA(su32(Ah + p * (128*QK_LDA) + row * QK_LDA + off),
                gXh + (size_t)(m0 + row) * DD + kt + off);
        } else {
            int c2 = c - 1024;             // 0..767
            int row = c2 / 12, off = (c2 - row * 12) * 8;
            CPA(su32(Bh + p * (64*QK_LDB) + row * QK_LDB + off),
                gWh + wbase + (size_t)(kt + row) * DHH + off);
        }
    }
}

__global__ __launch_bounds__(256, 2) void qkv_kernel(
    const float* __restrict__ bq, const float* __restrict__ bk, const float* __restrict__ bv)
{
    extern __shared__ __half smq[];
    __half* Ah = smq;                      // 2 x 128 x 72
    __half* Bh = Ah + 2*128*QK_LDA;        // 2 x 64 x 104

    const __half *gXh, *gWh; const float* bias; __half *oh;
    if (blockIdx.z == 0)      { gXh=g_Xqh; gWh=g_Wqh; bias=bq; oh=g_Qh; }
    else if (blockIdx.z == 1) { gXh=g_Xkh; gWh=g_Wkh; bias=bk; oh=g_Kh; }
    else                      { gXh=g_Xvh; gWh=g_Wvh; bias=bv; oh=g_Vh; }
    const float oscale = (blockIdx.z == 0) ? rsqrtf(96.0f) : 1.0f;

    const int h   = blockIdx.y;
    const int m0  = blockIdx.x * 128;
    const int tid = threadIdx.x;
    const int wid = tid >> 5, lane = tid & 31;
    const int wm  = wid >> 1, wn = wid & 1;
    const size_t wbase = (size_t)h * DD * DHH;

    float acc[2][6][4];
    #pragma unroll
    for (int i = 0; i < 2; i++)
        #pragma unroll
        for (int j = 0; j < 6; j++)
            #pragma unroll
            for (int k = 0; k < 4; k++) acc[i][j][k] = 0.f;

    const int lrow = lane & 15, lcol8 = (lane >> 4) << 3;

    qkv_load(Ah, Bh, gXh, gWh, 0, m0, 0, wbase, tid);
    CP_COMMIT;

    const int NT = DD / 64;   // 12
    for (int it = 0; it < NT; it++) {
        int p = it & 1;
        if (it + 1 < NT) {
            qkv_load(Ah, Bh, gXh, gWh, (it+1)&1, m0, (it+1)*64, wbase, tid);
            CP_COMMIT;
            CP_WAIT1;
        } else {
            CP_WAIT0;
        }
        __syncthreads();

        __half* Ahp = Ah + p * (128*QK_LDA);
        __half* Bhp = Bh + p * (64*QK_LDB);

        #pragma unroll
        for (int ks = 0; ks < 4; ks++) {
            int k0 = ks * 16;
            unsigned ah[2][4];
            #pragma unroll
            for (int mf = 0; mf < 2; mf++) {
                int row = wm * 32 + mf * 16 + lrow;
                ldsm4(ah[mf], su32(Ahp + row * QK_LDA + k0 + lcol8));
            }
            #pragma unroll
            for (int nf2 = 0; nf2 < 3; nf2++) {
                unsigned bh[4];
                int n0 = wn * 48 + nf2 * 16;
                ldsm4t(bh, su32(Bhp + (k0 + lrow) * QK_LDB + n0 + lcol8));
                #pragma unroll
                for (int hn = 0; hn < 2; hn++) {
                    #pragma unroll
                    for (int mf = 0; mf < 2; mf++)
                        mma16816(acc[mf][nf2*2 + hn], ah[mf], bh + hn*2);
                }
            }
        }
        __syncthreads();
    }

    #pragma unroll
    for (int mf = 0; mf < 2; mf++) {
        #pragma unroll
        for (int nf = 0; nf < 6; nf++) {
            int col = wn * 48 + nf * 8 + (lane & 3) * 2;
            float b0 = bias[h*DHH + col], b1 = bias[h*DHH + col + 1];
            #pragma unroll
            for (int hr = 0; hr < 2; hr++) {
                int m = m0 + wm * 32 + mf * 16 + (lane >> 2) + hr * 8;
                int bb = m >> 11, s = m & 2047;
                size_t off = (((size_t)(bb * HH + h)) * SS + s) * DHH + col;
                float v0 = (acc[mf][nf][hr*2 + 0] + b0) * oscale;
                float v1 = (acc[mf][nf][hr*2 + 1] + b1) * oscale;
                *(half2*)(oh + off) = __halves2half2(__float2half_rn(v0), __float2half_rn(v1));
            }
        }
    }
}

// ---------------------------------------------------------------------------
// Flash attention, fp16 mma, 3-stage KV pipeline. The Q smem region (26.6 KB)
// is reused as the third KV stage after the register hoist — smem stays 80 KB.
// Region rotation: tile t lives in region (t+1) % 3.
// ---------------------------------------------------------------------------
#define AT_LD 104
#define KV_REG (2*64*AT_LD)   // one region = K(64x104) + V(64x104) = 13312 halfs

__device__ __forceinline__ void attn_load_kv(__half* Kbuf, size_t gbase, int tid)
{
    __half* Vbuf = Kbuf + 64 * AT_LD;
    #pragma unroll
    for (int j = 0; j < 6; j++) {
        int c = tid + j * 256;            // 0..1535
        int arr = (c >= 768) ? 1 : 0;
        int rem = c - arr * 768;
        int row = rem / 12;
        int off = (rem - row * 12) * 8;
        const __half* sp = (arr ? g_Vh : g_Kh) + (gbase + row) * DHH + off;
        __half* dp = (arr ? Vbuf : Kbuf) + row * AT_LD + off;
        CPA(su32(dp), sp);
    }
}

__global__ __launch_bounds__(256, 2) void attn_kernel()
{
    extern __shared__ __half smh[];
    // region 0 holds Q initially, becomes a KV stage after hoist
    __half* R0 = smh;
    __half* R1 = smh + KV_REG;
    __half* R2 = smh + 2 * KV_REG;

    const int b  = blockIdx.z, h = blockIdx.y;
    const int s0 = blockIdx.x * 128;
    const int tid = threadIdx.x, wid = tid >> 5, lane = tid & 31;
    const size_t base = ((size_t)(b * HH + h)) * SS;

    {   // load Q tile into region 0 (regular loads)
        int r = tid >> 1, c0 = (tid & 1) * 48;
        size_t go = (base + s0 + r) * DHH + c0;
        __half* dh = R0 + r * AT_LD + c0;
        #pragma unroll
        for (int i = 0; i < 6; i++)
            *(uint4*)(dh + i*8) = *(const uint4*)(g_Qh + go + i*8);
    }

    attn_load_kv(R1, base, tid);      CP_COMMIT;   // tile 0
    attn_load_kv(R2, base + 64, tid); CP_COMMIT;   // tile 1

    const int lrow = lane & 15, lcol8 = (lane >> 4) << 3;
    const int krow_off = (lane & 7) + ((lane & 16) >> 1);
    const int kcol_off = (lane & 8);

    __syncthreads();   // Q ready
    unsigned qf[6][4];
    {
        int qrow = wid * 16 + lrow;
        #pragma unroll
        for (int dk = 0; dk < 6; dk++)
            ldsm4(qf[dk], su32(R0 + qrow * AT_LD + dk * 16 + lcol8));
    }
    __syncthreads();   // all warps done reading Q -> region 0 reusable

    attn_load_kv(R0, base + 128, tid); CP_COMMIT;  // tile 2

    float oacc[12][4];
    #pragma unroll
    for (int j = 0; j < 12; j++)
        #pragma unroll
        for (int t = 0; t < 4; t++) oacc[j][t] = 0.f;
    float m0r = -1e30f, m1r = -1e30f, l0r = 0.f, l1r = 0.f;

    const int NT = SS / 64;   // 32
    int cur = 1;              // region of tile 0
    for (int it = 0; it < NT; it++) {
        if (it < NT - 2)      { CP_WAIT2; }
        else if (it == NT - 2){ CP_WAIT1; }
        else                  { CP_WAIT0; }
        __syncthreads();

        __half* Kp = smh + cur * KV_REG;
        __half* Vp = Kp + 64 * AT_LD;

        // S = Q @ K^T
        float sacc[8][4];
        #pragma unroll
        for (int j = 0; j < 8; j++)
            #pragma unroll
            for (int t = 0; t < 4; t++) sacc[j][t] = 0.f;

        #pragma unroll
        for (int dk = 0; dk < 6; dk++) {
            int d0 = dk * 16;
            #pragma unroll
            for (int nf2 = 0; nf2 < 4; nf2++) {
                unsigned bh[4];
                ldsm4(bh, su32(Kp + (nf2 * 16 + krow_off) * AT_LD + d0 + kcol_off));
                mma16816(sacc[nf2*2 + 0], qf[dk], bh + 0);
                mma16816(sacc[nf2*2 + 1], qf[dk], bh + 2);
            }
        }

        // online softmax (registers)
        float mx0 = -1e30f, mx1 = -1e30f;
        #pragma unroll
        for (int j = 0; j < 8; j++) {
            mx0 = fmaxf(mx0, fmaxf(sacc[j][0], sacc[j][1]));
            mx1 = fmaxf(mx1, fmaxf(sacc[j][2], sacc[j][3]));
        }
        mx0 = fmaxf(mx0, __shfl_xor_sync(0xffffffffu, mx0, 1));
        mx0 = fmaxf(mx0, __shfl_xor_sync(0xffffffffu, mx0, 2));
        mx1 = fmaxf(mx1, __shfl_xor_sync(0xffffffffu, mx1, 1));
        mx1 = fmaxf(mx1, __shfl_xor_sync(0xffffffffu, mx1, 2));
        float mn0 = fmaxf(m0r, mx0), mn1 = fmaxf(m1r, mx1);
        float corr0 = __expf(m0r - mn0), corr1 = __expf(m1r - mn1);
        m0r = mn0; m1r = mn1;
        float sum0 = 0.f, sum1 = 0.f;
        #pragma unroll
        for (int j = 0; j < 8; j++) {
            sacc[j][0] = __expf(sacc[j][0] - mn0);
            sacc[j][1] = __expf(sacc[j][1] - mn0);
            sacc[j][2] = __expf(sacc[j][2] - mn1);
            sacc[j][3] = __expf(sacc[j][3] - mn1);
            sum0 += sacc[j][0] + sacc[j][1];
            sum1 += sacc[j][2] + sacc[j][3];
        }
        sum0 += __shfl_xor_sync(0xffffffffu, sum0, 1);
        sum0 += __shfl_xor_sync(0xffffffffu, sum0, 2);
        sum1 += __shfl_xor_sync(0xffffffffu, sum1, 1);
        sum1 += __shfl_xor_sync(0xffffffffu, sum1, 2);
        l0r = l0r * corr0 + sum0;
        l1r = l1r * corr1 + sum1;

        #pragma unroll
        for (int j = 0; j < 12; j++) {
            oacc[j][0] *= corr0; oacc[j][1] *= corr0;
            oacc[j][2] *= corr1; oacc[j][3] *= corr1;
        }

        // P fragments
        unsigned ph[4][4];
        #pragma unroll
        for (int kf = 0; kf < 4; kf++) {
            #pragma unroll
            for (int q = 0; q < 4; q++) {
                int fj = kf*2 + (q >> 1);
                int t0 = (q & 1) * 2;
                ph[kf][q] = h2u(__halves2half2(__float2half_rn(sacc[fj][t0]),
                                               __float2half_rn(sacc[fj][t0 + 1])));
            }
        }

        // O += P @ V
        #pragma unroll
        for (int kf = 0; kf < 4; kf++) {
            int k0 = kf * 16;
            #pragma unroll
            for (int nf2 = 0; nf2 < 6; nf2++) {
                unsigned bh[4];
                ldsm4t(bh, su32(Vp + (k0 + lrow) * AT_LD + nf2 * 16 + lcol8));
                mma16816(oacc[nf2*2 + 0], ph[kf], bh + 0);
                mma16816(oacc[nf2*2 + 1], ph[kf], bh + 2);
            }
        }
        __syncthreads();   // all warps done with this region
        if (it + 3 < NT) {
            attn_load_kv(Kp, base + (size_t)(it + 3) * 64, tid);  // reuse freed region
            CP_COMMIT;
        }
        cur = (cur == 2) ? 0 : cur + 1;
    }

    // Epilogue: normalize, store cat (fp16)
    float inv0 = 1.0f / l0r, inv1 = 1.0f / l1r;
    #pragma unroll
    for (int nf = 0; nf < 12; nf++) {
        int col = h * DHH + nf * 8 + (lane & 3) * 2;
        #pragma unroll
        for (int hr = 0; hr < 2; hr++) {
            int s = s0 + wid * 16 + (lane >> 2) + hr * 8;
            size_t off = ((size_t)b * SS + s) * DD + col;
            float inv = hr ? inv1 : inv0;
            float v0 = oacc[nf][hr*2 + 0] * inv;
            float v1 = oacc[nf][hr*2 + 1] * inv;
            *(half2*)(g_cath + off) = __halves2half2(__float2half_rn(v0), __float2half_rn(v1));
        }
    }
}

// ---------------------------------------------------------------------------
// Output projection (fp16): out = cath @ Woh + bo. BM=128, BN=128, BK=64.
// ---------------------------------------------------------------------------
#define OP_LDA 72
#define OP_LDB 136

__device__ __forceinline__ void oproj_load(
    __half* Ah, __half* Bh, int p, int m0, int n0b, int kt, int tid)
{
    #pragma unroll
    for (int j = 0; j < 8; j++) {
        int c = tid + j * 256;             // 0..2047
        if (c < 1024) {
            int row = c >> 3, off = (c & 7) * 8;
            CPA(su32(Ah + p * (128*OP_LDA) + row * OP_LDA + off),
                g_cath + (size_t)(m0 + row) * DD + kt + off);
        } else {
            int c2 = c - 1024;             // 0..1023
            int row = c2 >> 4, off = (c2 & 15) * 8;
            CPA(su32(Bh + p * (64*OP_LDB) + row * OP_LDB + off),
                g_Woh + (size_t)(kt + row) * DD + n0b + off);
        }
    }
}

__global__ __launch_bounds__(256, 2) void oproj_kernel(
    const float* __restrict__ bo, float* __restrict__ out)
{
    extern __shared__ __half smo[];
    __half* Ah = smo;
    __half* Bh = Ah + 2*128*OP_LDA;

    const int m0  = blockIdx.x * 128;
    const int n0b = blockIdx.y * 128;
    const int tid = threadIdx.x, wid = tid >> 5, lane = tid & 31;
    const int wm = wid >> 1, wn = wid & 1;

    float acc[2][8][4];
    #pragma unroll
    for (int i = 0; i < 2; i++)
        #pragma unroll
        for (int j = 0; j < 8; j++)
            #pragma unroll
            for (int k = 0; k < 4; k++) acc[i][j][k] = 0.f;

    const int lrow = lane & 15, lcol8 = (lane >> 4) << 3;

    oproj_load(Ah, Bh, 0, m0, n0b, 0, tid);
    CP_COMMIT;

    const int NT = DD / 64;   // 12
    for (int it = 0; it < NT; it++) {
        int p = it & 1;
        if (it + 1 < NT) {
            oproj_load(Ah, Bh, (it+1)&1, m0, n0b, (it+1)*64, tid);
            CP_COMMIT;
            CP_WAIT1;
        } else {
            CP_WAIT0;
        }
        __syncthreads();

        __half* Ahp = Ah + p * (128*OP_LDA);
        __half* Bhp = Bh + p * (64*OP_LDB);

        #pragma unroll
        for (int ks = 0; ks < 4; ks++) {
            int k0 = ks * 16;
            unsigned ah[2][4];
            #pragma unroll
            for (int mf = 0; mf < 2; mf++) {
                int row = wm * 32 + mf * 16 + lrow;
                ldsm4(ah[mf], su32(Ahp + row * OP_LDA + k0 + lcol8));
            }
            #pragma unroll
            for (int nf2 = 0; nf2 < 4; nf2++) {
                unsigned bh[4];
                int n0 = wn * 64 + nf2 * 16;
                ldsm4t(bh, su32(Bhp + (k0 + lrow) * OP_LDB + n0 + lcol8));
                #pragma unroll
                for (int hn = 0; hn < 2; hn++) {
                    #pragma unroll
                    for (int mf = 0; mf < 2; mf++)
                        mma16816(acc[mf][nf2*2 + hn], ah[mf], bh + hn*2);
                }
            }
        }
        __syncthreads();
    }

    #pragma unroll
    for (int mf = 0; mf < 2; mf++) {
        #pragma unroll
        for (int nf = 0; nf < 8; nf++) {
            int col = n0b + wn * 64 + nf * 8 + (lane & 3) * 2;
            float b0 = bo[col], b1 = bo[col + 1];
            #pragma unroll
            for (int hr = 0; hr < 2; hr++) {
                int m = m0 + wm * 32 + mf * 16 + (lane >> 2) + hr * 8;
                float2 v = make_float2(acc[mf][nf][hr*2+0] + b0,
                                       acc[mf][nf][hr*2+1] + b1);
                *(float2*)(out + (size_t)m * DD + col) = v;
            }
        }
    }
}

// ---------------------------------------------------------------------------
extern "C" void kernel_launch(void* const* d_in, const int* in_sizes, int n_in,
                              void* d_out, int out_size)
{
    (void)in_sizes; (void)n_in; (void)out_size;
    const float* Xq = (const float*)d_in[0];
    const float* Xk = (const float*)d_in[1];
    const float* Xv = (const float*)d_in[2];
    const float* Wq = (const float*)d_in[3];
    const float* bq = (const float*)d_in[4];
    const float* Wk = (const float*)d_in[5];
    const float* bk = (const float*)d_in[6];
    const float* Wv = (const float*)d_in[7];
    const float* bv = (const float*)d_in[8];
    const float* Wo = (const float*)d_in[9];
    const float* bo = (const float*)d_in[10];
    float* out = (float*)d_out;

    const int total4 = 3*NX4 + 4*NW4;
    convert_all<<<(total4 + 255) / 256, 256>>>(Xq, Xk, Xv, Wq, Wk, Wv, Wo);

    const int smem_qkv = (2*128*QK_LDA + 2*64*QK_LDB) * (int)sizeof(__half);   // 63488
    cudaFuncSetAttribute(qkv_kernel, cudaFuncAttributeMaxDynamicSharedMemorySize, smem_qkv);
    dim3 gq(MM / 128, HH, 3);
    qkv_kernel<<<gq, 256, smem_qkv>>>(bq, bk, bv);

    const int smem_attn = 3 * KV_REG * (int)sizeof(__half);                    // 79872
    cudaFuncSetAttribute(attn_kernel, cudaFuncAttributeMaxDynamicSharedMemorySize, smem_attn);
    dim3 ga(SS / 128, HH, BB);
    attn_kernel<<<ga, 256, smem_attn>>>();

    const int smem_op = (2*128*OP_LDA + 2*64*OP_LDB) * (int)sizeof(__half);    // 71680
    cudaFuncSetAttribute(oproj_kernel, cudaFuncAttributeMaxDynamicSharedMemorySize, smem_op);
    dim3 go(MM / 128, DD / 128);
    oproj_kernel<<<go, 256, smem_op>>>(bo, out);
}